// round 2
// baseline (speedup 1.0000x reference)
#include <cuda_runtime.h>
#include <math.h>

#define BB 8
#define LL 2500
#define EE 100
#define FF 50
#define KK 9
#define YY 8922
#define NC (BB*FF)   // 400

// Scratch (no allocations allowed)
__device__ float g_hp[BB*LL*FF];      // [b][l][f]  4 MB
__device__ float g_supT[YY*NC];       // [z][b*F+g] 14.3 MB

// ---------------------------------------------------------------------------
// Kernel 1: embedding gather + conv1d (same padding) + tanh -> g_hp
// grid (40, B), block 256. Tile: 64 l-positions, f padded to 64.
// ---------------------------------------------------------------------------
__global__ __launch_bounds__(256) void k_embconv(
    const int* __restrict__ x, const float* __restrict__ embw,
    const float* __restrict__ convw, const float* __restrict__ convb)
{
    __shared__ float es[72][101];   // emb tile with halo (64 + 2*4 rows), padded
    __shared__ float ws[100][64];   // conv_w slice for one k, f padded to 64

    const int b  = blockIdx.y;
    const int l0 = blockIdx.x * 64;
    const int tid = threadIdx.x;

    // load embedding tile rows l0-4 .. l0+67
    for (int idx = tid; idx < 72 * 100; idx += 256) {
        int r = idx / 100, e = idx - r * 100;
        int l = l0 - 4 + r;
        float v = 0.f;
        if (l >= 0 && l < LL) {
            int tok = x[b * LL + l];
            v = embw[(size_t)tok * EE + e];
        }
        es[r][e] = v;
    }

    const int fx = tid & 15;   // f group
    const int ly = tid >> 4;   // l group
    float acc[4][4] = {};

    for (int k = 0; k < KK; k++) {
        __syncthreads();
        for (int idx = tid; idx < 100 * 64; idx += 256) {
            int e = idx >> 6, f = idx & 63;
            ws[e][f] = (f < FF) ? convw[f * (EE * KK) + e * KK + k] : 0.f;
        }
        __syncthreads();
        #pragma unroll 4
        for (int e = 0; e < EE; e++) {
            float av[4], wv[4];
            #pragma unroll
            for (int i = 0; i < 4; i++) av[i] = es[ly + 16 * i + k][e];
            #pragma unroll
            for (int j = 0; j < 4; j++) wv[j] = ws[e][fx + 16 * j];
            #pragma unroll
            for (int i = 0; i < 4; i++)
                #pragma unroll
                for (int j = 0; j < 4; j++)
                    acc[i][j] += av[i] * wv[j];
        }
    }

    #pragma unroll
    for (int i = 0; i < 4; i++) {
        int l = l0 + ly + 16 * i;
        if (l >= LL) continue;
        #pragma unroll
        for (int j = 0; j < 4; j++) {
            int f = fx + 16 * j;
            if (f < FF)
                g_hp[((size_t)b * LL + l) * FF + f] = tanhf(acc[i][j] + convb[f]);
        }
    }
}

// ---------------------------------------------------------------------------
// Kernel 2: per-label attention (max-free softmax) + fused epilogue:
//   m4t, support (-> g_supT transposed), y4t -> out, y4 init -> out.
// grid (70, B), block 128, one y per thread.
// ---------------------------------------------------------------------------
__global__ __launch_bounds__(128, 3) void k_attn(
    const float* __restrict__ U4, const float* __restrict__ gcnw,
    const float* __restrict__ f4t_w, const float* __restrict__ f4t_b,
    const float* __restrict__ f4_w, const float* __restrict__ f4_b,
    float* __restrict__ out)
{
    __shared__ float hps[64 * 50];   // hp chunk
    __shared__ float gs[2500];       // gcn_w (50x50)

    const int b = blockIdx.y;
    const int tid = threadIdx.x;
    const int y = blockIdx.x * 128 + tid;
    const bool act = (y < YY);

    for (int i = tid; i < 2500; i += 128) gs[i] = gcnw[i];

    float u[50], acc[50];
    #pragma unroll
    for (int j = 0; j < 50; j++) {
        u[j] = act ? U4[(size_t)y * 50 + j] : 0.f;
        acc[j] = 0.f;
    }
    float ssum = 0.f;

    const float2* hpg = (const float2*)(g_hp + (size_t)b * LL * FF);

    for (int l0 = 0; l0 < LL; l0 += 64) {
        __syncthreads();
        int nl = min(64, LL - l0);
        float2* h2 = (float2*)hps;
        for (int i = tid; i < nl * 25; i += 128)
            h2[i] = hpg[l0 * 25 + i];
        __syncthreads();

        for (int l = 0; l < nl; l++) {
            const float2* row = (const float2*)(hps + l * 50);
            float s0 = 0.f, s1 = 0.f;
            #pragma unroll
            for (int j = 0; j < 25; j++) {
                float2 v = row[j];
                float p = u[2 * j] * v.x + u[2 * j + 1] * v.y;
                if (j & 1) s1 += p; else s0 += p;
            }
            float w = __expf(s0 + s1);   // scores are O(+-5): no max shift needed
            ssum += w;
            #pragma unroll
            for (int j = 0; j < 25; j++) {
                float2 v = row[j];
                acc[2 * j]     += w * v.x;
                acc[2 * j + 1] += w * v.y;
            }
        }
    }

    if (act) {
        float inv = 1.f / ssum;
        #pragma unroll
        for (int j = 0; j < 50; j++) acc[j] *= inv;   // acc = m4t[b][y][:]

        // support = m4t @ gcn_w, stored transposed for the adj GEMM
        float* supRow = g_supT + (size_t)y * NC + b * FF;
        for (int g = 0; g < 50; g++) {
            float s = 0.f;
            #pragma unroll
            for (int f = 0; f < 50; f++) s += acc[f] * gs[f * 50 + g];
            supRow[g] = s;
        }
        // y4t
        const float* wt = f4t_w + (size_t)y * 50;
        float s1 = 0.f;
        #pragma unroll
        for (int j = 0; j < 50; j++) s1 += acc[j] * wt[j];
        out[(size_t)b * YY + y] = s1 + f4t_b[y];
        // y4 init = m4t . final4_w[:, :50] + final4_b
        const float* w4 = f4_w + (size_t)y * 100;
        float s2 = 0.f;
        #pragma unroll
        for (int j = 0; j < 50; j++) s2 += acc[j] * w4[j];
        out[(size_t)BB * YY + (size_t)b * YY + y] = s2 + f4_b[y];
    }
}

// ---------------------------------------------------------------------------
// Kernel 3: out1 = adj @ supportT  (M=Y, N=400, K=Y), fused epilogue:
//   y4 += sum_g lrelu(out1 + gcn_b[g]) * final4_w[y, 50+g]  (atomicAdd)
// grid (5, 70), block 256. Tile 128(M) x 80(N), K-step 16, micro 8x5.
// ---------------------------------------------------------------------------
__global__ __launch_bounds__(256) void k_adj(
    const float* __restrict__ adj, const float* __restrict__ gcnb,
    const float* __restrict__ f4w, float* __restrict__ out)
{
    __shared__ float As[16][132];   // A^T tile: As[kk][m]
    __shared__ float Bs[16][80];    // Bs[kk][n]
    __shared__ float gb[50];

    const int tid = threadIdx.x;
    if (tid < 50) gb[tid] = gcnb[tid];

    const int n0 = blockIdx.x * 80;
    const int m0 = blockIdx.y * 128;
    const int tx = tid & 15;
    const int ty = tid >> 4;

    float acc[8][5] = {};

    for (int z0 = 0; z0 < YY; z0 += 16) {
        __syncthreads();
        for (int i = tid; i < 128 * 16; i += 256) {
            int m = i >> 4, kk = i & 15;
            int row = m0 + m, col = z0 + kk;
            As[kk][m] = (row < YY && col < YY) ? adj[(size_t)row * YY + col] : 0.f;
        }
        for (int i = tid; i < 16 * 80; i += 256) {
            int kk = i / 80, n = i - kk * 80;
            int z = z0 + kk;
            Bs[kk][n] = (z < YY) ? g_supT[(size_t)z * NC + n0 + n] : 0.f;
        }
        __syncthreads();

        #pragma unroll
        for (int kk = 0; kk < 16; kk++) {
            float4 a0 = *(const float4*)&As[kk][ty * 8];
            float4 a1 = *(const float4*)&As[kk][ty * 8 + 4];
            float a[8] = {a0.x, a0.y, a0.z, a0.w, a1.x, a1.y, a1.z, a1.w};
            float bv[5];
            #pragma unroll
            for (int j = 0; j < 5; j++) bv[j] = Bs[kk][tx * 5 + j];
            #pragma unroll
            for (int i = 0; i < 8; i++)
                #pragma unroll
                for (int j = 0; j < 5; j++)
                    acc[i][j] += a[i] * bv[j];
        }
    }

    const size_t obase = (size_t)BB * YY;
    #pragma unroll
    for (int i = 0; i < 8; i++) {
        int yrow = m0 + ty * 8 + i;
        if (yrow >= YY) break;
        const float* fw = f4w + (size_t)yrow * 100 + 50;
        int c0 = n0 + tx * 5;
        float s = 0.f;
        int bprev = c0 / 50;
        #pragma unroll
        for (int j = 0; j < 5; j++) {
            int c = c0 + j;
            int bb2 = c / 50;
            int g = c - bb2 * 50;
            if (bb2 != bprev) {
                atomicAdd(&out[obase + (size_t)bprev * YY + yrow], s);
                s = 0.f;
                bprev = bb2;
            }
            float v = acc[i][j] + gb[g];
            v = v > 0.f ? v : 0.2f * v;
            s += v * fw[g];
        }
        atomicAdd(&out[obase + (size_t)bprev * YY + yrow], s);
    }
}

// ---------------------------------------------------------------------------
extern "C" void kernel_launch(void* const* d_in, const int* in_sizes, int n_in,
                              void* d_out, int out_size)
{
    const int*   x     = (const int*)  d_in[0];
    // d_in[1] = target (unused)
    const float* embw  = (const float*)d_in[2];
    const float* convw = (const float*)d_in[3];
    const float* convb = (const float*)d_in[4];
    const float* U4    = (const float*)d_in[5];
    const float* gcnw  = (const float*)d_in[6];
    const float* gcnb  = (const float*)d_in[7];
    const float* adj   = (const float*)d_in[8];
    const float* f4tw  = (const float*)d_in[9];
    const float* f4tb  = (const float*)d_in[10];
    const float* f4w   = (const float*)d_in[11];
    const float* f4b   = (const float*)d_in[12];
    float* out = (float*)d_out;

    k_embconv<<<dim3(40, BB), 256>>>(x, embw, convw, convb);
    k_attn   <<<dim3(70, BB), 128>>>(U4, gcnw, f4tw, f4tb, f4w, f4b, out);
    k_adj    <<<dim3(5, 70),  256>>>(adj, gcnb, f4w, out);
}

// round 6
// speedup vs baseline: 1.1069x; 1.1069x over previous
#include <cuda_runtime.h>
#include <math.h>

#define BB 8
#define LL 2500
#define EE 100
#define FF 50
#define KK 9
#define YY 8922
#define NC (BB*FF)   // 400

typedef unsigned long long ull;

// Scratch (no allocations allowed)
__device__ float g_hp[BB*LL*FF];      // [b][l][f]  4 MB
__device__ float g_supT[YY*NC];       // [z][b*F+g] 14.3 MB

// ---------------------------------------------------------------------------
// Packed fp32x2 helpers (Blackwell FFMA2 path)
// ---------------------------------------------------------------------------
__device__ __forceinline__ ull ffma2(ull a, ull b, ull c) {
    ull d;
    asm("fma.rn.f32x2 %0, %1, %2, %3;" : "=l"(d) : "l"(a), "l"(b), "l"(c));
    return d;
}
__device__ __forceinline__ ull pack2(float lo, float hi) {
    ull r;
    asm("mov.b64 %0, {%1, %2};" : "=l"(r) : "f"(lo), "f"(hi));
    return r;
}
__device__ __forceinline__ void unpack2(ull v, float& lo, float& hi) {
    asm("mov.b64 {%0, %1}, %2;" : "=f"(lo), "=f"(hi) : "l"(v));
}

// ---------------------------------------------------------------------------
// Kernel 1: embedding gather + conv1d (same padding) + tanh -> g_hp
// ---------------------------------------------------------------------------
__global__ __launch_bounds__(256) void k_embconv(
    const int* __restrict__ x, const float* __restrict__ embw,
    const float* __restrict__ convw, const float* __restrict__ convb)
{
    __shared__ float es[72][101];
    __shared__ float ws[100][64];

    const int b  = blockIdx.y;
    const int l0 = blockIdx.x * 64;
    const int tid = threadIdx.x;

    for (int idx = tid; idx < 72 * 100; idx += 256) {
        int r = idx / 100, e = idx - r * 100;
        int l = l0 - 4 + r;
        float v = 0.f;
        if (l >= 0 && l < LL) {
            int tok = x[b * LL + l];
            v = embw[(size_t)tok * EE + e];
        }
        es[r][e] = v;
    }

    const int fx = tid & 15;
    const int ly = tid >> 4;
    float acc[4][4] = {};

    for (int k = 0; k < KK; k++) {
        __syncthreads();
        for (int idx = tid; idx < 100 * 64; idx += 256) {
            int e = idx >> 6, f = idx & 63;
            ws[e][f] = (f < FF) ? convw[f * (EE * KK) + e * KK + k] : 0.f;
        }
        __syncthreads();
        #pragma unroll 4
        for (int e = 0; e < EE; e++) {
            float av[4], wv[4];
            #pragma unroll
            for (int i = 0; i < 4; i++) av[i] = es[ly + 16 * i + k][e];
            #pragma unroll
            for (int j = 0; j < 4; j++) wv[j] = ws[e][fx + 16 * j];
            #pragma unroll
            for (int i = 0; i < 4; i++)
                #pragma unroll
                for (int j = 0; j < 4; j++)
                    acc[i][j] += av[i] * wv[j];
        }
    }

    #pragma unroll
    for (int i = 0; i < 4; i++) {
        int l = l0 + ly + 16 * i;
        if (l >= LL) continue;
        #pragma unroll
        for (int j = 0; j < 4; j++) {
            int f = fx + 16 * j;
            if (f < FF)
                g_hp[((size_t)b * LL + l) * FF + f] = tanhf(acc[i][j] + convb[f]);
        }
    }
}

// ---------------------------------------------------------------------------
// Kernel 2: per-label attention (max-free softmax), f32x2-packed inner loop.
// grid (70, B), block 128, one y per thread.
// ---------------------------------------------------------------------------
__global__ __launch_bounds__(128) void k_attn(
    const float* __restrict__ U4, const float* __restrict__ gcnw,
    const float* __restrict__ f4t_w, const float* __restrict__ f4t_b,
    const float* __restrict__ f4_w, const float* __restrict__ f4_b,
    float* __restrict__ out)
{
    __shared__ float hps[64 * 50];   // hp chunk (8B-aligned rows: 50 floats = 200B)
    __shared__ float gs[2500];       // gcn_w (50x50)

    const int b = blockIdx.y;
    const int tid = threadIdx.x;
    const int y = blockIdx.x * 128 + tid;
    const bool act = (y < YY);

    for (int i = tid; i < 2500; i += 128) gs[i] = gcnw[i];

    ull upk[25], accpk[25];
    #pragma unroll
    for (int j = 0; j < 25; j++) {
        upk[j] = act ? *(const ull*)(U4 + (size_t)y * 50 + 2 * j) : 0ull;
        accpk[j] = 0ull;
    }
    float ssum = 0.f;

    const ull* hpg = (const ull*)(g_hp + (size_t)b * LL * FF);

    for (int l0 = 0; l0 < LL; l0 += 64) {
        __syncthreads();
        int nl = min(64, LL - l0);
        ull* h2 = (ull*)hps;
        for (int i = tid; i < nl * 25; i += 128)
            h2[i] = hpg[l0 * 25 + i];
        __syncthreads();

        for (int l = 0; l < nl; l++) {
            const ull* row = (const ull*)(hps + l * 50);
            ull r[25];
            #pragma unroll
            for (int j = 0; j < 25; j++) r[j] = row[j];

            ull sA = 0ull, sB = 0ull;
            #pragma unroll
            for (int j = 0; j < 25; j++) {
                if (j & 1) sB = ffma2(upk[j], r[j], sB);
                else       sA = ffma2(upk[j], r[j], sA);
            }
            float a0, a1, b0, b1;
            unpack2(sA, a0, a1);
            unpack2(sB, b0, b1);
            float w = __expf((a0 + b0) + (a1 + b1));   // scores O(+-5): no shift needed
            ssum += w;
            ull wd = pack2(w, w);
            #pragma unroll
            for (int j = 0; j < 25; j++)
                accpk[j] = ffma2(wd, r[j], accpk[j]);
        }
    }

    if (act) {
        float inv = 1.f / ssum;
        float acc[50];
        #pragma unroll
        for (int j = 0; j < 25; j++) {
            float lo, hi;
            unpack2(accpk[j], lo, hi);
            acc[2 * j] = lo * inv;
            acc[2 * j + 1] = hi * inv;     // acc = m4t[b][y][:]
        }

        // support = m4t @ gcn_w, stored transposed for the adj GEMM
        float* supRow = g_supT + (size_t)y * NC + b * FF;
        for (int g = 0; g < 50; g++) {
            float s = 0.f;
            #pragma unroll
            for (int f = 0; f < 50; f++) s += acc[f] * gs[f * 50 + g];
            supRow[g] = s;
        }
        // y4t
        const float* wt = f4t_w + (size_t)y * 50;
        float s1 = 0.f;
        #pragma unroll
        for (int j = 0; j < 50; j++) s1 += acc[j] * wt[j];
        out[(size_t)b * YY + y] = s1 + f4t_b[y];
        // y4 init = m4t . final4_w[:, :50] + final4_b
        const float* w4 = f4_w + (size_t)y * 100;
        float s2 = 0.f;
        #pragma unroll
        for (int j = 0; j < 50; j++) s2 += acc[j] * w4[j];
        out[(size_t)BB * YY + (size_t)b * YY + y] = s2 + f4_b[y];
    }
}

// ---------------------------------------------------------------------------
// Kernel 3: out1 = adj @ supportT  (M=Y, N=400, K=Y), f32x2-packed micro-tile,
// fused epilogue (leaky-relu + gcn_b + dot final4_w[:,50:]) via atomicAdd.
// grid (5, 70), block 256. Tile 128(M) x 80(N), K-step 16, micro (8m x 5n).
// ---------------------------------------------------------------------------
__global__ __launch_bounds__(256) void k_adj(
    const float* __restrict__ adj, const float* __restrict__ gcnb,
    const float* __restrict__ f4w, float* __restrict__ out)
{
    __shared__ float As[16][132];    // A^T tile: As[kk][m], 16B-aligned rows
    __shared__ ull   BsD[16][80];    // B tile pre-duplicated: (v,v) pairs
    __shared__ float gb[50];

    const int tid = threadIdx.x;
    if (tid < 50) gb[tid] = gcnb[tid];

    const int n0 = blockIdx.x * 80;
    const int m0 = blockIdx.y * 128;
    const int tx = tid & 15;
    const int ty = tid >> 4;

    ull accpk[4][5];
    #pragma unroll
    for (int i = 0; i < 4; i++)
        #pragma unroll
        for (int j = 0; j < 5; j++) accpk[i][j] = 0ull;

    for (int z0 = 0; z0 < YY; z0 += 16) {
        __syncthreads();
        for (int i = tid; i < 128 * 16; i += 256) {
            int m = i >> 4, kk = i & 15;
            int row = m0 + m, col = z0 + kk;
            As[kk][m] = (row < YY && col < YY) ? adj[(size_t)row * YY + col] : 0.f;
        }
        for (int i = tid; i < 16 * 80; i += 256) {
            int kk = i / 80, n = i - kk * 80;
            int z = z0 + kk;
            float v = (z < YY) ? g_supT[(size_t)z * NC + n0 + n] : 0.f;
            BsD[kk][n] = pack2(v, v);
        }
        __syncthreads();

        #pragma unroll
        for (int kk = 0; kk < 16; kk++) {
            ulonglong2 av01 = *(const ulonglong2*)&As[kk][ty * 8];
            ulonglong2 av23 = *(const ulonglong2*)&As[kk][ty * 8 + 4];
            ull a[4] = {av01.x, av01.y, av23.x, av23.y};
            ull bv[5];
            #pragma unroll
            for (int j = 0; j < 5; j++) bv[j] = BsD[kk][tx * 5 + j];
            #pragma unroll
            for (int i = 0; i < 4; i++)
                #pragma unroll
                for (int j = 0; j < 5; j++)
                    accpk[i][j] = ffma2(a[i], bv[j], accpk[i][j]);
        }
    }

    // unpack to scalar accumulators: acc[i2][j], 8 m-rows x 5 n-cols
    float acc[8][5];
    #pragma unroll
    for (int i = 0; i < 4; i++)
        #pragma unroll
        for (int j = 0; j < 5; j++)
            unpack2(accpk[i][j], acc[2 * i][j], acc[2 * i + 1][j]);

    const size_t obase = (size_t)BB * YY;
    #pragma unroll
    for (int i = 0; i < 8; i++) {
        int yrow = m0 + ty * 8 + i;
        if (yrow >= YY) break;
        const float* fw = f4w + (size_t)yrow * 100 + 50;
        int c0 = n0 + tx * 5;
        float s = 0.f;
        int bprev = c0 / 50;
        #pragma unroll
        for (int j = 0; j < 5; j++) {
            int c = c0 + j;
            int bb2 = c / 50;
            int g = c - bb2 * 50;
            if (bb2 != bprev) {
                atomicAdd(&out[obase + (size_t)bprev * YY + yrow], s);
                s = 0.f;
                bprev = bb2;
            }
            float v = acc[i][j] + gb[g];
            v = v > 0.f ? v : 0.2f * v;
            s += v * fw[g];
        }
        atomicAdd(&out[obase + (size_t)bprev * YY + yrow], s);
    }
}

// ---------------------------------------------------------------------------
extern "C" void kernel_launch(void* const* d_in, const int* in_sizes, int n_in,
                              void* d_out, int out_size)
{
    const int*   x     = (const int*)  d_in[0];
    // d_in[1] = target (unused)
    const float* embw  = (const float*)d_in[2];
    const float* convw = (const float*)d_in[3];
    const float* convb = (const float*)d_in[4];
    const float* U4    = (const float*)d_in[5];
    const float* gcnw  = (const float*)d_in[6];
    const float* gcnb  = (const float*)d_in[7];
    const float* adj   = (const float*)d_in[8];
    const float* f4tw  = (const float*)d_in[9];
    const float* f4tb  = (const float*)d_in[10];
    const float* f4w   = (const float*)d_in[11];
    const float* f4b   = (const float*)d_in[12];
    float* out = (float*)d_out;

    k_embconv<<<dim3(40, BB), 256>>>(x, embw, convw, convb);
    k_attn   <<<dim3(70, BB), 128>>>(U4, gcnw, f4tw, f4tb, f4w, f4b, out);
    k_adj    <<<dim3(5, 70),  256>>>(adj, gcnb, f4w, out);
}

// round 8
// speedup vs baseline: 1.6209x; 1.4643x over previous
#include <cuda_runtime.h>
#include <cuda_bf16.h>
#include <math.h>
#include <cstdint>

#define BB 8
#define LL 2500
#define EE 100
#define FF 50
#define KK 9
#define YY 8922
#define NC (BB*FF)      // 400
#define YPAD 8960       // 70*128 = 140*64
#define NCHUNK 140      // K chunks of 64

typedef unsigned long long ull;

// Scratch (no allocations allowed)
__device__ float g_hp[BB*LL*FF];                 // [b][l][f]
__device__ __nv_bfloat16 g_sup_hi[NC*YPAD];      // [n400][z]
__device__ __nv_bfloat16 g_sup_lo[NC*YPAD];      // [n400][z]

// ---------------------------------------------------------------------------
// helpers
// ---------------------------------------------------------------------------
__device__ __forceinline__ ull ffma2(ull a, ull b, ull c) {
    ull d;
    asm("fma.rn.f32x2 %0, %1, %2, %3;" : "=l"(d) : "l"(a), "l"(b), "l"(c));
    return d;
}
__device__ __forceinline__ ull pack2(float lo, float hi) {
    ull r; asm("mov.b64 %0, {%1, %2};" : "=l"(r) : "f"(lo), "f"(hi)); return r;
}
__device__ __forceinline__ void unpack2(ull v, float& lo, float& hi) {
    asm("mov.b64 {%0, %1}, %2;" : "=f"(lo), "=f"(hi) : "l"(v));
}

__device__ __forceinline__ void mma16816(float d[4], const unsigned a[4], const unsigned b[2]) {
    asm volatile(
        "mma.sync.aligned.m16n8k16.row.col.f32.bf16.bf16.f32 "
        "{%0,%1,%2,%3}, {%4,%5,%6,%7}, {%8,%9}, {%0,%1,%2,%3};"
        : "+f"(d[0]), "+f"(d[1]), "+f"(d[2]), "+f"(d[3])
        : "r"(a[0]), "r"(a[1]), "r"(a[2]), "r"(a[3]), "r"(b[0]), "r"(b[1]));
}

// ---------------------------------------------------------------------------
// Kernel 1: embedding gather + conv1d + tanh -> g_hp (unchanged)
// ---------------------------------------------------------------------------
__global__ __launch_bounds__(256) void k_embconv(
    const int* __restrict__ x, const float* __restrict__ embw,
    const float* __restrict__ convw, const float* __restrict__ convb)
{
    __shared__ float es[72][101];
    __shared__ float ws[100][64];

    const int b  = blockIdx.y;
    const int l0 = blockIdx.x * 64;
    const int tid = threadIdx.x;

    for (int idx = tid; idx < 72 * 100; idx += 256) {
        int r = idx / 100, e = idx - r * 100;
        int l = l0 - 4 + r;
        float v = 0.f;
        if (l >= 0 && l < LL) {
            int tok = x[b * LL + l];
            v = embw[(size_t)tok * EE + e];
        }
        es[r][e] = v;
    }

    const int fx = tid & 15;
    const int ly = tid >> 4;
    float acc[4][4] = {};

    for (int k = 0; k < KK; k++) {
        __syncthreads();
        for (int idx = tid; idx < 100 * 64; idx += 256) {
            int e = idx >> 6, f = idx & 63;
            ws[e][f] = (f < FF) ? convw[f * (EE * KK) + e * KK + k] : 0.f;
        }
        __syncthreads();
        #pragma unroll 4
        for (int e = 0; e < EE; e++) {
            float av[4], wv[4];
            #pragma unroll
            for (int i = 0; i < 4; i++) av[i] = es[ly + 16 * i + k][e];
            #pragma unroll
            for (int j = 0; j < 4; j++) wv[j] = ws[e][fx + 16 * j];
            #pragma unroll
            for (int i = 0; i < 4; i++)
                #pragma unroll
                for (int j = 0; j < 4; j++)
                    acc[i][j] += av[i] * wv[j];
        }
    }

    #pragma unroll
    for (int i = 0; i < 4; i++) {
        int l = l0 + ly + 16 * i;
        if (l >= LL) continue;
        #pragma unroll
        for (int j = 0; j < 4; j++) {
            int f = fx + 16 * j;
            if (f < FF)
                g_hp[((size_t)b * LL + l) * FF + f] = tanhf(acc[i][j] + convb[f]);
        }
    }
}

// ---------------------------------------------------------------------------
// Kernel 2: per-label attention; epilogue writes support as bf16 hi/lo
// ([n400][z] layout, pad rows zero), y4t, and y4 init.
// grid (70, B), block 128, one y per thread (y covers 0..8959).
// ---------------------------------------------------------------------------
__global__ __launch_bounds__(128) void k_attn(
    const float* __restrict__ U4, const float* __restrict__ gcnw,
    const float* __restrict__ f4t_w, const float* __restrict__ f4t_b,
    const float* __restrict__ f4_w, const float* __restrict__ f4_b,
    float* __restrict__ out)
{
    __shared__ float hps[64 * 50];
    __shared__ float gs[2500];

    const int b = blockIdx.y;
    const int tid = threadIdx.x;
    const int y = blockIdx.x * 128 + tid;
    const bool act = (y < YY);

    for (int i = tid; i < 2500; i += 128) gs[i] = gcnw[i];

    ull upk[25], accpk[25];
    #pragma unroll
    for (int j = 0; j < 25; j++) {
        upk[j] = act ? *(const ull*)(U4 + (size_t)y * 50 + 2 * j) : 0ull;
        accpk[j] = 0ull;
    }
    float ssum = 0.f;

    const ull* hpg = (const ull*)(g_hp + (size_t)b * LL * FF);

    for (int l0 = 0; l0 < LL; l0 += 64) {
        __syncthreads();
        int nl = min(64, LL - l0);
        ull* h2 = (ull*)hps;
        for (int i = tid; i < nl * 25; i += 128)
            h2[i] = hpg[l0 * 25 + i];
        __syncthreads();

        for (int l = 0; l < nl; l++) {
            const ull* row = (const ull*)(hps + l * 50);
            ull r[25];
            #pragma unroll
            for (int j = 0; j < 25; j++) r[j] = row[j];

            ull sA = 0ull, sB = 0ull;
            #pragma unroll
            for (int j = 0; j < 25; j++) {
                if (j & 1) sB = ffma2(upk[j], r[j], sB);
                else       sA = ffma2(upk[j], r[j], sA);
            }
            float a0, a1, b0, b1;
            unpack2(sA, a0, a1);
            unpack2(sB, b0, b1);
            float w = __expf((a0 + b0) + (a1 + b1));
            ssum += w;
            ull wd = pack2(w, w);
            #pragma unroll
            for (int j = 0; j < 25; j++)
                accpk[j] = ffma2(wd, r[j], accpk[j]);
        }
    }

    // pad threads use inv = 0 -> zero support rows (K-padding for k_adj_mma)
    float inv = act ? 1.f / ssum : 0.f;
    float acc[50];
    #pragma unroll
    for (int j = 0; j < 25; j++) {
        float lo, hi;
        unpack2(accpk[j], lo, hi);
        acc[2 * j]     = lo * inv;
        acc[2 * j + 1] = hi * inv;     // acc = m4t[b][y][:] (0 for pads)
    }

    const int nbase = b * FF;
    for (int g = 0; g < 50; g++) {
        float s = 0.f;
        #pragma unroll
        for (int f = 0; f < 50; f++) s += acc[f] * gs[f * 50 + g];
        __nv_bfloat16 h = __float2bfloat16(s);
        float rem = s - __bfloat162float(h);
        size_t o = (size_t)(nbase + g) * YPAD + y;
        g_sup_hi[o] = h;
        g_sup_lo[o] = __float2bfloat16(rem);
    }

    if (act) {
        const float* wt = f4t_w + (size_t)y * 50;
        float s1 = 0.f;
        #pragma unroll
        for (int j = 0; j < 50; j++) s1 += acc[j] * wt[j];
        out[(size_t)b * YY + y] = s1 + f4t_b[y];

        const float* w4 = f4_w + (size_t)y * 100;
        float s2 = 0.f;
        #pragma unroll
        for (int j = 0; j < 50; j++) s2 += acc[j] * w4[j];
        out[(size_t)BB * YY + (size_t)b * YY + y] = s2 + f4_b[y];
    }
}

// ---------------------------------------------------------------------------
// Kernel 3: out1 = adj @ support via split-bf16 mma.sync (HMMA m16n8k16).
// grid (5, 70), block 256 (8 warps: 4m x 2n). CTA tile 128m x 80n, K chunks
// of 64 staged in smem (bf16 hi/lo, row stride 72 for conflict-free frags).
// Fused epilogue: + gcn_b, leaky-relu, dot final4_w[:,50:], atomicAdd -> y4.
// ---------------------------------------------------------------------------
#define ASTRIDE 72
#define A_TILE (128 * ASTRIDE)          // bf16 elems per A plane
#define B_TILE (80 * ASTRIDE)
#define SM_AHI 0
#define SM_ALO (A_TILE)
#define SM_BHI (2 * A_TILE)
#define SM_BLO (2 * A_TILE + B_TILE)
#define SM_ELEMS (2 * A_TILE + 2 * B_TILE)
#define SMEM_SZ (SM_ELEMS * 2 + 256)    // + gcn_b area

__global__ __launch_bounds__(256) void k_adj_mma(
    const float* __restrict__ adj, const float* __restrict__ gcnb,
    const float* __restrict__ f4w, float* __restrict__ out)
{
    extern __shared__ char smem[];
    __nv_bfloat16* sm = (__nv_bfloat16*)smem;
    float* gb = (float*)(smem + SM_ELEMS * 2);

    const int tid = threadIdx.x;
    const int wid = tid >> 5;
    const int lane = tid & 31;
    const int warp_m = wid & 3;          // 0..3 -> 32-row slices
    const int warp_n = wid >> 2;         // 0..1 -> 40-col slices
    const int r = lane >> 2;
    const int cc = (lane & 3) * 2;

    const int n0 = blockIdx.x * 80;
    const int m0 = blockIdx.y * 128;

    if (tid < 50) gb[tid] = gcnb[tid];

    float d[2][5][4];
    #pragma unroll
    for (int mt = 0; mt < 2; mt++)
        #pragma unroll
        for (int nt = 0; nt < 5; nt++)
            #pragma unroll
            for (int i = 0; i < 4; i++) d[mt][nt][i] = 0.f;

    for (int t = 0; t < NCHUNK; t++) {
        const int z0 = t * 64;
        __syncthreads();

        // --- stage A: adj[m0..+128][z0..+64] -> bf16 hi/lo
        for (int i = tid; i < 4096; i += 256) {
            int row = i >> 5, p = i & 31;
            int gm = m0 + row;
            int z = z0 + 2 * p;
            float v0 = 0.f, v1 = 0.f;
            if (gm < YY) {
                if (z + 1 < YY) {
                    float2 w = *(const float2*)(adj + (size_t)gm * YY + z);
                    v0 = w.x; v1 = w.y;
                } else if (z < YY) {
                    v0 = adj[(size_t)gm * YY + z];
                }
            }
            __nv_bfloat162 hh = __floats2bfloat162_rn(v0, v1);
            float r0 = v0 - __bfloat162float(hh.x);
            float r1 = v1 - __bfloat162float(hh.y);
            __nv_bfloat162 llv = __floats2bfloat162_rn(r0, r1);
            int off = row * ASTRIDE + 2 * p;
            *(uint32_t*)&sm[SM_AHI + off] = *(uint32_t*)&hh;
            *(uint32_t*)&sm[SM_ALO + off] = *(uint32_t*)&llv;
        }

        // --- stage B: support[n0..+80][z0..+64] bf16 hi/lo (pre-split)
        for (int i = tid; i < 640; i += 256) {
            int n = i >> 3, grp = i & 7;
            size_t o = (size_t)(n0 + n) * YPAD + z0 + grp * 8;
            uint4 vh = *(const uint4*)(g_sup_hi + o);
            uint4 vl = *(const uint4*)(g_sup_lo + o);
            int off = n * ASTRIDE + grp * 8;
            *(uint4*)&sm[SM_BHI + off] = vh;
            *(uint4*)&sm[SM_BLO + off] = vl;
        }
        __syncthreads();

        // --- compute: 4 k16-steps
        #pragma unroll
        for (int ks = 0; ks < 4; ks++) {
            const int kc = ks * 16 + cc;
            unsigned aH[2][4], aL[2][4], bH[5][2], bL[5][2];
            #pragma unroll
            for (int mt = 0; mt < 2; mt++) {
                int row = warp_m * 32 + mt * 16 + r;
                aH[mt][0] = *(const unsigned*)&sm[SM_AHI + row * ASTRIDE + kc];
                aH[mt][1] = *(const unsigned*)&sm[SM_AHI + (row + 8) * ASTRIDE + kc];
                aH[mt][2] = *(const unsigned*)&sm[SM_AHI + row * ASTRIDE + kc + 8];
                aH[mt][3] = *(const unsigned*)&sm[SM_AHI + (row + 8) * ASTRIDE + kc + 8];
                aL[mt][0] = *(const unsigned*)&sm[SM_ALO + row * ASTRIDE + kc];
                aL[mt][1] = *(const unsigned*)&sm[SM_ALO + (row + 8) * ASTRIDE + kc];
                aL[mt][2] = *(const unsigned*)&sm[SM_ALO + row * ASTRIDE + kc + 8];
                aL[mt][3] = *(const unsigned*)&sm[SM_ALO + (row + 8) * ASTRIDE + kc + 8];
            }
            #pragma unroll
            for (int nt = 0; nt < 5; nt++) {
                int n = warp_n * 40 + nt * 8 + r;
                bH[nt][0] = *(const unsigned*)&sm[SM_BHI + n * ASTRIDE + kc];
                bH[nt][1] = *(const unsigned*)&sm[SM_BHI + n * ASTRIDE + kc + 8];
                bL[nt][0] = *(const unsigned*)&sm[SM_BLO + n * ASTRIDE + kc];
                bL[nt][1] = *(const unsigned*)&sm[SM_BLO + n * ASTRIDE + kc + 8];
            }
            #pragma unroll
            for (int mt = 0; mt < 2; mt++)
                #pragma unroll
                for (int nt = 0; nt < 5; nt++) {
                    mma16816(d[mt][nt], aH[mt], bH[nt]);
                    mma16816(d[mt][nt], aH[mt], bL[nt]);
                    mma16816(d[mt][nt], aL[mt], bH[nt]);
                }
        }
    }

    // --- epilogue: gcn_b + leaky-relu + dot f4w[:,50:], atomicAdd into y4
    const size_t obase = (size_t)BB * YY;
    #pragma unroll
    for (int mt = 0; mt < 2; mt++) {
        int row0 = m0 + warp_m * 32 + mt * 16 + r;
        #pragma unroll
        for (int nt = 0; nt < 5; nt++) {
            int col0 = n0 + warp_n * 40 + nt * 8 + cc;
            int b = col0 / 50;
            int g = col0 - b * 50;      // g even, g+1 <= 49: same batch
            float gb0 = gb[g], gb1 = gb[g + 1];
            #pragma unroll
            for (int rr = 0; rr < 2; rr++) {
                int y = row0 + rr * 8;
                if (y < YY) {
                    float v0 = d[mt][nt][rr * 2 + 0] + gb0;
                    float v1 = d[mt][nt][rr * 2 + 1] + gb1;
                    v0 = v0 > 0.f ? v0 : 0.2f * v0;
                    v1 = v1 > 0.f ? v1 : 0.2f * v1;
                    const float* fw = f4w + (size_t)y * 100 + 50;
                    float s = v0 * fw[g] + v1 * fw[g + 1];
                    atomicAdd(&out[obase + (size_t)b * YY + y], s);
                }
            }
        }
    }
}

// ---------------------------------------------------------------------------
extern "C" void kernel_launch(void* const* d_in, const int* in_sizes, int n_in,
                              void* d_out, int out_size)
{
    const int*   x     = (const int*)  d_in[0];
    const float* embw  = (const float*)d_in[2];
    const float* convw = (const float*)d_in[3];
    const float* convb = (const float*)d_in[4];
    const float* U4    = (const float*)d_in[5];
    const float* gcnw  = (const float*)d_in[6];
    const float* gcnb  = (const float*)d_in[7];
    const float* adj   = (const float*)d_in[8];
    const float* f4tw  = (const float*)d_in[9];
    const float* f4tb  = (const float*)d_in[10];
    const float* f4w   = (const float*)d_in[11];
    const float* f4b   = (const float*)d_in[12];
    float* out = (float*)d_out;

    static int smem_set = 0;
    if (!smem_set) {
        cudaFuncSetAttribute(k_adj_mma, cudaFuncAttributeMaxDynamicSharedMemorySize, SMEM_SZ);
        smem_set = 1;
    }

    k_embconv<<<dim3(40, BB), 256>>>(x, embw, convw, convb);
    k_attn   <<<dim3(70, BB), 128>>>(U4, gcnw, f4tw, f4tb, f4w, f4b, out);
    k_adj_mma<<<dim3(5, 70), 256, SMEM_SZ>>>(adj, gcnb, f4w, out);
}

// round 10
// speedup vs baseline: 1.8913x; 1.1668x over previous
#include <cuda_runtime.h>
#include <cuda_bf16.h>
#include <math.h>
#include <cstdint>

#define BB 8
#define LL 2500
#define EE 100
#define FF 50
#define KK 9
#define YY 8922
#define NC (BB*FF)      // 400
#define YPAD 8960       // 70*128 = 140*64
#define NCHUNK 140      // K chunks of 64 for adj GEMM

typedef unsigned long long ull;

// Scratch (no allocations allowed)
__device__ float g_hp[BB*LL*FF];                 // [b][l][f]
__device__ __nv_bfloat16 g_sup_hi[NC*YPAD];      // [n400][z]
__device__ __nv_bfloat16 g_sup_lo[NC*YPAD];      // [n400][z]

// ---------------------------------------------------------------------------
// helpers
// ---------------------------------------------------------------------------
__device__ __forceinline__ void mma16816(float d[4], const unsigned a[4], const unsigned b[2]) {
    asm volatile(
        "mma.sync.aligned.m16n8k16.row.col.f32.bf16.bf16.f32 "
        "{%0,%1,%2,%3}, {%4,%5,%6,%7}, {%8,%9}, {%0,%1,%2,%3};"
        : "+f"(d[0]), "+f"(d[1]), "+f"(d[2]), "+f"(d[3])
        : "r"(a[0]), "r"(a[1]), "r"(a[2]), "r"(a[3]), "r"(b[0]), "r"(b[1]));
}
__device__ __forceinline__ void split2(float x, float y, unsigned& hi, unsigned& lo) {
    __nv_bfloat162 hh = __floats2bfloat162_rn(x, y);
    float r0 = x - __bfloat162float(hh.x);
    float r1 = y - __bfloat162float(hh.y);
    __nv_bfloat162 llv = __floats2bfloat162_rn(r0, r1);
    hi = *(unsigned*)&hh;
    lo = *(unsigned*)&llv;
}

// ---------------------------------------------------------------------------
// Kernel 1: embedding gather + conv1d + tanh -> g_hp (unchanged)
// ---------------------------------------------------------------------------
__global__ __launch_bounds__(256) void k_embconv(
    const int* __restrict__ x, const float* __restrict__ embw,
    const float* __restrict__ convw, const float* __restrict__ convb)
{
    __shared__ float es[72][101];
    __shared__ float ws[100][64];

    const int b  = blockIdx.y;
    const int l0 = blockIdx.x * 64;
    const int tid = threadIdx.x;

    for (int idx = tid; idx < 72 * 100; idx += 256) {
        int r = idx / 100, e = idx - r * 100;
        int l = l0 - 4 + r;
        float v = 0.f;
        if (l >= 0 && l < LL) {
            int tok = x[b * LL + l];
            v = embw[(size_t)tok * EE + e];
        }
        es[r][e] = v;
    }

    const int fx = tid & 15;
    const int ly = tid >> 4;
    float acc[4][4] = {};

    for (int k = 0; k < KK; k++) {
        __syncthreads();
        for (int idx = tid; idx < 100 * 64; idx += 256) {
            int e = idx >> 6, f = idx & 63;
            ws[e][f] = (f < FF) ? convw[f * (EE * KK) + e * KK + k] : 0.f;
        }
        __syncthreads();
        #pragma unroll 4
        for (int e = 0; e < EE; e++) {
            float av[4], wv[4];
            #pragma unroll
            for (int i = 0; i < 4; i++) av[i] = es[ly + 16 * i + k][e];
            #pragma unroll
            for (int j = 0; j < 4; j++) wv[j] = ws[e][fx + 16 * j];
            #pragma unroll
            for (int i = 0; i < 4; i++)
                #pragma unroll
                for (int j = 0; j < 4; j++)
                    acc[i][j] += av[i] * wv[j];
        }
    }

    #pragma unroll
    for (int i = 0; i < 4; i++) {
        int l = l0 + ly + 16 * i;
        if (l >= LL) continue;
        #pragma unroll
        for (int j = 0; j < 4; j++) {
            int f = fx + 16 * j;
            if (f < FF)
                g_hp[((size_t)b * LL + l) * FF + f] = tanhf(acc[i][j] + convb[f]);
        }
    }
}

// ---------------------------------------------------------------------------
// Kernel 2 (HMMA): per-label attention, flash-style.
// grid (70, B), block 256 (8 warps, 16 y-rows each; CTA = 128 y).
// Loop 40 l-chunks of 64:
//   scores = U4_split . hp_split^T (3 products), exp in regs (masked tail),
//   re-fragment exp(S) SPLIT hi/lo as bf16 A-frags (fixes round-9 1.4e-3),
//   m4t += wH.hH + wH.hL + wL.hH (3 products).
// Epilogue: normalize (inv=0 for pad y), support->bf16 hi/lo, y4t, y4 init.
// ---------------------------------------------------------------------------
#define HPK_HI 0
#define HPK_LO 9216
#define HPT_HI 18432
#define HPT_LO 27648
#define GCN_OFF 36864
#define M4T_OFF 0                        // aliases hp region after main loop
#define SMEM_ATTN (36864 + 10000)

__global__ __launch_bounds__(256, 1) void k_attn_mma(
    const float* __restrict__ U4, const float* __restrict__ gcnw,
    const float* __restrict__ f4t_w, const float* __restrict__ f4t_b,
    const float* __restrict__ f4_w, const float* __restrict__ f4_b,
    float* __restrict__ out)
{
    __shared__ __align__(16) char smraw[SMEM_ATTN];
    __nv_bfloat16* hpk_hi = (__nv_bfloat16*)(smraw + HPK_HI);
    __nv_bfloat16* hpk_lo = (__nv_bfloat16*)(smraw + HPK_LO);
    __nv_bfloat16* hpt_hi = (__nv_bfloat16*)(smraw + HPT_HI);
    __nv_bfloat16* hpt_lo = (__nv_bfloat16*)(smraw + HPT_LO);
    float* gs = (float*)(smraw + GCN_OFF);
    float* m4s = (float*)(smraw + M4T_OFF);   // [128][68] f32, after main loop

    const int b = blockIdx.y;
    const int y0 = blockIdx.x * 128;
    const int tid = threadIdx.x;
    const int wy = tid >> 5;
    const int lane = tid & 31;
    const int r = lane >> 2;
    const int c2 = (lane & 3) * 2;

    for (int i = tid; i < 2500; i += 256) gs[i] = gcnw[i];

    // --- preload U4 split A-fragments (per warp: rows y0+wy*16+{r,r+8})
    const int yr0 = y0 + wy * 16 + r;
    const int yr1 = yr0 + 8;
    unsigned uH[4][4], uL[4][4];
    #pragma unroll
    for (int ks = 0; ks < 4; ks++) {
        #pragma unroll
        for (int q = 0; q < 4; q++) {
            int row = (q & 1) ? yr1 : yr0;
            int col = ks * 16 + c2 + ((q & 2) ? 8 : 0);
            float v0 = 0.f, v1 = 0.f;
            if (row < YY) {
                if (col < FF)     v0 = U4[(size_t)row * FF + col];
                if (col + 1 < FF) v1 = U4[(size_t)row * FF + col + 1];
            }
            split2(v0, v1, uH[ks][q], uL[ks][q]);
        }
    }

    float D2[8][4];
    #pragma unroll
    for (int n = 0; n < 8; n++)
        #pragma unroll
        for (int i = 0; i < 4; i++) D2[n][i] = 0.f;
    float rs0 = 0.f, rs1 = 0.f;

    const int lrow = tid >> 2;        // staging: l row 0..63
    const int fq = (tid & 3) * 16;    // f quarter

    for (int t = 0; t < 40; t++) {
        const int l0 = t * 64;
        __syncthreads();

        // --- stage hp chunk: [64 l][64 f] bf16 hi/lo + transpose [64 f][64 l]
        {
            const int lg = l0 + lrow;
            const float* src = g_hp + ((size_t)b * LL + lg) * FF;
            #pragma unroll
            for (int j = 0; j < 16; j += 2) {
                float2 p = make_float2(0.f, 0.f);
                if (lg < LL && fq + j < FF) p = *(const float2*)(src + fq + j);
                __nv_bfloat162 hh = __floats2bfloat162_rn(p.x, p.y);
                float q0 = p.x - __bfloat162float(hh.x);
                float q1 = p.y - __bfloat162float(hh.y);
                __nv_bfloat162 llv = __floats2bfloat162_rn(q0, q1);
                int ok = lrow * 72 + fq + j;
                *(unsigned*)&hpk_hi[ok] = *(unsigned*)&hh;
                *(unsigned*)&hpk_lo[ok] = *(unsigned*)&llv;
                hpt_hi[(fq + j) * 72 + lrow]     = hh.x;
                hpt_hi[(fq + j + 1) * 72 + lrow] = hh.y;
                hpt_lo[(fq + j) * 72 + lrow]     = llv.x;
                hpt_lo[(fq + j + 1) * 72 + lrow] = llv.y;
            }
        }
        __syncthreads();

        // --- scores: S[16y x 64l] = U . hp^T (split, 3 products)
        float sw[8][4];
        #pragma unroll
        for (int nt = 0; nt < 8; nt++) {
            #pragma unroll
            for (int i = 0; i < 4; i++) sw[nt][i] = 0.f;
            #pragma unroll
            for (int ks = 0; ks < 4; ks++) {
                int boff = (nt * 8 + r) * 72 + ks * 16 + c2;
                unsigned bh[2], bl[2];
                bh[0] = *(unsigned*)&hpk_hi[boff];
                bh[1] = *(unsigned*)&hpk_hi[boff + 8];
                bl[0] = *(unsigned*)&hpk_lo[boff];
                bl[1] = *(unsigned*)&hpk_lo[boff + 8];
                mma16816(sw[nt], uH[ks], bh);
                mma16816(sw[nt], uH[ks], bl);
                mma16816(sw[nt], uL[ks], bh);
            }
        }

        // --- exp + tail mask + row sums
        const bool full = (l0 + 64 <= LL);
        #pragma unroll
        for (int nt = 0; nt < 8; nt++) {
            float e0 = __expf(sw[nt][0]);
            float e1 = __expf(sw[nt][1]);
            float e2 = __expf(sw[nt][2]);
            float e3 = __expf(sw[nt][3]);
            if (!full) {
                int lc = l0 + nt * 8 + c2;
                if (lc >= LL)     { e0 = 0.f; e2 = 0.f; }
                if (lc + 1 >= LL) { e1 = 0.f; e3 = 0.f; }
            }
            rs0 += e0 + e1;
            rs1 += e2 + e3;
            sw[nt][0] = e0; sw[nt][1] = e1; sw[nt][2] = e2; sw[nt][3] = e3;
        }

        // --- re-fragment exp(S) SPLIT hi/lo as bf16 A-frags
        unsigned aWH[4][4], aWL[4][4];
        #pragma unroll
        for (int kt = 0; kt < 4; kt++) {
            split2(sw[2 * kt][0],     sw[2 * kt][1],     aWH[kt][0], aWL[kt][0]);
            split2(sw[2 * kt][2],     sw[2 * kt][3],     aWH[kt][1], aWL[kt][1]);
            split2(sw[2 * kt + 1][0], sw[2 * kt + 1][1], aWH[kt][2], aWL[kt][2]);
            split2(sw[2 * kt + 1][2], sw[2 * kt + 1][3], aWH[kt][3], aWL[kt][3]);
        }

        // --- m4t accumulate: D2[16y x 64f] += w . hp  (3 products)
        #pragma unroll
        for (int nt = 0; nt < 8; nt++) {
            #pragma unroll
            for (int ks = 0; ks < 4; ks++) {
                int boff = (nt * 8 + r) * 72 + ks * 16 + c2;
                unsigned bh[2], bl[2];
                bh[0] = *(unsigned*)&hpt_hi[boff];
                bh[1] = *(unsigned*)&hpt_hi[boff + 8];
                bl[0] = *(unsigned*)&hpt_lo[boff];
                bl[1] = *(unsigned*)&hpt_lo[boff + 8];
                mma16816(D2[nt], aWH[ks], bh);
                mma16816(D2[nt], aWH[ks], bl);
                mma16816(D2[nt], aWL[ks], bh);
            }
        }
    }

    // --- normalize: row-sum reduce across lane quad
    rs0 += __shfl_xor_sync(0xFFFFFFFF, rs0, 1);
    rs0 += __shfl_xor_sync(0xFFFFFFFF, rs0, 2);
    rs1 += __shfl_xor_sync(0xFFFFFFFF, rs1, 1);
    rs1 += __shfl_xor_sync(0xFFFFFFFF, rs1, 2);
    float inv0 = (yr0 < YY) ? 1.f / rs0 : 0.f;
    float inv1 = (yr1 < YY) ? 1.f / rs1 : 0.f;

    __syncthreads();   // all hp smem reads done; m4s aliases that region
    #pragma unroll
    for (int nt = 0; nt < 8; nt++) {
        int col = nt * 8 + c2;
        m4s[(wy * 16 + r) * 68 + col]         = D2[nt][0] * inv0;
        m4s[(wy * 16 + r) * 68 + col + 1]     = D2[nt][1] * inv0;
        m4s[(wy * 16 + 8 + r) * 68 + col]     = D2[nt][2] * inv1;
        m4s[(wy * 16 + 8 + r) * 68 + col + 1] = D2[nt][3] * inv1;
    }
    __syncthreads();

    // --- epilogue: 2 threads per y
    {
        const int yl = tid >> 1;
        const int half = tid & 1;
        const int y = y0 + yl;
        float m[50];
        #pragma unroll
        for (int f = 0; f < 50; f++) m[f] = m4s[yl * 68 + f];

        // support -> bf16 hi/lo (zero rows for pad y since m == 0)
        const int g0 = half * 25;
        for (int g = g0; g < g0 + 25; g++) {
            float s = 0.f;
            #pragma unroll
            for (int f = 0; f < 50; f++) s += m[f] * gs[f * 50 + g];
            __nv_bfloat16 h = __float2bfloat16(s);
            float rem = s - __bfloat162float(h);
            size_t o = (size_t)(b * FF + g) * YPAD + y;
            g_sup_hi[o] = h;
            g_sup_lo[o] = __float2bfloat16(rem);
        }

        if (y < YY) {
            if (half == 0) {
                const float* wt = f4t_w + (size_t)y * 50;
                float s1 = 0.f;
                #pragma unroll
                for (int f = 0; f < 50; f++) s1 += m[f] * wt[f];
                out[(size_t)b * YY + y] = s1 + f4t_b[y];
            } else {
                const float* w4 = f4_w + (size_t)y * 100;
                float s2 = 0.f;
                #pragma unroll
                for (int f = 0; f < 50; f++) s2 += m[f] * w4[f];
                out[(size_t)BB * YY + (size_t)b * YY + y] = s2 + f4_b[y];
            }
        }
    }
}

// ---------------------------------------------------------------------------
// Kernel 3: out1 = adj @ support via split-bf16 mma.sync (unchanged)
// ---------------------------------------------------------------------------
#define ASTRIDE 72
#define A_TILE (128 * ASTRIDE)
#define B_TILE (80 * ASTRIDE)
#define SM_AHI 0
#define SM_ALO (A_TILE)
#define SM_BHI (2 * A_TILE)
#define SM_BLO (2 * A_TILE + B_TILE)
#define SM_ELEMS (2 * A_TILE + 2 * B_TILE)
#define SMEM_SZ (SM_ELEMS * 2 + 256)

__global__ __launch_bounds__(256) void k_adj_mma(
    const float* __restrict__ adj, const float* __restrict__ gcnb,
    const float* __restrict__ f4w, float* __restrict__ out)
{
    extern __shared__ char smem[];
    __nv_bfloat16* sm = (__nv_bfloat16*)smem;
    float* gb = (float*)(smem + SM_ELEMS * 2);

    const int tid = threadIdx.x;
    const int wid = tid >> 5;
    const int lane = tid & 31;
    const int warp_m = wid & 3;
    const int warp_n = wid >> 2;
    const int r = lane >> 2;
    const int cc = (lane & 3) * 2;

    const int n0 = blockIdx.x * 80;
    const int m0 = blockIdx.y * 128;

    if (tid < 50) gb[tid] = gcnb[tid];

    float d[2][5][4];
    #pragma unroll
    for (int mt = 0; mt < 2; mt++)
        #pragma unroll
        for (int nt = 0; nt < 5; nt++)
            #pragma unroll
            for (int i = 0; i < 4; i++) d[mt][nt][i] = 0.f;

    for (int t = 0; t < NCHUNK; t++) {
        const int z0 = t * 64;
        __syncthreads();

        for (int i = tid; i < 4096; i += 256) {
            int row = i >> 5, p = i & 31;
            int gm = m0 + row;
            int z = z0 + 2 * p;
            float v0 = 0.f, v1 = 0.f;
            if (gm < YY) {
                if (z + 1 < YY) {
                    float2 w = *(const float2*)(adj + (size_t)gm * YY + z);
                    v0 = w.x; v1 = w.y;
                } else if (z < YY) {
                    v0 = adj[(size_t)gm * YY + z];
                }
            }
            unsigned hiw, low;
            split2(v0, v1, hiw, low);
            int off = row * ASTRIDE + 2 * p;
            *(uint32_t*)&sm[SM_AHI + off] = hiw;
            *(uint32_t*)&sm[SM_ALO + off] = low;
        }

        for (int i = tid; i < 640; i += 256) {
            int n = i >> 3, grp = i & 7;
            size_t o = (size_t)(n0 + n) * YPAD + z0 + grp * 8;
            uint4 vh = *(const uint4*)(g_sup_hi + o);
            uint4 vl = *(const uint4*)(g_sup_lo + o);
            int off = n * ASTRIDE + grp * 8;
            *(uint4*)&sm[SM_BHI + off] = vh;
            *(uint4*)&sm[SM_BLO + off] = vl;
        }
        __syncthreads();

        #pragma unroll
        for (int ks = 0; ks < 4; ks++) {
            const int kc = ks * 16 + cc;
            unsigned aH[2][4], aL[2][4], bH[5][2], bL[5][2];
            #pragma unroll
            for (int mt = 0; mt < 2; mt++) {
                int row = warp_m * 32 + mt * 16 + r;
                aH[mt][0] = *(const unsigned*)&sm[SM_AHI + row * ASTRIDE + kc];
                aH[mt][1] = *(const unsigned*)&sm[SM_AHI + (row + 8) * ASTRIDE + kc];
                aH[mt][2] = *(const unsigned*)&sm[SM_AHI + row * ASTRIDE + kc + 8];
                aH[mt][3] = *(const unsigned*)&sm[SM_AHI + (row + 8) * ASTRIDE + kc + 8];
                aL[mt][0] = *(const unsigned*)&sm[SM_ALO + row * ASTRIDE + kc];
                aL[mt][1] = *(const unsigned*)&sm[SM_ALO + (row + 8) * ASTRIDE + kc];
                aL[mt][2] = *(const unsigned*)&sm[SM_ALO + row * ASTRIDE + kc + 8];
                aL[mt][3] = *(const unsigned*)&sm[SM_ALO + (row + 8) * ASTRIDE + kc + 8];
            }
            #pragma unroll
            for (int nt = 0; nt < 5; nt++) {
                int n = warp_n * 40 + nt * 8 + r;
                bH[nt][0] = *(const unsigned*)&sm[SM_BHI + n * ASTRIDE + kc];
                bH[nt][1] = *(const unsigned*)&sm[SM_BHI + n * ASTRIDE + kc + 8];
                bL[nt][0] = *(const unsigned*)&sm[SM_BLO + n * ASTRIDE + kc];
                bL[nt][1] = *(const unsigned*)&sm[SM_BLO + n * ASTRIDE + kc + 8];
            }
            #pragma unroll
            for (int mt = 0; mt < 2; mt++)
                #pragma unroll
                for (int nt = 0; nt < 5; nt++) {
                    mma16816(d[mt][nt], aH[mt], bH[nt]);
                    mma16816(d[mt][nt], aH[mt], bL[nt]);
                    mma16816(d[mt][nt], aL[mt], bH[nt]);
                }
        }
    }

    const size_t obase = (size_t)BB * YY;
    #pragma unroll
    for (int mt = 0; mt < 2; mt++) {
        int row0 = m0 + warp_m * 32 + mt * 16 + r;
        #pragma unroll
        for (int nt = 0; nt < 5; nt++) {
            int col0 = n0 + warp_n * 40 + nt * 8 + cc;
            int b = col0 / 50;
            int g = col0 - b * 50;
            float gb0 = gb[g], gb1 = gb[g + 1];
            #pragma unroll
            for (int rr = 0; rr < 2; rr++) {
                int y = row0 + rr * 8;
                if (y < YY) {
                    float v0 = d[mt][nt][rr * 2 + 0] + gb0;
                    float v1 = d[mt][nt][rr * 2 + 1] + gb1;
                    v0 = v0 > 0.f ? v0 : 0.2f * v0;
                    v1 = v1 > 0.f ? v1 : 0.2f * v1;
                    const float* fw = f4w + (size_t)y * 100 + 50;
                    float s = v0 * fw[g] + v1 * fw[g + 1];
                    atomicAdd(&out[obase + (size_t)b * YY + y], s);
                }
            }
        }
    }
}

// ---------------------------------------------------------------------------
extern "C" void kernel_launch(void* const* d_in, const int* in_sizes, int n_in,
                              void* d_out, int out_size)
{
    const int*   x     = (const int*)  d_in[0];
    const float* embw  = (const float*)d_in[2];
    const float* convw = (const float*)d_in[3];
    const float* convb = (const float*)d_in[4];
    const float* U4    = (const float*)d_in[5];
    const float* gcnw  = (const float*)d_in[6];
    const float* gcnb  = (const float*)d_in[7];
    const float* adj   = (const float*)d_in[8];
    const float* f4tw  = (const float*)d_in[9];
    const float* f4tb  = (const float*)d_in[10];
    const float* f4w   = (const float*)d_in[11];
    const float* f4b   = (const float*)d_in[12];
    float* out = (float*)d_out;

    static int smem_set = 0;
    if (!smem_set) {
        cudaFuncSetAttribute(k_adj_mma, cudaFuncAttributeMaxDynamicSharedMemorySize, SMEM_SZ);
        smem_set = 1;
    }

    k_embconv <<<dim3(40, BB), 256>>>(x, embw, convw, convb);
    k_attn_mma<<<dim3(70, BB), 256>>>(U4, gcnw, f4tw, f4tb, f4w, f4b, out);
    k_adj_mma <<<dim3(5, 70), 256, SMEM_SZ>>>(adj, gcnb, f4w, out);
}

// round 12
// speedup vs baseline: 2.8238x; 1.4931x over previous
#include <cuda_runtime.h>
#include <cuda_bf16.h>
#include <math.h>
#include <cstdint>

#define BB 8
#define LL 2500
#define LPAD 2560       // 40 chunks of 64
#define EE 100
#define FF 50
#define KK 9
#define YY 8922
#define NC (BB*FF)      // 400
#define YPAD 8960       // 70*128 = 140*64
#define NCHUNK 140      // K chunks of 64 for adj GEMM

typedef unsigned long long ull;

// Scratch (no allocations allowed)
__device__ __nv_bfloat16 g_hpk_hi[BB*LPAD*64];   // [b][l][f]
__device__ __nv_bfloat16 g_hpk_lo[BB*LPAD*64];
__device__ __nv_bfloat16 g_hpt_hi[BB*64*LPAD];   // [b][f][l]
__device__ __nv_bfloat16 g_hpt_lo[BB*64*LPAD];
__device__ __nv_bfloat16 g_sup_hi[NC*YPAD];      // [n400][z]
__device__ __nv_bfloat16 g_sup_lo[NC*YPAD];

// ---------------------------------------------------------------------------
// helpers
// ---------------------------------------------------------------------------
__device__ __forceinline__ void mma16816(float d[4], const unsigned a[4], const unsigned b[2]) {
    asm volatile(
        "mma.sync.aligned.m16n8k16.row.col.f32.bf16.bf16.f32 "
        "{%0,%1,%2,%3}, {%4,%5,%6,%7}, {%8,%9}, {%0,%1,%2,%3};"
        : "+f"(d[0]), "+f"(d[1]), "+f"(d[2]), "+f"(d[3])
        : "r"(a[0]), "r"(a[1]), "r"(a[2]), "r"(a[3]), "r"(b[0]), "r"(b[1]));
}
__device__ __forceinline__ void split2(float x, float y, unsigned& hi, unsigned& lo) {
    __nv_bfloat162 hh = __floats2bfloat162_rn(x, y);
    float r0 = x - __bfloat162float(hh.x);
    float r1 = y - __bfloat162float(hh.y);
    __nv_bfloat162 llv = __floats2bfloat162_rn(r0, r1);
    hi = *(unsigned*)&hh;
    lo = *(unsigned*)&llv;
}
__device__ __forceinline__ uint32_t smem_u32(const void* p) {
    uint32_t a;
    asm("{ .reg .u64 t; cvta.to.shared.u64 t, %1; cvt.u32.u64 %0, t; }" : "=r"(a) : "l"(p));
    return a;
}
__device__ __forceinline__ void cp16(uint32_t dst, const void* src) {
    asm volatile("cp.async.cg.shared.global [%0], [%1], 16;" :: "r"(dst), "l"(src) : "memory");
}
#define CP_COMMIT() asm volatile("cp.async.commit_group;" ::: "memory")
#define CP_WAIT1()  asm volatile("cp.async.wait_group 1;" ::: "memory")

// ---------------------------------------------------------------------------
// Kernel 1: embedding + conv1d + tanh -> bf16 hi/lo in BOTH layouts (padded,
// pads zeroed). grid (40, B) covers l 0..2559.
// ---------------------------------------------------------------------------
__global__ __launch_bounds__(256) void k_embconv(
    const int* __restrict__ x, const float* __restrict__ embw,
    const float* __restrict__ convw, const float* __restrict__ convb)
{
    __shared__ float es[72][101];
    __shared__ float ws[100][64];

    const int b  = blockIdx.y;
    const int l0 = blockIdx.x * 64;
    const int tid = threadIdx.x;

    for (int idx = tid; idx < 72 * 100; idx += 256) {
        int r = idx / 100, e = idx - r * 100;
        int l = l0 - 4 + r;
        float v = 0.f;
        if (l >= 0 && l < LL) {
            int tok = x[b * LL + l];
            v = embw[(size_t)tok * EE + e];
        }
        es[r][e] = v;
    }

    const int fx = tid & 15;
    const int ly = tid >> 4;
    float acc[4][4] = {};

    for (int k = 0; k < KK; k++) {
        __syncthreads();
        for (int idx = tid; idx < 100 * 64; idx += 256) {
            int e = idx >> 6, f = idx & 63;
            ws[e][f] = (f < FF) ? convw[f * (EE * KK) + e * KK + k] : 0.f;
        }
        __syncthreads();
        #pragma unroll 4
        for (int e = 0; e < EE; e++) {
            float av[4], wv[4];
            #pragma unroll
            for (int i = 0; i < 4; i++) av[i] = es[ly + 16 * i + k][e];
            #pragma unroll
            for (int j = 0; j < 4; j++) wv[j] = ws[e][fx + 16 * j];
            #pragma unroll
            for (int i = 0; i < 4; i++)
                #pragma unroll
                for (int j = 0; j < 4; j++)
                    acc[i][j] += av[i] * wv[j];
        }
    }

    #pragma unroll
    for (int i = 0; i < 4; i++) {
        int l = l0 + ly + 16 * i;          // < 2560 always
        #pragma unroll
        for (int j = 0; j < 4; j++) {
            int f = fx + 16 * j;           // < 64 always
            float val = 0.f;
            if (l < LL && f < FF) val = tanhf(acc[i][j] + convb[f]);
            __nv_bfloat16 h = __float2bfloat16(val);
            __nv_bfloat16 lo = __float2bfloat16(val - __bfloat162float(h));
            size_t ok = ((size_t)b * LPAD + l) * 64 + f;
            g_hpk_hi[ok] = h;
            g_hpk_lo[ok] = lo;
            size_t ot = ((size_t)b * 64 + f) * LPAD + l;
            g_hpt_hi[ot] = h;
            g_hpt_lo[ot] = lo;
        }
    }
}

// ---------------------------------------------------------------------------
// Kernel 2 (HMMA): per-label attention, flash-style, cp.async double-buffered.
// grid (70, B), block 256 (8 warps, 16 y each). 40 l-chunks of 64.
// Smem (dynamic): 2 stages x 36864 (hpk hi/lo + hpt hi/lo, stride 144B) +
// gcn_w at 73728. m4s aliases stage region after the main loop.
// ---------------------------------------------------------------------------
#define ATT_STG 36864
#define ATT_GS  73728
#define ATT_SMEM (73728 + 10016)

__global__ __launch_bounds__(256) void k_attn_mma(
    const float* __restrict__ U4, const float* __restrict__ gcnw,
    const float* __restrict__ f4t_w, const float* __restrict__ f4t_b,
    const float* __restrict__ f4_w, const float* __restrict__ f4_b,
    float* __restrict__ out)
{
    extern __shared__ __align__(16) char smd[];
    const uint32_t sb = smem_u32(smd);
    float* gs = (float*)(smd + ATT_GS);
    float* m4s = (float*)smd;              // [128][68] after main loop

    const int b = blockIdx.y;
    const int y0 = blockIdx.x * 128;
    const int tid = threadIdx.x;
    const int wy = tid >> 5;
    const int lane = tid & 31;
    const int r = lane >> 2;
    const int c2 = (lane & 3) * 2;

    for (int i = tid; i < 2500; i += 256) gs[i] = gcnw[i];

    // stage chunk t into buffer s (pure cp.async, data pre-split & pre-padded)
    auto stage = [&](int t, int s) {
        const int l0c = t * 64;
        const uint32_t base = sb + s * ATT_STG;
        #pragma unroll
        for (int it = 0; it < 2; it++) {
            int idx = tid + it * 256;      // 0..511
            int row = idx >> 3, c = idx & 7;
            uint32_t d0 = base + row * 144 + c * 16;
            size_t srck = ((size_t)b * LPAD + l0c + row) * 64 + c * 8;
            cp16(d0,         g_hpk_hi + srck);
            cp16(d0 + 9216,  g_hpk_lo + srck);
            size_t srct = ((size_t)b * 64 + row) * LPAD + l0c + c * 8;
            cp16(d0 + 18432, g_hpt_hi + srct);
            cp16(d0 + 27648, g_hpt_lo + srct);
        }
    };

    // --- preload U4 split A-fragments
    const int yr0 = y0 + wy * 16 + r;
    const int yr1 = yr0 + 8;
    unsigned uH[4][4], uL[4][4];
    #pragma unroll
    for (int ks = 0; ks < 4; ks++) {
        #pragma unroll
        for (int q = 0; q < 4; q++) {
            int row = (q & 1) ? yr1 : yr0;
            int col = ks * 16 + c2 + ((q & 2) ? 8 : 0);
            float v0 = 0.f, v1 = 0.f;
            if (row < YY) {
                if (col < FF)     v0 = U4[(size_t)row * FF + col];
                if (col + 1 < FF) v1 = U4[(size_t)row * FF + col + 1];
            }
            split2(v0, v1, uH[ks][q], uL[ks][q]);
        }
    }

    float D2[8][4];
    #pragma unroll
    for (int n = 0; n < 8; n++)
        #pragma unroll
        for (int i = 0; i < 4; i++) D2[n][i] = 0.f;
    float rs0 = 0.f, rs1 = 0.f;

    stage(0, 0); CP_COMMIT();
    stage(1, 1); CP_COMMIT();
    CP_WAIT1();                            // stage 0 complete
    __syncthreads();

    for (int t = 0; t < 40; t++) {
        const int s = t & 1;
        const int l0 = t * 64;
        const __nv_bfloat16* hpk_hi = (const __nv_bfloat16*)(smd + s * ATT_STG);
        const __nv_bfloat16* hpk_lo = (const __nv_bfloat16*)(smd + s * ATT_STG + 9216);
        const __nv_bfloat16* hpt_hi = (const __nv_bfloat16*)(smd + s * ATT_STG + 18432);
        const __nv_bfloat16* hpt_lo = (const __nv_bfloat16*)(smd + s * ATT_STG + 27648);

        // --- scores: S[16y x 64l] = U . hp^T (split, 3 products)
        float sw[8][4];
        #pragma unroll
        for (int nt = 0; nt < 8; nt++) {
            #pragma unroll
            for (int i = 0; i < 4; i++) sw[nt][i] = 0.f;
            #pragma unroll
            for (int ks = 0; ks < 4; ks++) {
                int boff = (nt * 8 + r) * 72 + ks * 16 + c2;
                unsigned bh[2], bl[2];
                bh[0] = *(unsigned*)&hpk_hi[boff];
                bh[1] = *(unsigned*)&hpk_hi[boff + 8];
                bl[0] = *(unsigned*)&hpk_lo[boff];
                bl[1] = *(unsigned*)&hpk_lo[boff + 8];
                mma16816(sw[nt], uH[ks], bh);
                mma16816(sw[nt], uH[ks], bl);
                mma16816(sw[nt], uL[ks], bh);
            }
        }

        // --- exp + tail mask + row sums
        const bool full = (l0 + 64 <= LL);
        #pragma unroll
        for (int nt = 0; nt < 8; nt++) {
            float e0 = __expf(sw[nt][0]);
            float e1 = __expf(sw[nt][1]);
            float e2 = __expf(sw[nt][2]);
            float e3 = __expf(sw[nt][3]);
            if (!full) {
                int lc = l0 + nt * 8 + c2;
                if (lc >= LL)     { e0 = 0.f; e2 = 0.f; }
                if (lc + 1 >= LL) { e1 = 0.f; e3 = 0.f; }
            }
            rs0 += e0 + e1;
            rs1 += e2 + e3;
            sw[nt][0] = e0; sw[nt][1] = e1; sw[nt][2] = e2; sw[nt][3] = e3;
        }

        // --- re-fragment exp(S) split hi/lo as A-frags
        unsigned aWH[4][4], aWL[4][4];
        #pragma unroll
        for (int kt = 0; kt < 4; kt++) {
            split2(sw[2 * kt][0],     sw[2 * kt][1],     aWH[kt][0], aWL[kt][0]);
            split2(sw[2 * kt][2],     sw[2 * kt][3],     aWH[kt][1], aWL[kt][1]);
            split2(sw[2 * kt + 1][0], sw[2 * kt + 1][1], aWH[kt][2], aWL[kt][2]);
            split2(sw[2 * kt + 1][2], sw[2 * kt + 1][3], aWH[kt][3], aWL[kt][3]);
        }

        // --- m4t accumulate: D2 += w . hp  (3 products)
        #pragma unroll
        for (int nt = 0; nt < 8; nt++) {
            #pragma unroll
            for (int ks = 0; ks < 4; ks++) {
                int boff = (nt * 8 + r) * 72 + ks * 16 + c2;
                unsigned bh[2], bl[2];
                bh[0] = *(unsigned*)&hpt_hi[boff];
                bh[1] = *(unsigned*)&hpt_hi[boff + 8];
                bl[0] = *(unsigned*)&hpt_lo[boff];
                bl[1] = *(unsigned*)&hpt_lo[boff + 8];
                mma16816(D2[nt], aWH[ks], bh);
                mma16816(D2[nt], aWH[ks], bl);
                mma16816(D2[nt], aWL[ks], bh);
            }
        }

        __syncthreads();                    // all reads of stage t done
        if (t + 2 < 40) stage(t + 2, s);    // refill this buffer
        CP_COMMIT();
        CP_WAIT1();                         // stage t+1 complete
        __syncthreads();
    }

    // --- normalize
    rs0 += __shfl_xor_sync(0xFFFFFFFF, rs0, 1);
    rs0 += __shfl_xor_sync(0xFFFFFFFF, rs0, 2);
    rs1 += __shfl_xor_sync(0xFFFFFFFF, rs1, 1);
    rs1 += __shfl_xor_sync(0xFFFFFFFF, rs1, 2);
    float inv0 = (yr0 < YY) ? 1.f / rs0 : 0.f;
    float inv1 = (yr1 < YY) ? 1.f / rs1 : 0.f;

    #pragma unroll
    for (int nt = 0; nt < 8; nt++) {
        int col = nt * 8 + c2;
        m4s[(wy * 16 + r) * 68 + col]         = D2[nt][0] * inv0;
        m4s[(wy * 16 + r) * 68 + col + 1]     = D2[nt][1] * inv0;
        m4s[(wy * 16 + 8 + r) * 68 + col]     = D2[nt][2] * inv1;
        m4s[(wy * 16 + 8 + r) * 68 + col + 1] = D2[nt][3] * inv1;
    }
    __syncthreads();

    // --- epilogue: 2 threads per y
    {
        const int yl = tid >> 1;
        const int half = tid & 1;
        const int y = y0 + yl;
        float m[50];
        #pragma unroll
        for (int f = 0; f < 50; f++) m[f] = m4s[yl * 68 + f];

        const int g0 = half * 25;
        for (int g = g0; g < g0 + 25; g++) {
            float s = 0.f;
            #pragma unroll
            for (int f = 0; f < 50; f++) s += m[f] * gs[f * 50 + g];
            __nv_bfloat16 h = __float2bfloat16(s);
            float rem = s - __bfloat162float(h);
            size_t o = (size_t)(b * FF + g) * YPAD + y;
            g_sup_hi[o] = h;
            g_sup_lo[o] = __float2bfloat16(rem);
        }

        if (y < YY) {
            if (half == 0) {
                const float* wt = f4t_w + (size_t)y * 50;
                float s1 = 0.f;
                #pragma unroll
                for (int f = 0; f < 50; f++) s1 += m[f] * wt[f];
                out[(size_t)b * YY + y] = s1 + f4t_b[y];
            } else {
                const float* w4 = f4_w + (size_t)y * 100;
                float s2 = 0.f;
                #pragma unroll
                for (int f = 0; f < 50; f++) s2 += m[f] * w4[f];
                out[(size_t)BB * YY + (size_t)b * YY + y] = s2 + f4_b[y];
            }
        }
    }
}

// ---------------------------------------------------------------------------
// Kernel 3: out1 = adj @ support, split-bf16 HMMA, double-buffered:
// A (adj) register-prefetch + convert/STS; B (support) cp.async.
// grid (5, 70), block 256. Smem (dynamic): A 2x36864 + B 2x23040 + gb.
// ---------------------------------------------------------------------------
#define ADJ_ASTG 36864                 // per A stage (hi 18432 + lo 18432)
#define ADJ_BBASE 73728
#define ADJ_BSTG 23040                 // per B stage (hi 11520 + lo 11520)
#define ADJ_GB (73728 + 46080)
#define ADJ_SMEM (ADJ_GB + 256)

__global__ __launch_bounds__(256) void k_adj_mma(
    const float* __restrict__ adj, const float* __restrict__ gcnb,
    const float* __restrict__ f4w, float* __restrict__ out)
{
    extern __shared__ __align__(16) char smd[];
    const uint32_t sb = smem_u32(smd);
    float* gb = (float*)(smd + ADJ_GB);

    const int tid = threadIdx.x;
    const int wid = tid >> 5;
    const int lane = tid & 31;
    const int warp_m = wid & 3;
    const int warp_n = wid >> 2;
    const int r = lane >> 2;
    const int cc = (lane & 3) * 2;

    const int n0 = blockIdx.x * 80;
    const int m0 = blockIdx.y * 128;

    if (tid < 50) gb[tid] = gcnb[tid];

    float2 av[16];

    auto ldgA = [&](int t) {
        const int z0 = t * 64;
        #pragma unroll
        for (int k = 0; k < 16; k++) {
            int i = tid + k * 256;
            int row = i >> 5, p = i & 31;
            int gm = m0 + row, z = z0 + 2 * p;
            float2 v = make_float2(0.f, 0.f);
            if (gm < YY) {
                if (z + 1 < YY) v = *(const float2*)(adj + (size_t)gm * YY + z);
                else if (z < YY) v.x = adj[(size_t)gm * YY + z];
            }
            av[k] = v;
        }
    };
    auto stsA = [&](int s) {
        const uint32_t base = sb + s * ADJ_ASTG;
        #pragma unroll
        for (int k = 0; k < 16; k++) {
            int i = tid + k * 256;
            int row = i >> 5, p = i & 31;
            unsigned hi, lo;
            split2(av[k].x, av[k].y, hi, lo);
            uint32_t d = base + row * 144 + p * 4;
            *(unsigned*)(smd + (d - sb)) = hi;
            *(unsigned*)(smd + (d - sb) + 18432) = lo;
        }
    };
    auto stageB = [&](int t, int s) {
        const int z0 = t * 64;
        const uint32_t base = sb + ADJ_BBASE + s * ADJ_BSTG;
        for (int i = tid; i < 640; i += 256) {
            int n = i >> 3, c = i & 7;
            size_t o = (size_t)(n0 + n) * YPAD + z0 + c * 8;
            uint32_t d = base + n * 144 + c * 16;
            cp16(d,         g_sup_hi + o);
            cp16(d + 11520, g_sup_lo + o);
        }
    };

    float d[2][5][4];
    #pragma unroll
    for (int mt = 0; mt < 2; mt++)
        #pragma unroll
        for (int nt = 0; nt < 5; nt++)
            #pragma unroll
            for (int i = 0; i < 4; i++) d[mt][nt][i] = 0.f;

    // preloop
    ldgA(0); stageB(0, 0); CP_COMMIT();
    stsA(0);
    ldgA(1); stageB(1, 1); CP_COMMIT();
    CP_WAIT1();                            // B0 done
    __syncthreads();

    for (int t = 0; t < NCHUNK; t++) {
        const int s = t & 1;
        const __nv_bfloat16* aHp = (const __nv_bfloat16*)(smd + s * ADJ_ASTG);
        const __nv_bfloat16* aLp = (const __nv_bfloat16*)(smd + s * ADJ_ASTG + 18432);
        const __nv_bfloat16* bHp = (const __nv_bfloat16*)(smd + ADJ_BBASE + s * ADJ_BSTG);
        const __nv_bfloat16* bLp = (const __nv_bfloat16*)(smd + ADJ_BBASE + s * ADJ_BSTG + 11520);

        #pragma unroll
        for (int ks = 0; ks < 4; ks++) {
            const int kc = ks * 16 + cc;
            unsigned aH[2][4], aL[2][4], bH[5][2], bL[5][2];
            #pragma unroll
            for (int mt = 0; mt < 2; mt++) {
                int row = warp_m * 32 + mt * 16 + r;
                aH[mt][0] = *(const unsigned*)&aHp[row * 72 + kc];
                aH[mt][1] = *(const unsigned*)&aHp[(row + 8) * 72 + kc];
                aH[mt][2] = *(const unsigned*)&aHp[row * 72 + kc + 8];
                aH[mt][3] = *(const unsigned*)&aHp[(row + 8) * 72 + kc + 8];
                aL[mt][0] = *(const unsigned*)&aLp[row * 72 + kc];
                aL[mt][1] = *(const unsigned*)&aLp[(row + 8) * 72 + kc];
                aL[mt][2] = *(const unsigned*)&aLp[row * 72 + kc + 8];
                aL[mt][3] = *(const unsigned*)&aLp[(row + 8) * 72 + kc + 8];
            }
            #pragma unroll
            for (int nt = 0; nt < 5; nt++) {
                int n = warp_n * 40 + nt * 8 + r;
                bH[nt][0] = *(const unsigned*)&bHp[n * 72 + kc];
                bH[nt][1] = *(const unsigned*)&bHp[n * 72 + kc + 8];
                bL[nt][0] = *(const unsigned*)&bLp[n * 72 + kc];
                bL[nt][1] = *(const unsigned*)&bLp[n * 72 + kc + 8];
            }
            #pragma unroll
            for (int mt = 0; mt < 2; mt++)
                #pragma unroll
                for (int nt = 0; nt < 5; nt++) {
                    mma16816(d[mt][nt], aH[mt], bH[nt]);
                    mma16816(d[mt][nt], aH[mt], bL[nt]);
                    mma16816(d[mt][nt], aL[mt], bH[nt]);
                }
        }

        __syncthreads();                    // stage t fully consumed
        if (t + 1 < NCHUNK) stsA((t + 1) & 1);           // A(t+1) -> idle buf
        if (t + 2 < NCHUNK) { ldgA(t + 2); stageB(t + 2, s); }
        CP_COMMIT();
        CP_WAIT1();                         // B(t+1) done
        __syncthreads();
    }

    const size_t obase = (size_t)BB * YY;
    #pragma unroll
    for (int mt = 0; mt < 2; mt++) {
        int row0 = m0 + warp_m * 32 + mt * 16 + r;
        #pragma unroll
        for (int nt = 0; nt < 5; nt++) {
            int col0 = n0 + warp_n * 40 + nt * 8 + cc;
            int b = col0 / 50;
            int g = col0 - b * 50;
            float gb0 = gb[g], gb1 = gb[g + 1];
            #pragma unroll
            for (int rr = 0; rr < 2; rr++) {
                int y = row0 + rr * 8;
                if (y < YY) {
                    float v0 = d[mt][nt][rr * 2 + 0] + gb0;
                    float v1 = d[mt][nt][rr * 2 + 1] + gb1;
                    v0 = v0 > 0.f ? v0 : 0.2f * v0;
                    v1 = v1 > 0.f ? v1 : 0.2f * v1;
                    const float* fw = f4w + (size_t)y * 100 + 50;
                    float s = v0 * fw[g] + v1 * fw[g + 1];
                    atomicAdd(&out[obase + (size_t)b * YY + y], s);
                }
            }
        }
    }
}

// ---------------------------------------------------------------------------
extern "C" void kernel_launch(void* const* d_in, const int* in_sizes, int n_in,
                              void* d_out, int out_size)
{
    const int*   x     = (const int*)  d_in[0];
    const float* embw  = (const float*)d_in[2];
    const float* convw = (const float*)d_in[3];
    const float* convb = (const float*)d_in[4];
    const float* U4    = (const float*)d_in[5];
    const float* gcnw  = (const float*)d_in[6];
    const float* gcnb  = (const float*)d_in[7];
    const float* adj   = (const float*)d_in[8];
    const float* f4tw  = (const float*)d_in[9];
    const float* f4tb  = (const float*)d_in[10];
    const float* f4w   = (const float*)d_in[11];
    const float* f4b   = (const float*)d_in[12];
    float* out = (float*)d_out;

    cudaFuncSetAttribute(k_attn_mma, cudaFuncAttributeMaxDynamicSharedMemorySize, ATT_SMEM);
    cudaFuncSetAttribute(k_adj_mma,  cudaFuncAttributeMaxDynamicSharedMemorySize, ADJ_SMEM);

    k_embconv <<<dim3(40, BB), 256>>>(x, embw, convw, convb);
    k_attn_mma<<<dim3(70, BB), 256, ATT_SMEM>>>(U4, gcnw, f4tw, f4tb, f4w, f4b, out);
    k_adj_mma <<<dim3(5, 70), 256, ADJ_SMEM>>>(adj, gcnb, f4w, out);
}

// round 13
// speedup vs baseline: 3.0812x; 1.0911x over previous
#include <cuda_runtime.h>
#include <cuda_bf16.h>
#include <math.h>
#include <cstdint>

#define BB 8
#define LL 2500
#define LPAD 2560       // 40 chunks of 64
#define EE 100
#define FF 50
#define KK 9
#define YY 8922
#define NC (BB*FF)      // 400
#define YPAD 8960       // 70*128 = 140*64
#define NCHUNK 140      // K chunks of 64 for adj GEMM

typedef unsigned long long ull;

// Scratch (no allocations allowed)
__device__ __nv_bfloat16 g_hpk_hi[BB*LPAD*64];   // [b][l][f]
__device__ __nv_bfloat16 g_hpk_lo[BB*LPAD*64];
__device__ __nv_bfloat16 g_hpt_hi[BB*64*LPAD];   // [b][f][l]
__device__ __nv_bfloat16 g_hpt_lo[BB*64*LPAD];
__device__ __nv_bfloat16 g_sup_hi[NC*YPAD];      // [n400][z]
__device__ __nv_bfloat16 g_sup_lo[NC*YPAD];

// ---------------------------------------------------------------------------
// helpers
// ---------------------------------------------------------------------------
__device__ __forceinline__ void mma16816(float d[4], const unsigned a[4], const unsigned b[2]) {
    asm volatile(
        "mma.sync.aligned.m16n8k16.row.col.f32.bf16.bf16.f32 "
        "{%0,%1,%2,%3}, {%4,%5,%6,%7}, {%8,%9}, {%0,%1,%2,%3};"
        : "+f"(d[0]), "+f"(d[1]), "+f"(d[2]), "+f"(d[3])
        : "r"(a[0]), "r"(a[1]), "r"(a[2]), "r"(a[3]), "r"(b[0]), "r"(b[1]));
}
__device__ __forceinline__ void split2(float x, float y, unsigned& hi, unsigned& lo) {
    __nv_bfloat162 hh = __floats2bfloat162_rn(x, y);
    float r0 = x - __bfloat162float(hh.x);
    float r1 = y - __bfloat162float(hh.y);
    __nv_bfloat162 llv = __floats2bfloat162_rn(r0, r1);
    hi = *(unsigned*)&hh;
    lo = *(unsigned*)&llv;
}
__device__ __forceinline__ uint32_t smem_u32(const void* p) {
    uint32_t a;
    asm("{ .reg .u64 t; cvta.to.shared.u64 t, %1; cvt.u32.u64 %0, t; }" : "=r"(a) : "l"(p));
    return a;
}
__device__ __forceinline__ void cp16(uint32_t dst, const void* src) {
    asm volatile("cp.async.cg.shared.global [%0], [%1], 16;" :: "r"(dst), "l"(src) : "memory");
}
#define CP_COMMIT() asm volatile("cp.async.commit_group;" ::: "memory")
#define CP_WAIT1()  asm volatile("cp.async.wait_group 1;" ::: "memory")

__device__ __forceinline__ void ldm_x4(unsigned r[4], uint32_t addr) {
    asm volatile("ldmatrix.sync.aligned.m8n8.x4.shared.b16 {%0,%1,%2,%3}, [%4];"
        : "=r"(r[0]), "=r"(r[1]), "=r"(r[2]), "=r"(r[3]) : "r"(addr));
}
__device__ __forceinline__ void ldm_x2(unsigned r[2], uint32_t addr) {
    asm volatile("ldmatrix.sync.aligned.m8n8.x2.shared.b16 {%0,%1}, [%2];"
        : "=r"(r[0]), "=r"(r[1]) : "r"(addr));
}

// ---------------------------------------------------------------------------
// Kernel 1: embedding + conv1d + tanh -> bf16 hi/lo in BOTH layouts.
// Vectorized: ws staged f-major, float4 LDS in the hot loop.
// ---------------------------------------------------------------------------
__global__ __launch_bounds__(256) void k_embconv(
    const int* __restrict__ x, const float* __restrict__ embw,
    const float* __restrict__ convw, const float* __restrict__ convb)
{
    __shared__ float es[72][104];      // 416B rows, float4-aligned
    __shared__ float ws2[64][108];     // f-major, stride 108 (conflict-free)

    const int b  = blockIdx.y;
    const int l0 = blockIdx.x * 64;
    const int tid = threadIdx.x;

    for (int idx = tid; idx < 72 * 100; idx += 256) {
        int r = idx / 100, e = idx - r * 100;
        int l = l0 - 4 + r;
        float v = 0.f;
        if (l >= 0 && l < LL) {
            int tok = x[b * LL + l];
            v = embw[(size_t)tok * EE + e];
        }
        es[r][e] = v;
    }

    const int fx = tid & 15;
    const int ly = tid >> 4;
    float acc[4][4] = {};

    for (int k = 0; k < KK; k++) {
        __syncthreads();
        for (int idx = tid; idx < 6400; idx += 256) {
            int f = idx & 63, e = idx >> 6;
            ws2[f][e] = (f < FF) ? convw[f * (EE * KK) + e * KK + k] : 0.f;
        }
        __syncthreads();
        #pragma unroll 5
        for (int e = 0; e < EE; e += 4) {
            float4 av4[4], wv4[4];
            #pragma unroll
            for (int i = 0; i < 4; i++) av4[i] = *(const float4*)&es[ly + 16 * i + k][e];
            #pragma unroll
            for (int j = 0; j < 4; j++) wv4[j] = *(const float4*)&ws2[fx + 16 * j][e];
            #pragma unroll
            for (int i = 0; i < 4; i++)
                #pragma unroll
                for (int j = 0; j < 4; j++) {
                    acc[i][j] += av4[i].x * wv4[j].x;
                    acc[i][j] += av4[i].y * wv4[j].y;
                    acc[i][j] += av4[i].z * wv4[j].z;
                    acc[i][j] += av4[i].w * wv4[j].w;
                }
        }
    }

    #pragma unroll
    for (int i = 0; i < 4; i++) {
        int l = l0 + ly + 16 * i;          // < 2560 always
        #pragma unroll
        for (int j = 0; j < 4; j++) {
            int f = fx + 16 * j;           // < 64 always
            float val = 0.f;
            if (l < LL && f < FF) val = tanhf(acc[i][j] + convb[f]);
            __nv_bfloat16 h = __float2bfloat16(val);
            __nv_bfloat16 lo = __float2bfloat16(val - __bfloat162float(h));
            size_t ok = ((size_t)b * LPAD + l) * 64 + f;
            g_hpk_hi[ok] = h;
            g_hpk_lo[ok] = lo;
            size_t ot = ((size_t)b * 64 + f) * LPAD + l;
            g_hpt_hi[ot] = h;
            g_hpt_lo[ot] = lo;
        }
    }
}

// ---------------------------------------------------------------------------
// Kernel 2 (HMMA): attention, flash-style, cp.async double-buffered,
// ldmatrix fragment loads. grid (70, B), block 256.
// ---------------------------------------------------------------------------
#define ATT_STG 36864
#define ATT_GS  73728
#define ATT_SMEM (73728 + 10016)

__global__ __launch_bounds__(256) void k_attn_mma(
    const float* __restrict__ U4, const float* __restrict__ gcnw,
    const float* __restrict__ f4t_w, const float* __restrict__ f4t_b,
    const float* __restrict__ f4_w, const float* __restrict__ f4_b,
    float* __restrict__ out)
{
    extern __shared__ __align__(16) char smd[];
    const uint32_t sb = smem_u32(smd);
    float* gs = (float*)(smd + ATT_GS);
    float* m4s = (float*)smd;              // [128][68] after main loop

    const int b = blockIdx.y;
    const int y0 = blockIdx.x * 128;
    const int tid = threadIdx.x;
    const int wy = tid >> 5;
    const int lane = tid & 31;
    const int r = lane >> 2;
    const int c2 = (lane & 3) * 2;

    // ldmatrix per-thread address term for B frags (8x8 pair layout)
    const int row_b = (lane & 7) | ((lane & 16) >> 1);
    const int colh  = (lane >> 3) & 1;
    const uint32_t boffT = (uint32_t)(row_b * 144 + colh * 16);

    for (int i = tid; i < 2500; i += 256) gs[i] = gcnw[i];

    auto stage = [&](int t, int s) {
        const int l0c = t * 64;
        const uint32_t base = sb + s * ATT_STG;
        #pragma unroll
        for (int it = 0; it < 2; it++) {
            int idx = tid + it * 256;
            int row = idx >> 3, c = idx & 7;
            uint32_t d0 = base + row * 144 + c * 16;
            size_t srck = ((size_t)b * LPAD + l0c + row) * 64 + c * 8;
            cp16(d0,         g_hpk_hi + srck);
            cp16(d0 + 9216,  g_hpk_lo + srck);
            size_t srct = ((size_t)b * 64 + row) * LPAD + l0c + c * 8;
            cp16(d0 + 18432, g_hpt_hi + srct);
            cp16(d0 + 27648, g_hpt_lo + srct);
        }
    };

    // --- preload U4 split A-fragments
    const int yr0 = y0 + wy * 16 + r;
    const int yr1 = yr0 + 8;
    unsigned uH[4][4], uL[4][4];
    #pragma unroll
    for (int ks = 0; ks < 4; ks++) {
        #pragma unroll
        for (int q = 0; q < 4; q++) {
            int row = (q & 1) ? yr1 : yr0;
            int col = ks * 16 + c2 + ((q & 2) ? 8 : 0);
            float v0 = 0.f, v1 = 0.f;
            if (row < YY) {
                if (col < FF)     v0 = U4[(size_t)row * FF + col];
                if (col + 1 < FF) v1 = U4[(size_t)row * FF + col + 1];
            }
            split2(v0, v1, uH[ks][q], uL[ks][q]);
        }
    }

    float D2[8][4];
    #pragma unroll
    for (int n = 0; n < 8; n++)
        #pragma unroll
        for (int i = 0; i < 4; i++) D2[n][i] = 0.f;
    float rs0 = 0.f, rs1 = 0.f;

    stage(0, 0); CP_COMMIT();
    stage(1, 1); CP_COMMIT();
    CP_WAIT1();
    __syncthreads();

    for (int t = 0; t < 40; t++) {
        const int s = t & 1;
        const int l0 = t * 64;
        const uint32_t kb = sb + s * ATT_STG + boffT;   // hpk planes
        const uint32_t tb = kb + 18432;                 // hpt planes

        // --- scores: S = U . hp^T (split, 3 products), ks-outer
        float sw[8][4];
        #pragma unroll
        for (int nt = 0; nt < 8; nt++)
            #pragma unroll
            for (int i = 0; i < 4; i++) sw[nt][i] = 0.f;

        #pragma unroll
        for (int ks = 0; ks < 4; ks++) {
            const uint32_t ks32 = ks * 32;
            unsigned bh[4][4], bl4[4][4];
            #pragma unroll
            for (int ntp = 0; ntp < 4; ntp++) {
                ldm_x4(bh[ntp],  kb + ntp * 2304 + ks32);
                ldm_x4(bl4[ntp], kb + 9216 + ntp * 2304 + ks32);
            }
            #pragma unroll
            for (int nt = 0; nt < 8; nt++) {
                unsigned hbx[2] = { bh[nt >> 1][(nt & 1) * 2], bh[nt >> 1][(nt & 1) * 2 + 1] };
                unsigned lbx[2] = { bl4[nt >> 1][(nt & 1) * 2], bl4[nt >> 1][(nt & 1) * 2 + 1] };
                mma16816(sw[nt], uH[ks], hbx);
                mma16816(sw[nt], uH[ks], lbx);
                mma16816(sw[nt], uL[ks], hbx);
            }
        }

        // --- exp + tail mask + row sums
        const bool full = (l0 + 64 <= LL);
        #pragma unroll
        for (int nt = 0; nt < 8; nt++) {
            float e0 = __expf(sw[nt][0]);
            float e1 = __expf(sw[nt][1]);
            float e2 = __expf(sw[nt][2]);
            float e3 = __expf(sw[nt][3]);
            if (!full) {
                int lc = l0 + nt * 8 + c2;
                if (lc >= LL)     { e0 = 0.f; e2 = 0.f; }
                if (lc + 1 >= LL) { e1 = 0.f; e3 = 0.f; }
            }
            rs0 += e0 + e1;
            rs1 += e2 + e3;
            sw[nt][0] = e0; sw[nt][1] = e1; sw[nt][2] = e2; sw[nt][3] = e3;
        }

        // --- re-fragment exp(S) split hi/lo as A-frags
        unsigned aWH[4][4], aWL[4][4];
        #pragma unroll
        for (int kt = 0; kt < 4; kt++) {
            split2(sw[2 * kt][0],     sw[2 * kt][1],     aWH[kt][0], aWL[kt][0]);
            split2(sw[2 * kt][2],     sw[2 * kt][3],     aWH[kt][1], aWL[kt][1]);
            split2(sw[2 * kt + 1][0], sw[2 * kt + 1][1], aWH[kt][2], aWL[kt][2]);
            split2(sw[2 * kt + 1][2], sw[2 * kt + 1][3], aWH[kt][3], aWL[kt][3]);
        }

        // --- m4t accumulate: D2 += w . hp  (3 products), ks-outer
        #pragma unroll
        for (int ks = 0; ks < 4; ks++) {
            const uint32_t ks32 = ks * 32;
            unsigned bh[4][4], bl4[4][4];
            #pragma unroll
            for (int ntp = 0; ntp < 4; ntp++) {
                ldm_x4(bh[ntp],  tb + ntp * 2304 + ks32);
                ldm_x4(bl4[ntp], tb + 9216 + ntp * 2304 + ks32);
            }
            #pragma unroll
            for (int nt = 0; nt < 8; nt++) {
                unsigned hbx[2] = { bh[nt >> 1][(nt & 1) * 2], bh[nt >> 1][(nt & 1) * 2 + 1] };
                unsigned lbx[2] = { bl4[nt >> 1][(nt & 1) * 2], bl4[nt >> 1][(nt & 1) * 2 + 1] };
                mma16816(D2[nt], aWH[ks], hbx);
                mma16816(D2[nt], aWH[ks], lbx);
                mma16816(D2[nt], aWL[ks], hbx);
            }
        }

        __syncthreads();
        if (t + 2 < 40) stage(t + 2, s);
        CP_COMMIT();
        CP_WAIT1();
        __syncthreads();
    }

    // --- normalize
    rs0 += __shfl_xor_sync(0xFFFFFFFF, rs0, 1);
    rs0 += __shfl_xor_sync(0xFFFFFFFF, rs0, 2);
    rs1 += __shfl_xor_sync(0xFFFFFFFF, rs1, 1);
    rs1 += __shfl_xor_sync(0xFFFFFFFF, rs1, 2);
    float inv0 = (yr0 < YY) ? 1.f / rs0 : 0.f;
    float inv1 = (yr1 < YY) ? 1.f / rs1 : 0.f;

    #pragma unroll
    for (int nt = 0; nt < 8; nt++) {
        int col = nt * 8 + c2;
        m4s[(wy * 16 + r) * 68 + col]         = D2[nt][0] * inv0;
        m4s[(wy * 16 + r) * 68 + col + 1]     = D2[nt][1] * inv0;
        m4s[(wy * 16 + 8 + r) * 68 + col]     = D2[nt][2] * inv1;
        m4s[(wy * 16 + 8 + r) * 68 + col + 1] = D2[nt][3] * inv1;
    }
    __syncthreads();

    // --- epilogue: 2 threads per y
    {
        const int yl = tid >> 1;
        const int half = tid & 1;
        const int y = y0 + yl;
        float m[50];
        #pragma unroll
        for (int f = 0; f < 50; f++) m[f] = m4s[yl * 68 + f];

        const int g0 = half * 25;
        for (int g = g0; g < g0 + 25; g++) {
            float s = 0.f;
            #pragma unroll
            for (int f = 0; f < 50; f++) s += m[f] * gs[f * 50 + g];
            __nv_bfloat16 h = __float2bfloat16(s);
            float rem = s - __bfloat162float(h);
            size_t o = (size_t)(b * FF + g) * YPAD + y;
            g_sup_hi[o] = h;
            g_sup_lo[o] = __float2bfloat16(rem);
        }

        if (y < YY) {
            if (half == 0) {
                const float* wt = f4t_w + (size_t)y * 50;
                float s1 = 0.f;
                #pragma unroll
                for (int f = 0; f < 50; f++) s1 += m[f] * wt[f];
                out[(size_t)b * YY + y] = s1 + f4t_b[y];
            } else {
                const float* w4 = f4_w + (size_t)y * 100;
                float s2 = 0.f;
                #pragma unroll
                for (int f = 0; f < 50; f++) s2 += m[f] * w4[f];
                out[(size_t)BB * YY + (size_t)b * YY + y] = s2 + f4_b[y];
            }
        }
    }
}

// ---------------------------------------------------------------------------
// Kernel 3: adj GEMM, split-bf16 HMMA, ldmatrix frags, single-sync pipeline:
// A 2-stage (reg prefetch + STS), B 3-stage (cp.async).
// ---------------------------------------------------------------------------
#define ADJ_ASTG 36864                 // per A stage (hi 18432 + lo 18432)
#define ADJ_BBASE 73728
#define ADJ_BSTG 23040                 // per B stage (hi 11520 + lo 11520)
#define ADJ_GB (73728 + 3 * 23040)     // 142848
#define ADJ_SMEM (ADJ_GB + 256)

__global__ __launch_bounds__(256) void k_adj_mma(
    const float* __restrict__ adj, const float* __restrict__ gcnb,
    const float* __restrict__ f4w, float* __restrict__ out)
{
    extern __shared__ __align__(16) char smd[];
    const uint32_t sb = smem_u32(smd);
    float* gb = (float*)(smd + ADJ_GB);

    const int tid = threadIdx.x;
    const int wid = tid >> 5;
    const int lane = tid & 31;
    const int warp_m = wid & 3;
    const int warp_n = wid >> 2;
    const int r = lane >> 2;
    const int cc = (lane & 3) * 2;

    const int n0 = blockIdx.x * 80;
    const int m0 = blockIdx.y * 128;

    if (tid < 50) gb[tid] = gcnb[tid];

    // ldmatrix per-thread address terms
    const uint32_t aoff = (uint32_t)((warp_m * 32 + (lane & 15)) * 144 + (lane >> 4) * 16);
    const int row_b = (lane & 7) | ((lane & 16) >> 1);
    const int colh  = (lane >> 3) & 1;
    const uint32_t bpair = (uint32_t)((warp_n * 40 + row_b) * 144 + colh * 16);
    const uint32_t blast = (uint32_t)((warp_n * 40 + 32 + (lane & 7)) * 144 + ((lane >> 3) & 1) * 16);

    float2 av[16];

    auto ldgA = [&](int t) {
        const int z0 = t * 64;
        #pragma unroll
        for (int k = 0; k < 16; k++) {
            int i = tid + k * 256;
            int row = i >> 5, p = i & 31;
            int gm = m0 + row, z = z0 + 2 * p;
            float2 v = make_float2(0.f, 0.f);
            if (gm < YY) {
                if (z + 1 < YY) v = *(const float2*)(adj + (size_t)gm * YY + z);
                else if (z < YY) v.x = adj[(size_t)gm * YY + z];
            }
            av[k] = v;
        }
    };
    auto stsA = [&](int s) {
        const int base = s * ADJ_ASTG;
        #pragma unroll
        for (int k = 0; k < 16; k++) {
            int i = tid + k * 256;
            int row = i >> 5, p = i & 31;
            unsigned hi, lo;
            split2(av[k].x, av[k].y, hi, lo);
            int d = base + row * 144 + p * 4;
            *(unsigned*)(smd + d) = hi;
            *(unsigned*)(smd + d + 18432) = lo;
        }
    };
    auto stageB = [&](int t, int s) {
        const int z0 = t * 64;
        const uint32_t base = sb + ADJ_BBASE + s * ADJ_BSTG;
        for (int i = tid; i < 640; i += 256) {
            int n = i >> 3, c = i & 7;
            size_t o = (size_t)(n0 + n) * YPAD + z0 + c * 8;
            uint32_t d = base + n * 144 + c * 16;
            cp16(d,         g_sup_hi + o);
            cp16(d + 11520, g_sup_lo + o);
        }
    };

    float d[2][5][4];
    #pragma unroll
    for (int mt = 0; mt < 2; mt++)
        #pragma unroll
        for (int nt = 0; nt < 5; nt++)
            #pragma unroll
            for (int i = 0; i < 4; i++) d[mt][nt][i] = 0.f;

    // preloop
    ldgA(0);
    stageB(0, 0); CP_COMMIT();
    stageB(1, 1); CP_COMMIT();
    stsA(0);
    ldgA(1);

    int bs = 0;                            // t % 3
    for (int t = 0; t < NCHUNK; t++) {
        const int s = t & 1;
        CP_WAIT1();                        // B(t) done
        __syncthreads();                   // A(t) stores + prev compute done

        const uint32_t aA = sb + s * ADJ_ASTG + aoff;
        const uint32_t bBp = sb + ADJ_BBASE + bs * ADJ_BSTG + bpair;
        const uint32_t bBl = sb + ADJ_BBASE + bs * ADJ_BSTG + blast;

        #pragma unroll
        for (int ks = 0; ks < 4; ks++) {
            const uint32_t ks32 = ks * 32;
            unsigned aH[2][4], aL[2][4];
            ldm_x4(aH[0], aA + ks32);
            ldm_x4(aH[1], aA + 2304 + ks32);
            ldm_x4(aL[0], aA + 18432 + ks32);
            ldm_x4(aL[1], aA + 18432 + 2304 + ks32);

            unsigned bH[5][2], bL[5][2];
            {
                unsigned p0[4], p1[4], q[2];
                ldm_x4(p0, bBp + ks32);
                ldm_x4(p1, bBp + 2304 + ks32);
                ldm_x2(q,  bBl + ks32);
                bH[0][0]=p0[0]; bH[0][1]=p0[1]; bH[1][0]=p0[2]; bH[1][1]=p0[3];
                bH[2][0]=p1[0]; bH[2][1]=p1[1]; bH[3][0]=p1[2]; bH[3][1]=p1[3];
                bH[4][0]=q[0];  bH[4][1]=q[1];
                ldm_x4(p0, bBp + 11520 + ks32);
                ldm_x4(p1, bBp + 11520 + 2304 + ks32);
                ldm_x2(q,  bBl + 11520 + ks32);
                bL[0][0]=p0[0]; bL[0][1]=p0[1]; bL[1][0]=p0[2]; bL[1][1]=p0[3];
                bL[2][0]=p1[0]; bL[2][1]=p1[1]; bL[3][0]=p1[2]; bL[3][1]=p1[3];
                bL[4][0]=q[0];  bL[4][1]=q[1];
            }
            #pragma unroll
            for (int mt = 0; mt < 2; mt++)
                #pragma unroll
                for (int nt = 0; nt < 5; nt++) {
                    mma16816(d[mt][nt], aH[mt], bH[nt]);
                    mma16816(d[mt][nt], aH[mt], bL[nt]);
                    mma16816(d[mt][nt], aL[mt], bH[nt]);
                }
        }

        if (t + 1 < NCHUNK) stsA((t + 1) & 1);
        if (t + 2 < NCHUNK) {
            ldgA(t + 2);
            int bs2 = bs + 2; if (bs2 >= 3) bs2 -= 3;
            stageB(t + 2, bs2);
        }
        CP_COMMIT();
        if (++bs == 3) bs = 0;
    }

    const size_t obase = (size_t)BB * YY;
    #pragma unroll
    for (int mt = 0; mt < 2; mt++) {
        int row0 = m0 + warp_m * 32 + mt * 16 + r;
        #pragma unroll
        for (int nt = 0; nt < 5; nt++) {
            int col0 = n0 + warp_n * 40 + nt * 8 + cc;
            int b = col0 / 50;
            int g = col0 - b * 50;
            float gb0 = gb[g], gb1 = gb[g + 1];
            #pragma unroll
            for (int rr = 0; rr < 2; rr++) {
                int y = row0 + rr * 8;
                if (y < YY) {
                    float v0 = d[mt][nt][rr * 2 + 0] + gb0;
                    float v1 = d[mt][nt][rr * 2 + 1] + gb1;
                    v0 = v0 > 0.f ? v0 : 0.2f * v0;
                    v1 = v1 > 0.f ? v1 : 0.2f * v1;
                    const float* fw = f4w + (size_t)y * 100 + 50;
                    float s = v0 * fw[g] + v1 * fw[g + 1];
                    atomicAdd(&out[obase + (size_t)b * YY + y], s);
                }
            }
        }
    }
}

// ---------------------------------------------------------------------------
extern "C" void kernel_launch(void* const* d_in, const int* in_sizes, int n_in,
                              void* d_out, int out_size)
{
    const int*   x     = (const int*)  d_in[0];
    const float* embw  = (const float*)d_in[2];
    const float* convw = (const float*)d_in[3];
    const float* convb = (const float*)d_in[4];
    const float* U4    = (const float*)d_in[5];
    const float* gcnw  = (const float*)d_in[6];
    const float* gcnb  = (const float*)d_in[7];
    const float* adj   = (const float*)d_in[8];
    const float* f4tw  = (const float*)d_in[9];
    const float* f4tb  = (const float*)d_in[10];
    const float* f4w   = (const float*)d_in[11];
    const float* f4b   = (const float*)d_in[12];
    float* out = (float*)d_out;

    cudaFuncSetAttribute(k_attn_mma, cudaFuncAttributeMaxDynamicSharedMemorySize, ATT_SMEM);
    cudaFuncSetAttribute(k_adj_mma,  cudaFuncAttributeMaxDynamicSharedMemorySize, ADJ_SMEM);

    k_embconv <<<dim3(40, BB), 256>>>(x, embw, convw, convb);
    k_attn_mma<<<dim3(70, BB), 256, ATT_SMEM>>>(U4, gcnw, f4tw, f4tb, f4w, f4b, out);
    k_adj_mma <<<dim3(5, 70), 256, ADJ_SMEM>>>(adj, gcnb, f4w, out);
}

// round 14
// speedup vs baseline: 5.1334x; 1.6661x over previous
#include <cuda_runtime.h>
#include <cuda_fp16.h>
#include <math.h>
#include <cstdint>

#define BB 8
#define LL 2500
#define LPAD 2560       // 40 chunks of 64
#define EE 100
#define FF 50
#define KK 9
#define YY 8922
#define NC (BB*FF)      // 400
#define YPAD 8960       // 70*128 = 140*64
#define NCHUNK 140      // K chunks of 64 for adj GEMM

// Scratch (no allocations allowed)
__device__ __half g_hpk[BB*LPAD*64];     // [b][l][f]   fp16(hp)
__device__ __half g_hpt_hi[BB*64*LPAD];  // [b][f][l]   fp16(hp)
__device__ __half g_hpt_lo[BB*64*LPAD];  // [b][f][l]   fp16(hp - hi)
__device__ __half g_sup[NC*YPAD];        // [n400][z]   fp16(support)

// ---------------------------------------------------------------------------
// helpers
// ---------------------------------------------------------------------------
__device__ __forceinline__ void mma16816h(float d[4], const unsigned a[4], const unsigned b[2]) {
    asm volatile(
        "mma.sync.aligned.m16n8k16.row.col.f32.f16.f16.f32 "
        "{%0,%1,%2,%3}, {%4,%5,%6,%7}, {%8,%9}, {%0,%1,%2,%3};"
        : "+f"(d[0]), "+f"(d[1]), "+f"(d[2]), "+f"(d[3])
        : "r"(a[0]), "r"(a[1]), "r"(a[2]), "r"(a[3]), "r"(b[0]), "r"(b[1]));
}
__device__ __forceinline__ void split2h(float x, float y, unsigned& hi, unsigned& lo) {
    __half2 hh = __floats2half2_rn(x, y);
    float2 bk = __half22float2(hh);
    __half2 llv = __floats2half2_rn(x - bk.x, y - bk.y);
    hi = *(unsigned*)&hh;
    lo = *(unsigned*)&llv;
}
__device__ __forceinline__ uint32_t smem_u32(const void* p) {
    uint32_t a;
    asm("{ .reg .u64 t; cvta.to.shared.u64 t, %1; cvt.u32.u64 %0, t; }" : "=r"(a) : "l"(p));
    return a;
}
__device__ __forceinline__ void cp16(uint32_t dst, const void* src) {
    asm volatile("cp.async.cg.shared.global [%0], [%1], 16;" :: "r"(dst), "l"(src) : "memory");
}
#define CP_COMMIT() asm volatile("cp.async.commit_group;" ::: "memory")
#define CP_WAIT1()  asm volatile("cp.async.wait_group 1;" ::: "memory")

__device__ __forceinline__ void ldm_x4(unsigned r[4], uint32_t addr) {
    asm volatile("ldmatrix.sync.aligned.m8n8.x4.shared.b16 {%0,%1,%2,%3}, [%4];"
        : "=r"(r[0]), "=r"(r[1]), "=r"(r[2]), "=r"(r[3]) : "r"(addr));
}
__device__ __forceinline__ void ldm_x2(unsigned r[2], uint32_t addr) {
    asm volatile("ldmatrix.sync.aligned.m8n8.x2.shared.b16 {%0,%1}, [%2];"
        : "=r"(r[0]), "=r"(r[1]) : "r"(addr));
}

// ---------------------------------------------------------------------------
// Kernel 1: embedding + conv1d + tanh -> fp16 planes (hpk single, hpt hi/lo).
// ---------------------------------------------------------------------------
__global__ __launch_bounds__(256) void k_embconv(
    const int* __restrict__ x, const float* __restrict__ embw,
    const float* __restrict__ convw, const float* __restrict__ convb)
{
    __shared__ float es[72][104];
    __shared__ float ws2[64][108];

    const int b  = blockIdx.y;
    const int l0 = blockIdx.x * 64;
    const int tid = threadIdx.x;

    for (int idx = tid; idx < 72 * 100; idx += 256) {
        int r = idx / 100, e = idx - r * 100;
        int l = l0 - 4 + r;
        float v = 0.f;
        if (l >= 0 && l < LL) {
            int tok = x[b * LL + l];
            v = embw[(size_t)tok * EE + e];
        }
        es[r][e] = v;
    }

    const int fx = tid & 15;
    const int ly = tid >> 4;
    float acc[4][4] = {};

    for (int k = 0; k < KK; k++) {
        __syncthreads();
        for (int idx = tid; idx < 6400; idx += 256) {
            int f = idx & 63, e = idx >> 6;
            ws2[f][e] = (f < FF) ? convw[f * (EE * KK) + e * KK + k] : 0.f;
        }
        __syncthreads();
        #pragma unroll 5
        for (int e = 0; e < EE; e += 4) {
            float4 av4[4], wv4[4];
            #pragma unroll
            for (int i = 0; i < 4; i++) av4[i] = *(const float4*)&es[ly + 16 * i + k][e];
            #pragma unroll
            for (int j = 0; j < 4; j++) wv4[j] = *(const float4*)&ws2[fx + 16 * j][e];
            #pragma unroll
            for (int i = 0; i < 4; i++)
                #pragma unroll
                for (int j = 0; j < 4; j++) {
                    acc[i][j] += av4[i].x * wv4[j].x;
                    acc[i][j] += av4[i].y * wv4[j].y;
                    acc[i][j] += av4[i].z * wv4[j].z;
                    acc[i][j] += av4[i].w * wv4[j].w;
                }
        }
    }

    #pragma unroll
    for (int i = 0; i < 4; i++) {
        int l = l0 + ly + 16 * i;
        #pragma unroll
        for (int j = 0; j < 4; j++) {
            int f = fx + 16 * j;
            float val = 0.f;
            if (l < LL && f < FF) val = tanhf(acc[i][j] + convb[f]);
            __half h = __float2half_rn(val);
            __half lo = __float2half_rn(val - __half2float(h));
            g_hpk[((size_t)b * LPAD + l) * 64 + f] = h;
            size_t ot = ((size_t)b * 64 + f) * LPAD + l;
            g_hpt_hi[ot] = h;
            g_hpt_lo[ot] = lo;
        }
    }
}

// ---------------------------------------------------------------------------
// Kernel 2 (HMMA fp16): attention. grid (70, B), block 256.
// scores: split-u (2 products); m4t: single fp16 w' x split hpT (2 products).
// w' = exp(S)*2^-4; row sums accumulate the ROUNDED weights (consistent).
// ---------------------------------------------------------------------------
#define ATT_STG 27648                  // 3 planes x 9216
#define ATT_GS  55296
#define ATT_SMEM (55296 + 10016)

__global__ __launch_bounds__(256) void k_attn_mma(
    const float* __restrict__ U4, const float* __restrict__ gcnw,
    const float* __restrict__ f4t_w, const float* __restrict__ f4t_b,
    const float* __restrict__ f4_w, const float* __restrict__ f4_b,
    float* __restrict__ out)
{
    extern __shared__ __align__(16) char smd[];
    const uint32_t sb = smem_u32(smd);
    float* gs = (float*)(smd + ATT_GS);
    float* m4s = (float*)smd;              // [128][68] after main loop

    const int b = blockIdx.y;
    const int y0 = blockIdx.x * 128;
    const int tid = threadIdx.x;
    const int wy = tid >> 5;
    const int lane = tid & 31;
    const int r = lane >> 2;
    const int c2 = (lane & 3) * 2;

    const int row_b = (lane & 7) | ((lane & 16) >> 1);
    const int colh  = (lane >> 3) & 1;
    const uint32_t boffT = (uint32_t)(row_b * 144 + colh * 16);

    for (int i = tid; i < 2500; i += 256) gs[i] = gcnw[i];

    auto stage = [&](int t, int s) {
        const int l0c = t * 64;
        const uint32_t base = sb + s * ATT_STG;
        #pragma unroll
        for (int it = 0; it < 2; it++) {
            int idx = tid + it * 256;
            int row = idx >> 3, c = idx & 7;
            uint32_t d0 = base + row * 144 + c * 16;
            size_t srck = ((size_t)b * LPAD + l0c + row) * 64 + c * 8;
            cp16(d0, g_hpk + srck);
            size_t srct = ((size_t)b * 64 + row) * LPAD + l0c + c * 8;
            cp16(d0 + 9216,  g_hpt_hi + srct);
            cp16(d0 + 18432, g_hpt_lo + srct);
        }
    };

    // --- preload U4 split-fp16 A-fragments
    const int yr0 = y0 + wy * 16 + r;
    const int yr1 = yr0 + 8;
    unsigned uH[4][4], uL[4][4];
    #pragma unroll
    for (int ks = 0; ks < 4; ks++) {
        #pragma unroll
        for (int q = 0; q < 4; q++) {
            int row = (q & 1) ? yr1 : yr0;
            int col = ks * 16 + c2 + ((q & 2) ? 8 : 0);
            float v0 = 0.f, v1 = 0.f;
            if (row < YY) {
                if (col < FF)     v0 = U4[(size_t)row * FF + col];
                if (col + 1 < FF) v1 = U4[(size_t)row * FF + col + 1];
            }
            split2h(v0, v1, uH[ks][q], uL[ks][q]);
        }
    }

    float D2[8][4];
    #pragma unroll
    for (int n = 0; n < 8; n++)
        #pragma unroll
        for (int i = 0; i < 4; i++) D2[n][i] = 0.f;
    float rs0 = 0.f, rs1 = 0.f;

    stage(0, 0); CP_COMMIT();
    stage(1, 1); CP_COMMIT();
    CP_WAIT1();
    __syncthreads();

    for (int t = 0; t < 40; t++) {
        const int s = t & 1;
        const int l0 = t * 64;
        const uint32_t kb = sb + s * ATT_STG + boffT;   // hpk plane
        const uint32_t tbH = kb + 9216;                 // hptH plane
        const uint32_t tbL = kb + 18432;                // hptL plane

        // --- scores: S = (uH+uL) . hpk (2 products)
        float sw[8][4];
        #pragma unroll
        for (int nt = 0; nt < 8; nt++)
            #pragma unroll
            for (int i = 0; i < 4; i++) sw[nt][i] = 0.f;

        #pragma unroll
        for (int ks = 0; ks < 4; ks++) {
            const uint32_t ks32 = ks * 32;
            unsigned bh[4][4];
            #pragma unroll
            for (int ntp = 0; ntp < 4; ntp++)
                ldm_x4(bh[ntp], kb + ntp * 2304 + ks32);
            #pragma unroll
            for (int nt = 0; nt < 8; nt++) {
                unsigned hbx[2] = { bh[nt >> 1][(nt & 1) * 2], bh[nt >> 1][(nt & 1) * 2 + 1] };
                mma16816h(sw[nt], uH[ks], hbx);
                mma16816h(sw[nt], uL[ks], hbx);
            }
        }

        // --- exp (scaled 2^-4) + tail mask; pack fp16 weights; consistent sums
        const bool full = (l0 + 64 <= LL);
        unsigned pk01[8], pk23[8];
        #pragma unroll
        for (int nt = 0; nt < 8; nt++) {
            float e0 = __expf(sw[nt][0]) * 0.0625f;
            float e1 = __expf(sw[nt][1]) * 0.0625f;
            float e2 = __expf(sw[nt][2]) * 0.0625f;
            float e3 = __expf(sw[nt][3]) * 0.0625f;
            if (!full) {
                int lc = l0 + nt * 8 + c2;
                if (lc >= LL)     { e0 = 0.f; e2 = 0.f; }
                if (lc + 1 >= LL) { e1 = 0.f; e3 = 0.f; }
            }
            __half2 q01 = __floats2half2_rn(e0, e1);
            __half2 q23 = __floats2half2_rn(e2, e3);
            float2 f01 = __half22float2(q01);
            float2 f23 = __half22float2(q23);
            rs0 += f01.x + f01.y;
            rs1 += f23.x + f23.y;
            pk01[nt] = *(unsigned*)&q01;
            pk23[nt] = *(unsigned*)&q23;
        }

        // A-frags for m4t from packed weights
        unsigned aW[4][4];
        #pragma unroll
        for (int kt = 0; kt < 4; kt++) {
            aW[kt][0] = pk01[2 * kt];
            aW[kt][1] = pk23[2 * kt];
            aW[kt][2] = pk01[2 * kt + 1];
            aW[kt][3] = pk23[2 * kt + 1];
        }

        // --- m4t accumulate: D2 += w' . (hptH + hptL)  (2 products)
        #pragma unroll
        for (int ks = 0; ks < 4; ks++) {
            const uint32_t ks32 = ks * 32;
            unsigned bhH[4][4], bhL[4][4];
            #pragma unroll
            for (int ntp = 0; ntp < 4; ntp++) {
                ldm_x4(bhH[ntp], tbH + ntp * 2304 + ks32);
                ldm_x4(bhL[ntp], tbL + ntp * 2304 + ks32);
            }
            #pragma unroll
            for (int nt = 0; nt < 8; nt++) {
                unsigned hx[2] = { bhH[nt >> 1][(nt & 1) * 2], bhH[nt >> 1][(nt & 1) * 2 + 1] };
                unsigned lx[2] = { bhL[nt >> 1][(nt & 1) * 2], bhL[nt >> 1][(nt & 1) * 2 + 1] };
                mma16816h(D2[nt], aW[ks], hx);
                mma16816h(D2[nt], aW[ks], lx);
            }
        }

        __syncthreads();
        if (t + 2 < 40) stage(t + 2, s);
        CP_COMMIT();
        CP_WAIT1();
        __syncthreads();
    }

    // --- normalize (rounded-weight sums -> exact weighted average)
    rs0 += __shfl_xor_sync(0xFFFFFFFF, rs0, 1);
    rs0 += __shfl_xor_sync(0xFFFFFFFF, rs0, 2);
    rs1 += __shfl_xor_sync(0xFFFFFFFF, rs1, 1);
    rs1 += __shfl_xor_sync(0xFFFFFFFF, rs1, 2);
    float inv0 = (yr0 < YY) ? 1.f / rs0 : 0.f;
    float inv1 = (yr1 < YY) ? 1.f / rs1 : 0.f;

    #pragma unroll
    for (int nt = 0; nt < 8; nt++) {
        int col = nt * 8 + c2;
        m4s[(wy * 16 + r) * 68 + col]         = D2[nt][0] * inv0;
        m4s[(wy * 16 + r) * 68 + col + 1]     = D2[nt][1] * inv0;
        m4s[(wy * 16 + 8 + r) * 68 + col]     = D2[nt][2] * inv1;
        m4s[(wy * 16 + 8 + r) * 68 + col + 1] = D2[nt][3] * inv1;
    }
    __syncthreads();

    // --- epilogue: 2 threads per y
    {
        const int yl = tid >> 1;
        const int half = tid & 1;
        const int y = y0 + yl;
        float m[50];
        #pragma unroll
        for (int f = 0; f < 50; f++) m[f] = m4s[yl * 68 + f];

        const int g0 = half * 25;
        for (int g = g0; g < g0 + 25; g++) {
            float s = 0.f;
            #pragma unroll
            for (int f = 0; f < 50; f++) s += m[f] * gs[f * 50 + g];
            g_sup[(size_t)(b * FF + g) * YPAD + y] = __float2half_rn(s);
        }

        if (y < YY) {
            if (half == 0) {
                const float* wt = f4t_w + (size_t)y * 50;
                float s1 = 0.f;
                #pragma unroll
                for (int f = 0; f < 50; f++) s1 += m[f] * wt[f];
                out[(size_t)b * YY + y] = s1 + f4t_b[y];
            } else {
                const float* w4 = f4_w + (size_t)y * 100;
                float s2 = 0.f;
                #pragma unroll
                for (int f = 0; f < 50; f++) s2 += m[f] * w4[f];
                out[(size_t)BB * YY + (size_t)b * YY + y] = s2 + f4_b[y];
            }
        }
    }
}

// ---------------------------------------------------------------------------
// Kernel 3: adj GEMM, single-product fp16 (A = fp16(adj*4096), B = fp16(sup)),
// ldmatrix frags, single-sync pipeline: A 2-stage reg-prefetch, B 3-stage.
// ---------------------------------------------------------------------------
#define ADJ_ASTG 18432                 // per A stage (single fp16 plane)
#define ADJ_BBASE 36864
#define ADJ_BSTG 11520                 // per B stage (single fp16 plane)
#define ADJ_GB (36864 + 3 * 11520)     // 71424
#define ADJ_SMEM (ADJ_GB + 256)

__global__ __launch_bounds__(256) void k_adj_mma(
    const float* __restrict__ adj, const float* __restrict__ gcnb,
    const float* __restrict__ f4w, float* __restrict__ out)
{
    extern __shared__ __align__(16) char smd[];
    const uint32_t sb = smem_u32(smd);
    float* gb = (float*)(smd + ADJ_GB);

    const int tid = threadIdx.x;
    const int wid = tid >> 5;
    const int lane = tid & 31;
    const int warp_m = wid & 3;
    const int warp_n = wid >> 2;
    const int r = lane >> 2;
    const int cc = (lane & 3) * 2;

    const int n0 = blockIdx.x * 80;
    const int m0 = blockIdx.y * 128;

    if (tid < 50) gb[tid] = gcnb[tid];

    const uint32_t aoff = (uint32_t)((warp_m * 32 + (lane & 15)) * 144 + (lane >> 4) * 16);
    const int row_b = (lane & 7) | ((lane & 16) >> 1);
    const int colh  = (lane >> 3) & 1;
    const uint32_t bpair = (uint32_t)((warp_n * 40 + row_b) * 144 + colh * 16);
    const uint32_t blast = (uint32_t)((warp_n * 40 + 32 + (lane & 7)) * 144 + ((lane >> 3) & 1) * 16);

    float2 av[16];

    auto ldgA = [&](int t) {
        const int z0 = t * 64;
        #pragma unroll
        for (int k = 0; k < 16; k++) {
            int i = tid + k * 256;
            int row = i >> 5, p = i & 31;
            int gm = m0 + row, z = z0 + 2 * p;
            float2 v = make_float2(0.f, 0.f);
            if (gm < YY) {
                if (z + 1 < YY) v = *(const float2*)(adj + (size_t)gm * YY + z);
                else if (z < YY) v.x = adj[(size_t)gm * YY + z];
            }
            av[k] = v;
        }
    };
    auto stsA = [&](int s) {
        const int base = s * ADJ_ASTG;
        #pragma unroll
        for (int k = 0; k < 16; k++) {
            int i = tid + k * 256;
            int row = i >> 5, p = i & 31;
            __half2 hv = __floats2half2_rn(av[k].x * 4096.f, av[k].y * 4096.f);
            *(unsigned*)(smd + base + row * 144 + p * 4) = *(unsigned*)&hv;
        }
    };
    auto stageB = [&](int t, int s) {
        const int z0 = t * 64;
        const uint32_t base = sb + ADJ_BBASE + s * ADJ_BSTG;
        for (int i = tid; i < 640; i += 256) {
            int n = i >> 3, c = i & 7;
            size_t o = (size_t)(n0 + n) * YPAD + z0 + c * 8;
            cp16(base + n * 144 + c * 16, g_sup + o);
        }
    };

    float d[2][5][4];
    #pragma unroll
    for (int mt = 0; mt < 2; mt++)
        #pragma unroll
        for (int nt = 0; nt < 5; nt++)
            #pragma unroll
            for (int i = 0; i < 4; i++) d[mt][nt][i] = 0.f;

    // preloop
    ldgA(0);
    stageB(0, 0); CP_COMMIT();
    stageB(1, 1); CP_COMMIT();
    stsA(0);
    ldgA(1);

    int bs = 0;                            // t % 3
    for (int t = 0; t < NCHUNK; t++) {
        const int s = t & 1;
        CP_WAIT1();                        // B(t) done
        __syncthreads();                   // A(t) stores + prev compute done

        const uint32_t aA = sb + s * ADJ_ASTG + aoff;
        const uint32_t bBp = sb + ADJ_BBASE + bs * ADJ_BSTG + bpair;
        const uint32_t bBl = sb + ADJ_BBASE + bs * ADJ_BSTG + blast;

        #pragma unroll
        for (int ks = 0; ks < 4; ks++) {
            const uint32_t ks32 = ks * 32;
            unsigned aH[2][4];
            ldm_x4(aH[0], aA + ks32);
            ldm_x4(aH[1], aA + 2304 + ks32);

            unsigned bH[5][2];
            {
                unsigned p0[4], p1[4], q[2];
                ldm_x4(p0, bBp + ks32);
                ldm_x4(p1, bBp + 2304 + ks32);
                ldm_x2(q,  bBl + ks32);
                bH[0][0]=p0[0]; bH[0][1]=p0[1]; bH[1][0]=p0[2]; bH[1][1]=p0[3];
                bH[2][0]=p1[0]; bH[2][1]=p1[1]; bH[3][0]=p1[2]; bH[3][1]=p1[3];
                bH[4][0]=q[0];  bH[4][1]=q[1];
            }
            #pragma unroll
            for (int mt = 0; mt < 2; mt++)
                #pragma unroll
                for (int nt = 0; nt < 5; nt++)
                    mma16816h(d[mt][nt], aH[mt], bH[nt]);
        }

        if (t + 1 < NCHUNK) stsA((t + 1) & 1);
        if (t + 2 < NCHUNK) {
            ldgA(t + 2);
            int bs2 = bs + 2; if (bs2 >= 3) bs2 -= 3;
            stageB(t + 2, bs2);
        }
        CP_COMMIT();
        if (++bs == 3) bs = 0;
    }

    const float inv_scale = 1.f / 4096.f;
    const size_t obase = (size_t)BB * YY;
    #pragma unroll
    for (int mt = 0; mt < 2; mt++) {
        int row0 = m0 + warp_m * 32 + mt * 16 + r;
        #pragma unroll
        for (int nt = 0; nt < 5; nt++) {
            int col0 = n0 + warp_n * 40 + nt * 8 + cc;
            int b = col0 / 50;
            int g = col0 - b * 50;
            float gb0 = gb[g], gb1 = gb[g + 1];
            #pragma unroll
            for (int rr = 0; rr < 2; rr++) {
                int y = row0 + rr * 8;
                if (y < YY) {
                    float v0 = d[mt][nt][rr * 2 + 0] * inv_scale + gb0;
                    float v1 = d[mt][nt][rr * 2 + 1] * inv_scale + gb1;
                    v0 = v0 > 0.f ? v0 : 0.2f * v0;
                    v1 = v1 > 0.f ? v1 : 0.2f * v1;
                    const float* fw = f4w + (size_t)y * 100 + 50;
                    float s = v0 * fw[g] + v1 * fw[g + 1];
                    atomicAdd(&out[obase + (size_t)b * YY + y], s);
                }
            }
        }
    }
}

// ---------------------------------------------------------------------------
extern "C" void kernel_launch(void* const* d_in, const int* in_sizes, int n_in,
                              void* d_out, int out_size)
{
    const int*   x     = (const int*)  d_in[0];
    const float* embw  = (const float*)d_in[2];
    const float* convw = (const float*)d_in[3];
    const float* convb = (const float*)d_in[4];
    const float* U4    = (const float*)d_in[5];
    const float* gcnw  = (const float*)d_in[6];
    const float* gcnb  = (const float*)d_in[7];
    const float* adj   = (const float*)d_in[8];
    const float* f4tw  = (const float*)d_in[9];
    const float* f4tb  = (const float*)d_in[10];
    const float* f4w   = (const float*)d_in[11];
    const float* f4b   = (const float*)d_in[12];
    float* out = (float*)d_out;

    cudaFuncSetAttribute(k_attn_mma, cudaFuncAttributeMaxDynamicSharedMemorySize, ATT_SMEM);
    cudaFuncSetAttribute(k_adj_mma,  cudaFuncAttributeMaxDynamicSharedMemorySize, ADJ_SMEM);

    k_embconv <<<dim3(40, BB), 256>>>(x, embw, convw, convb);
    k_attn_mma<<<dim3(70, BB), 256, ATT_SMEM>>>(U4, gcnw, f4tw, f4tb, f4w, f4b, out);
    k_adj_mma <<<dim3(5, 70), 256, ADJ_SMEM>>>(adj, gcnb, f4w, out);
}

// round 15
// speedup vs baseline: 6.1937x; 1.2066x over previous
#include <cuda_runtime.h>
#include <cuda_fp16.h>
#include <math.h>
#include <cstdint>

#define BB 8
#define LL 2500
#define LPAD 2560       // 40 chunks of 64
#define EE 100
#define FF 50
#define KK 9
#define YY 8922
#define NC (BB*FF)      // 400
#define YPAD 8960       // 70*128 = 140*64
#define NCHUNK 140      // K chunks of 64 for adj GEMM

// Scratch (no allocations allowed)
__device__ __half g_hpk[BB*LPAD*64];     // [b][l][f]   fp16(hp)
__device__ __half g_hpt[BB*64*LPAD];     // [b][f][l]   fp16(hp)
__device__ __half g_sup[NC*YPAD];        // [n400][z]   fp16(support)

// ---------------------------------------------------------------------------
// helpers
// ---------------------------------------------------------------------------
__device__ __forceinline__ void mma16816h(float d[4], const unsigned a[4], const unsigned b[2]) {
    asm volatile(
        "mma.sync.aligned.m16n8k16.row.col.f32.f16.f16.f32 "
        "{%0,%1,%2,%3}, {%4,%5,%6,%7}, {%8,%9}, {%0,%1,%2,%3};"
        : "+f"(d[0]), "+f"(d[1]), "+f"(d[2]), "+f"(d[3])
        : "r"(a[0]), "r"(a[1]), "r"(a[2]), "r"(a[3]), "r"(b[0]), "r"(b[1]));
}
__device__ __forceinline__ uint32_t smem_u32(const void* p) {
    uint32_t a;
    asm("{ .reg .u64 t; cvta.to.shared.u64 t, %1; cvt.u32.u64 %0, t; }" : "=r"(a) : "l"(p));
    return a;
}
__device__ __forceinline__ void cp16(uint32_t dst, const void* src) {
    asm volatile("cp.async.cg.shared.global [%0], [%1], 16;" :: "r"(dst), "l"(src) : "memory");
}
#define CP_COMMIT() asm volatile("cp.async.commit_group;" ::: "memory")
#define CP_WAIT1()  asm volatile("cp.async.wait_group 1;" ::: "memory")

__device__ __forceinline__ void ldm_x4(unsigned r[4], uint32_t addr) {
    asm volatile("ldmatrix.sync.aligned.m8n8.x4.shared.b16 {%0,%1,%2,%3}, [%4];"
        : "=r"(r[0]), "=r"(r[1]), "=r"(r[2]), "=r"(r[3]) : "r"(addr));
}
__device__ __forceinline__ void ldm_x2(unsigned r[2], uint32_t addr) {
    asm volatile("ldmatrix.sync.aligned.m8n8.x2.shared.b16 {%0,%1}, [%2];"
        : "=r"(r[0]), "=r"(r[1]) : "r"(addr));
}

// ---------------------------------------------------------------------------
// Kernel 1: embedding + conv1d + tanh -> fp16 planes (hpk + hpt).
// ---------------------------------------------------------------------------
__global__ __launch_bounds__(256) void k_embconv(
    const int* __restrict__ x, const float* __restrict__ embw,
    const float* __restrict__ convw, const float* __restrict__ convb)
{
    __shared__ float es[72][104];
    __shared__ float ws2[64][108];

    const int b  = blockIdx.y;
    const int l0 = blockIdx.x * 64;
    const int tid = threadIdx.x;

    for (int idx = tid; idx < 72 * 100; idx += 256) {
        int r = idx / 100, e = idx - r * 100;
        int l = l0 - 4 + r;
        float v = 0.f;
        if (l >= 0 && l < LL) {
            int tok = x[b * LL + l];
            v = embw[(size_t)tok * EE + e];
        }
        es[r][e] = v;
    }

    const int fx = tid & 15;
    const int ly = tid >> 4;
    float acc[4][4] = {};

    for (int k = 0; k < KK; k++) {
        __syncthreads();
        for (int idx = tid; idx < 6400; idx += 256) {
            int f = idx & 63, e = idx >> 6;
            ws2[f][e] = (f < FF) ? convw[f * (EE * KK) + e * KK + k] : 0.f;
        }
        __syncthreads();
        #pragma unroll 5
        for (int e = 0; e < EE; e += 4) {
            float4 av4[4], wv4[4];
            #pragma unroll
            for (int i = 0; i < 4; i++) av4[i] = *(const float4*)&es[ly + 16 * i + k][e];
            #pragma unroll
            for (int j = 0; j < 4; j++) wv4[j] = *(const float4*)&ws2[fx + 16 * j][e];
            #pragma unroll
            for (int i = 0; i < 4; i++)
                #pragma unroll
                for (int j = 0; j < 4; j++) {
                    acc[i][j] += av4[i].x * wv4[j].x;
                    acc[i][j] += av4[i].y * wv4[j].y;
                    acc[i][j] += av4[i].z * wv4[j].z;
                    acc[i][j] += av4[i].w * wv4[j].w;
                }
        }
    }

    #pragma unroll
    for (int i = 0; i < 4; i++) {
        int l = l0 + ly + 16 * i;
        #pragma unroll
        for (int j = 0; j < 4; j++) {
            int f = fx + 16 * j;
            float val = 0.f;
            if (l < LL && f < FF) val = tanhf(acc[i][j] + convb[f]);
            __half h = __float2half_rn(val);
            g_hpk[((size_t)b * LPAD + l) * 64 + f] = h;
            g_hpt[((size_t)b * 64 + f) * LPAD + l] = h;
        }
    }
}

// ---------------------------------------------------------------------------
// Kernel 2 (HMMA fp16): attention. grid (70, B), block 256.
// scores: single fp16 u (1 product); m4t: single fp16 w' x hpt (1 product).
// w' = exp(S)*2^-4; row sums accumulate the ROUNDED weights (consistent).
// ---------------------------------------------------------------------------
#define ATT_STG 18432                  // 2 planes x 9216
#define ATT_GS  36864
#define ATT_SMEM (36864 + 10016)

__global__ __launch_bounds__(256) void k_attn_mma(
    const float* __restrict__ U4, const float* __restrict__ gcnw,
    const float* __restrict__ f4t_w, const float* __restrict__ f4t_b,
    const float* __restrict__ f4_w, const float* __restrict__ f4_b,
    float* __restrict__ out)
{
    extern __shared__ __align__(16) char smd[];
    const uint32_t sb = smem_u32(smd);
    float* gs = (float*)(smd + ATT_GS);
    float* m4s = (float*)smd;              // [128][68] after main loop

    const int b = blockIdx.y;
    const int y0 = blockIdx.x * 128;
    const int tid = threadIdx.x;
    const int wy = tid >> 5;
    const int lane = tid & 31;
    const int r = lane >> 2;
    const int c2 = (lane & 3) * 2;

    const int row_b = (lane & 7) | ((lane & 16) >> 1);
    const int colh  = (lane >> 3) & 1;
    const uint32_t boffT = (uint32_t)(row_b * 144 + colh * 16);

    for (int i = tid; i < 2500; i += 256) gs[i] = gcnw[i];

    auto stage = [&](int t, int s) {
        const int l0c = t * 64;
        const uint32_t base = sb + s * ATT_STG;
        #pragma unroll
        for (int it = 0; it < 2; it++) {
            int idx = tid + it * 256;
            int row = idx >> 3, c = idx & 7;
            uint32_t d0 = base + row * 144 + c * 16;
            size_t srck = ((size_t)b * LPAD + l0c + row) * 64 + c * 8;
            cp16(d0, g_hpk + srck);
            size_t srct = ((size_t)b * 64 + row) * LPAD + l0c + c * 8;
            cp16(d0 + 9216, g_hpt + srct);
        }
    };

    // --- preload U4 single-fp16 A-fragments
    const int yr0 = y0 + wy * 16 + r;
    const int yr1 = yr0 + 8;
    unsigned uH[4][4];
    #pragma unroll
    for (int ks = 0; ks < 4; ks++) {
        #pragma unroll
        for (int q = 0; q < 4; q++) {
            int row = (q & 1) ? yr1 : yr0;
            int col = ks * 16 + c2 + ((q & 2) ? 8 : 0);
            float v0 = 0.f, v1 = 0.f;
            if (row < YY) {
                if (col < FF)     v0 = U4[(size_t)row * FF + col];
                if (col + 1 < FF) v1 = U4[(size_t)row * FF + col + 1];
            }
            __half2 hh = __floats2half2_rn(v0, v1);
            uH[ks][q] = *(unsigned*)&hh;
        }
    }

    float D2[8][4];
    #pragma unroll
    for (int n = 0; n < 8; n++)
        #pragma unroll
        for (int i = 0; i < 4; i++) D2[n][i] = 0.f;
    float rs0 = 0.f, rs1 = 0.f;

    stage(0, 0); CP_COMMIT();
    stage(1, 1); CP_COMMIT();
    CP_WAIT1();
    __syncthreads();

    for (int t = 0; t < 40; t++) {
        const int s = t & 1;
        const int l0 = t * 64;
        const uint32_t kb = sb + s * ATT_STG + boffT;   // hpk plane
        const uint32_t tb = kb + 9216;                  // hpt plane

        // --- scores: S = u . hpk (1 product)
        float sw[8][4];
        #pragma unroll
        for (int nt = 0; nt < 8; nt++)
            #pragma unroll
            for (int i = 0; i < 4; i++) sw[nt][i] = 0.f;

        #pragma unroll
        for (int ks = 0; ks < 4; ks++) {
            const uint32_t ks32 = ks * 32;
            unsigned bh[4][4];
            #pragma unroll
            for (int ntp = 0; ntp < 4; ntp++)
                ldm_x4(bh[ntp], kb + ntp * 2304 + ks32);
            #pragma unroll
            for (int nt = 0; nt < 8; nt++) {
                unsigned hbx[2] = { bh[nt >> 1][(nt & 1) * 2], bh[nt >> 1][(nt & 1) * 2 + 1] };
                mma16816h(sw[nt], uH[ks], hbx);
            }
        }

        // --- exp (scaled 2^-4) + tail mask; pack fp16 weights; consistent sums
        const bool full = (l0 + 64 <= LL);
        unsigned pk01[8], pk23[8];
        #pragma unroll
        for (int nt = 0; nt < 8; nt++) {
            float e0 = __expf(sw[nt][0]) * 0.0625f;
            float e1 = __expf(sw[nt][1]) * 0.0625f;
            float e2 = __expf(sw[nt][2]) * 0.0625f;
            float e3 = __expf(sw[nt][3]) * 0.0625f;
            if (!full) {
                int lc = l0 + nt * 8 + c2;
                if (lc >= LL)     { e0 = 0.f; e2 = 0.f; }
                if (lc + 1 >= LL) { e1 = 0.f; e3 = 0.f; }
            }
            __half2 q01 = __floats2half2_rn(e0, e1);
            __half2 q23 = __floats2half2_rn(e2, e3);
            float2 f01 = __half22float2(q01);
            float2 f23 = __half22float2(q23);
            rs0 += f01.x + f01.y;
            rs1 += f23.x + f23.y;
            pk01[nt] = *(unsigned*)&q01;
            pk23[nt] = *(unsigned*)&q23;
        }

        // A-frags for m4t from packed weights
        unsigned aW[4][4];
        #pragma unroll
        for (int kt = 0; kt < 4; kt++) {
            aW[kt][0] = pk01[2 * kt];
            aW[kt][1] = pk23[2 * kt];
            aW[kt][2] = pk01[2 * kt + 1];
            aW[kt][3] = pk23[2 * kt + 1];
        }

        // --- m4t accumulate: D2 += w' . hpt  (1 product)
        #pragma unroll
        for (int ks = 0; ks < 4; ks++) {
            const uint32_t ks32 = ks * 32;
            unsigned bhH[4][4];
            #pragma unroll
            for (int ntp = 0; ntp < 4; ntp++)
                ldm_x4(bhH[ntp], tb + ntp * 2304 + ks32);
            #pragma unroll
            for (int nt = 0; nt < 8; nt++) {
                unsigned hx[2] = { bhH[nt >> 1][(nt & 1) * 2], bhH[nt >> 1][(nt & 1) * 2 + 1] };
                mma16816h(D2[nt], aW[ks], hx);
            }
        }

        __syncthreads();
        if (t + 2 < 40) stage(t + 2, s);
        CP_COMMIT();
        CP_WAIT1();
        __syncthreads();
    }

    // --- normalize (rounded-weight sums -> exact weighted average)
    rs0 += __shfl_xor_sync(0xFFFFFFFF, rs0, 1);
    rs0 += __shfl_xor_sync(0xFFFFFFFF, rs0, 2);
    rs1 += __shfl_xor_sync(0xFFFFFFFF, rs1, 1);
    rs1 += __shfl_xor_sync(0xFFFFFFFF, rs1, 2);
    float inv0 = (yr0 < YY) ? 1.f / rs0 : 0.f;
    float inv1 = (yr1 < YY) ? 1.f / rs1 : 0.f;

    #pragma unroll
    for (int nt = 0; nt < 8; nt++) {
        int col = nt * 8 + c2;
        m4s[(wy * 16 + r) * 68 + col]         = D2[nt][0] * inv0;
        m4s[(wy * 16 + r) * 68 + col + 1]     = D2[nt][1] * inv0;
        m4s[(wy * 16 + 8 + r) * 68 + col]     = D2[nt][2] * inv1;
        m4s[(wy * 16 + 8 + r) * 68 + col + 1] = D2[nt][3] * inv1;
    }
    __syncthreads();

    // --- epilogue: 2 threads per y
    {
        const int yl = tid >> 1;
        const int half = tid & 1;
        const int y = y0 + yl;
        float m[50];
        #pragma unroll
        for (int f = 0; f < 50; f++) m[f] = m4s[yl * 68 + f];

        const int g0 = half * 25;
        for (int g = g0; g < g0 + 25; g++) {
            float s = 0.f;
            #pragma unroll
            for (int f = 0; f < 50; f++) s += m[f] * gs[f * 50 + g];
            g_sup[(size_t)(b * FF + g) * YPAD + y] = __float2half_rn(s);
        }

        if (y < YY) {
            if (half == 0) {
                const float* wt = f4t_w + (size_t)y * 50;
                float s1 = 0.f;
                #pragma unroll
                for (int f = 0; f < 50; f++) s1 += m[f] * wt[f];
                out[(size_t)b * YY + y] = s1 + f4t_b[y];
            } else {
                const float* w4 = f4_w + (size_t)y * 100;
                float s2 = 0.f;
                #pragma unroll
                for (int f = 0; f < 50; f++) s2 += m[f] * w4[f];
                out[(size_t)BB * YY + (size_t)b * YY + y] = s2 + f4_b[y];
            }
        }
    }
}

// ---------------------------------------------------------------------------
// Kernel 3: adj GEMM, single-product fp16 (A = fp16(adj*4096), B = fp16(sup)),
// ldmatrix frags, single-sync pipeline: A 2-stage reg-prefetch, B 3-stage.
// ---------------------------------------------------------------------------
#define ADJ_ASTG 18432                 // per A stage (single fp16 plane)
#define ADJ_BBASE 36864
#define ADJ_BSTG 11520                 // per B stage (single fp16 plane)
#define ADJ_GB (36864 + 3 * 11520)     // 71424
#define ADJ_SMEM (ADJ_GB + 256)

__global__ __launch_bounds__(256) void k_adj_mma(
    const float* __restrict__ adj, const float* __restrict__ gcnb,
    const float* __restrict__ f4w, float* __restrict__ out)
{
    extern __shared__ __align__(16) char smd[];
    const uint32_t sb = smem_u32(smd);
    float* gb = (float*)(smd + ADJ_GB);

    const int tid = threadIdx.x;
    const int wid = tid >> 5;
    const int lane = tid & 31;
    const int warp_m = wid & 3;
    const int warp_n = wid >> 2;
    const int r = lane >> 2;
    const int cc = (lane & 3) * 2;

    const int n0 = blockIdx.x * 80;
    const int m0 = blockIdx.y * 128;

    if (tid < 50) gb[tid] = gcnb[tid];

    const uint32_t aoff = (uint32_t)((warp_m * 32 + (lane & 15)) * 144 + (lane >> 4) * 16);
    const int row_b = (lane & 7) | ((lane & 16) >> 1);
    const int colh  = (lane >> 3) & 1;
    const uint32_t bpair = (uint32_t)((warp_n * 40 + row_b) * 144 + colh * 16);
    const uint32_t blast = (uint32_t)((warp_n * 40 + 32 + (lane & 7)) * 144 + ((lane >> 3) & 1) * 16);

    float2 av[16];

    auto ldgA = [&](int t) {
        const int z0 = t * 64;
        #pragma unroll
        for (int k = 0; k < 16; k++) {
            int i = tid + k * 256;
            int row = i >> 5, p = i & 31;
            int gm = m0 + row, z = z0 + 2 * p;
            float2 v = make_float2(0.f, 0.f);
            if (gm < YY) {
                if (z + 1 < YY) v = *(const float2*)(adj + (size_t)gm * YY + z);
                else if (z < YY) v.x = adj[(size_t)gm * YY + z];
            }
            av[k] = v;
        }
    };
    auto stsA = [&](int s) {
        const int base = s * ADJ_ASTG;
        #pragma unroll
        for (int k = 0; k < 16; k++) {
            int i = tid + k * 256;
            int row = i >> 5, p = i & 31;
            __half2 hv = __floats2half2_rn(av[k].x * 4096.f, av[k].y * 4096.f);
            *(unsigned*)(smd + base + row * 144 + p * 4) = *(unsigned*)&hv;
        }
    };
    auto stageB = [&](int t, int s) {
        const int z0 = t * 64;
        const uint32_t base = sb + ADJ_BBASE + s * ADJ_BSTG;
        for (int i = tid; i < 640; i += 256) {
            int n = i >> 3, c = i & 7;
            size_t o = (size_t)(n0 + n) * YPAD + z0 + c * 8;
            cp16(base + n * 144 + c * 16, g_sup + o);
        }
    };

    float d[2][5][4];
    #pragma unroll
    for (int mt = 0; mt < 2; mt++)
        #pragma unroll
        for (int nt = 0; nt < 5; nt++)
            #pragma unroll
            for (int i = 0; i < 4; i++) d[mt][nt][i] = 0.f;

    // preloop
    ldgA(0);
    stageB(0, 0); CP_COMMIT();
    stageB(1, 1); CP_COMMIT();
    stsA(0);
    ldgA(1);

    int bs = 0;                            // t % 3
    for (int t = 0; t < NCHUNK; t++) {
        const int s = t & 1;
        CP_WAIT1();                        // B(t) done
        __syncthreads();                   // A(t) stores + prev compute done

        const uint32_t aA = sb + s * ADJ_ASTG + aoff;
        const uint32_t bBp = sb + ADJ_BBASE + bs * ADJ_BSTG + bpair;
        const uint32_t bBl = sb + ADJ_BBASE + bs * ADJ_BSTG + blast;

        #pragma unroll
        for (int ks = 0; ks < 4; ks++) {
            const uint32_t ks32 = ks * 32;
            unsigned aH[2][4];
            ldm_x4(aH[0], aA + ks32);
            ldm_x4(aH[1], aA + 2304 + ks32);

            unsigned bH[5][2];
            {
                unsigned p0[4], p1[4], q[2];
                ldm_x4(p0, bBp + ks32);
                ldm_x4(p1, bBp + 2304 + ks32);
                ldm_x2(q,  bBl + ks32);
                bH[0][0]=p0[0]; bH[0][1]=p0[1]; bH[1][0]=p0[2]; bH[1][1]=p0[3];
                bH[2][0]=p1[0]; bH[2][1]=p1[1]; bH[3][0]=p1[2]; bH[3][1]=p1[3];
                bH[4][0]=q[0];  bH[4][1]=q[1];
            }
            #pragma unroll
            for (int mt = 0; mt < 2; mt++)
                #pragma unroll
                for (int nt = 0; nt < 5; nt++)
                    mma16816h(d[mt][nt], aH[mt], bH[nt]);
        }

        if (t + 1 < NCHUNK) stsA((t + 1) & 1);
        if (t + 2 < NCHUNK) {
            ldgA(t + 2);
            int bs2 = bs + 2; if (bs2 >= 3) bs2 -= 3;
            stageB(t + 2, bs2);
        }
        CP_COMMIT();
        if (++bs == 3) bs = 0;
    }

    const float inv_scale = 1.f / 4096.f;
    const size_t obase = (size_t)BB * YY;
    #pragma unroll
    for (int mt = 0; mt < 2; mt++) {
        int row0 = m0 + warp_m * 32 + mt * 16 + r;
        #pragma unroll
        for (int nt = 0; nt < 5; nt++) {
            int col0 = n0 + warp_n * 40 + nt * 8 + cc;
            int b = col0 / 50;
            int g = col0 - b * 50;
            float gb0 = gb[g], gb1 = gb[g + 1];
            #pragma unroll
            for (int rr = 0; rr < 2; rr++) {
                int y = row0 + rr * 8;
                if (y < YY) {
                    float v0 = d[mt][nt][rr * 2 + 0] * inv_scale + gb0;
                    float v1 = d[mt][nt][rr * 2 + 1] * inv_scale + gb1;
                    v0 = v0 > 0.f ? v0 : 0.2f * v0;
                    v1 = v1 > 0.f ? v1 : 0.2f * v1;
                    const float* fw = f4w + (size_t)y * 100 + 50;
                    float s = v0 * fw[g] + v1 * fw[g + 1];
                    atomicAdd(&out[obase + (size_t)b * YY + y], s);
                }
            }
        }
    }
}

// ---------------------------------------------------------------------------
extern "C" void kernel_launch(void* const* d_in, const int* in_sizes, int n_in,
                              void* d_out, int out_size)
{
    const int*   x     = (const int*)  d_in[0];
    const float* embw  = (const float*)d_in[2];
    const float* convw = (const float*)d_in[3];
    const float* convb = (const float*)d_in[4];
    const float* U4    = (const float*)d_in[5];
    const float* gcnw  = (const float*)d_in[6];
    const float* gcnb  = (const float*)d_in[7];
    const float* adj   = (const float*)d_in[8];
    const float* f4tw  = (const float*)d_in[9];
    const float* f4tb  = (const float*)d_in[10];
    const float* f4w   = (const float*)d_in[11];
    const float* f4b   = (const float*)d_in[12];
    float* out = (float*)d_out;

    cudaFuncSetAttribute(k_attn_mma, cudaFuncAttributeMaxDynamicSharedMemorySize, ATT_SMEM);
    cudaFuncSetAttribute(k_adj_mma,  cudaFuncAttributeMaxDynamicSharedMemorySize, ADJ_SMEM);

    k_embconv <<<dim3(40, BB), 256>>>(x, embw, convw, convb);
    k_attn_mma<<<dim3(70, BB), 256, ATT_SMEM>>>(U4, gcnw, f4tw, f4tb, f4w, f4b, out);
    k_adj_mma <<<dim3(5, 70), 256, ADJ_SMEM>>>(adj, gcnb, f4w, out);
}

// round 16
// speedup vs baseline: 6.2863x; 1.0150x over previous
#include <cuda_runtime.h>
#include <cuda_fp16.h>
#include <math.h>
#include <cstdint>

#define BB 8
#define LL 2500
#define LPAD 2560       // 40 chunks of 64
#define EE 100
#define FF 50
#define KK 9
#define YY 8922
#define NC (BB*FF)      // 400
#define YPAD 8960       // 70*128 = 140*64
#define NCHUNK 140      // K chunks of 64 for adj GEMM

typedef unsigned long long ull;

// Scratch (no allocations allowed)
__device__ __half g_hpk[BB*LPAD*64];     // [b][l][f]   fp16(hp)
__device__ __half g_hpt[BB*64*LPAD];     // [b][f][l]   fp16(hp)
__device__ __half g_sup[NC*YPAD];        // [n400][z]   fp16(support)

// ---------------------------------------------------------------------------
// helpers
// ---------------------------------------------------------------------------
__device__ __forceinline__ void mma16816h(float d[4], const unsigned a[4], const unsigned b[2]) {
    asm volatile(
        "mma.sync.aligned.m16n8k16.row.col.f32.f16.f16.f32 "
        "{%0,%1,%2,%3}, {%4,%5,%6,%7}, {%8,%9}, {%0,%1,%2,%3};"
        : "+f"(d[0]), "+f"(d[1]), "+f"(d[2]), "+f"(d[3])
        : "r"(a[0]), "r"(a[1]), "r"(a[2]), "r"(a[3]), "r"(b[0]), "r"(b[1]));
}
__device__ __forceinline__ void mma16808h(float d[4], const unsigned a[2], const unsigned b0) {
    asm volatile(
        "mma.sync.aligned.m16n8k8.row.col.f32.f16.f16.f32 "
        "{%0,%1,%2,%3}, {%4,%5}, {%6}, {%0,%1,%2,%3};"
        : "+f"(d[0]), "+f"(d[1]), "+f"(d[2]), "+f"(d[3])
        : "r"(a[0]), "r"(a[1]), "r"(b0));
}
__device__ __forceinline__ ull ffma2(ull a, ull b, ull c) {
    ull d;
    asm("fma.rn.f32x2 %0, %1, %2, %3;" : "=l"(d) : "l"(a), "l"(b), "l"(c));
    return d;
}
__device__ __forceinline__ void unpack2(ull v, float& lo, float& hi) {
    asm("mov.b64 {%0, %1}, %2;" : "=f"(lo), "=f"(hi) : "l"(v));
}
__device__ __forceinline__ uint32_t smem_u32(const void* p) {
    uint32_t a;
    asm("{ .reg .u64 t; cvta.to.shared.u64 t, %1; cvt.u32.u64 %0, t; }" : "=r"(a) : "l"(p));
    return a;
}
__device__ __forceinline__ void cp16(uint32_t dst, const void* src) {
    asm volatile("cp.async.cg.shared.global [%0], [%1], 16;" :: "r"(dst), "l"(src) : "memory");
}
#define CP_COMMIT() asm volatile("cp.async.commit_group;" ::: "memory")
#define CP_WAIT1()  asm volatile("cp.async.wait_group 1;" ::: "memory")

__device__ __forceinline__ void ldm_x4(unsigned r[4], uint32_t addr) {
    asm volatile("ldmatrix.sync.aligned.m8n8.x4.shared.b16 {%0,%1,%2,%3}, [%4];"
        : "=r"(r[0]), "=r"(r[1]), "=r"(r[2]), "=r"(r[3]) : "r"(addr));
}
__device__ __forceinline__ void ldm_x2(unsigned r[2], uint32_t addr) {
    asm volatile("ldmatrix.sync.aligned.m8n8.x2.shared.b16 {%0,%1}, [%2];"
        : "=r"(r[0]), "=r"(r[1]) : "r"(addr));
}

// ---------------------------------------------------------------------------
// Kernel 1: embedding + conv1d + tanh -> fp16 planes (hpk + hpt).
// FFMA2-packed inner loop; hpt via smem transpose + coalesced uint4 stores.
// ---------------------------------------------------------------------------
__global__ __launch_bounds__(256) void k_embconv(
    const int* __restrict__ x, const float* __restrict__ embw,
    const float* __restrict__ convw, const float* __restrict__ convb)
{
    __shared__ float es[72][104];      // 416B rows, 16B-aligned
    __shared__ float ws2[64][108];     // f-major

    const int b  = blockIdx.y;
    const int l0 = blockIdx.x * 64;
    const int tid = threadIdx.x;

    for (int idx = tid; idx < 72 * 100; idx += 256) {
        int r = idx / 100, e = idx - r * 100;
        int l = l0 - 4 + r;
        float v = 0.f;
        if (l >= 0 && l < LL) {
            int tok = x[b * LL + l];
            v = embw[(size_t)tok * EE + e];
        }
        es[r][e] = v;
    }

    const int fx = tid & 15;
    const int ly = tid >> 4;
    ull acc2[4][4][2];
    #pragma unroll
    for (int i = 0; i < 4; i++)
        #pragma unroll
        for (int j = 0; j < 4; j++) { acc2[i][j][0] = 0ull; acc2[i][j][1] = 0ull; }

    for (int k = 0; k < KK; k++) {
        __syncthreads();
        for (int idx = tid; idx < 6400; idx += 256) {
            int f = idx & 63, e = idx >> 6;
            ws2[f][e] = (f < FF) ? convw[f * (EE * KK) + e * KK + k] : 0.f;
        }
        __syncthreads();
        #pragma unroll 5
        for (int e = 0; e < EE; e += 4) {
            ulonglong2 au[4], wu[4];
            #pragma unroll
            for (int i = 0; i < 4; i++) au[i] = *(const ulonglong2*)&es[ly + 16 * i + k][e];
            #pragma unroll
            for (int j = 0; j < 4; j++) wu[j] = *(const ulonglong2*)&ws2[fx + 16 * j][e];
            #pragma unroll
            for (int i = 0; i < 4; i++)
                #pragma unroll
                for (int j = 0; j < 4; j++) {
                    acc2[i][j][0] = ffma2(au[i].x, wu[j].x, acc2[i][j][0]);
                    acc2[i][j][1] = ffma2(au[i].y, wu[j].y, acc2[i][j][1]);
                }
        }
    }

    __syncthreads();                       // done reading es: alias as fp16 transpose buf
    __half* tp = (__half*)es;              // [64 f][72 l-stride]

    #pragma unroll
    for (int i = 0; i < 4; i++) {
        int lr = ly + 16 * i;              // local l 0..63
        int l = l0 + lr;
        #pragma unroll
        for (int j = 0; j < 4; j++) {
            int f = fx + 16 * j;
            float a0, a1, b0, b1;
            unpack2(acc2[i][j][0], a0, a1);
            unpack2(acc2[i][j][1], b0, b1);
            float s = (a0 + a1) + (b0 + b1);
            float val = 0.f;
            if (l < LL && f < FF) val = tanhf(s + convb[f]);
            __half h = __float2half_rn(val);
            g_hpk[((size_t)b * LPAD + l) * 64 + f] = h;
            tp[f * 72 + lr] = h;
        }
    }
    __syncthreads();

    // coalesced hpt store: each thread one f row quarter (16 l = 32B)
    {
        int f = tid >> 2;
        int c0 = (tid & 3) * 16;
        uint4 v0 = *(const uint4*)&tp[f * 72 + c0];
        uint4 v1 = *(const uint4*)&tp[f * 72 + c0 + 8];
        size_t o = ((size_t)b * 64 + f) * LPAD + l0 + c0;
        *(uint4*)&g_hpt[o] = v0;
        *(uint4*)&g_hpt[o + 8] = v1;
    }
}

// ---------------------------------------------------------------------------
// Kernel 2 (HMMA fp16): attention. grid (70, B), block 256.
// scores: 3x k16 + 1x k8 (f 48..55 covers the real 50); m4t: 7 n-tiles (56>=50).
// w' = exp(S)*2^-4; row sums accumulate the ROUNDED weights (consistent).
// ---------------------------------------------------------------------------
#define ATT_STG 18432                  // 2 planes x 9216
#define ATT_GS  36864
#define ATT_SMEM (36864 + 10016)

__global__ __launch_bounds__(256) void k_attn_mma(
    const float* __restrict__ U4, const float* __restrict__ gcnw,
    const float* __restrict__ f4t_w, const float* __restrict__ f4t_b,
    const float* __restrict__ f4_w, const float* __restrict__ f4_b,
    float* __restrict__ out)
{
    extern __shared__ __align__(16) char smd[];
    const uint32_t sb = smem_u32(smd);
    float* gs = (float*)(smd + ATT_GS);
    float* m4s = (float*)smd;              // [128][68] after main loop

    const int b = blockIdx.y;
    const int y0 = blockIdx.x * 128;
    const int tid = threadIdx.x;
    const int wy = tid >> 5;
    const int lane = tid & 31;
    const int r = lane >> 2;
    const int c2 = (lane & 3) * 2;

    const int row_b = (lane & 7) | ((lane & 16) >> 1);
    const int colh  = (lane >> 3) & 1;
    const uint32_t boffT = (uint32_t)(row_b * 144 + colh * 16);

    for (int i = tid; i < 2500; i += 256) gs[i] = gcnw[i];

    auto stage = [&](int t, int s) {
        const int l0c = t * 64;
        const uint32_t base = sb + s * ATT_STG;
        #pragma unroll
        for (int it = 0; it < 2; it++) {
            int idx = tid + it * 256;
            int row = idx >> 3, c = idx & 7;
            uint32_t d0 = base + row * 144 + c * 16;
            size_t srck = ((size_t)b * LPAD + l0c + row) * 64 + c * 8;
            cp16(d0, g_hpk + srck);
            size_t srct = ((size_t)b * 64 + row) * LPAD + l0c + c * 8;
            cp16(d0 + 9216, g_hpt + srct);
        }
    };

    // --- preload U4 single-fp16 A-fragments
    const int yr0 = y0 + wy * 16 + r;
    const int yr1 = yr0 + 8;
    unsigned uH[4][4];
    #pragma unroll
    for (int ks = 0; ks < 4; ks++) {
        #pragma unroll
        for (int q = 0; q < 4; q++) {
            int row = (q & 1) ? yr1 : yr0;
            int col = ks * 16 + c2 + ((q & 2) ? 8 : 0);
            float v0 = 0.f, v1 = 0.f;
            if (row < YY) {
                if (col < FF)     v0 = U4[(size_t)row * FF + col];
                if (col + 1 < FF) v1 = U4[(size_t)row * FF + col + 1];
            }
            __half2 hh = __floats2half2_rn(v0, v1);
            uH[ks][q] = *(unsigned*)&hh;
        }
    }

    float D2[7][4];
    #pragma unroll
    for (int n = 0; n < 7; n++)
        #pragma unroll
        for (int i = 0; i < 4; i++) D2[n][i] = 0.f;
    float rs0 = 0.f, rs1 = 0.f;

    stage(0, 0); CP_COMMIT();
    stage(1, 1); CP_COMMIT();
    CP_WAIT1();
    __syncthreads();

    for (int t = 0; t < 40; t++) {
        const int s = t & 1;
        const int l0 = t * 64;
        const uint32_t kb = sb + s * ATT_STG + boffT;   // hpk plane
        const uint32_t tb = kb + 9216;                  // hpt plane

        // --- scores: S = u . hpk  (3x k16 + 1x k8 over f48-55)
        float sw[8][4];
        #pragma unroll
        for (int nt = 0; nt < 8; nt++)
            #pragma unroll
            for (int i = 0; i < 4; i++) sw[nt][i] = 0.f;

        #pragma unroll
        for (int ks = 0; ks < 4; ks++) {
            const uint32_t ks32 = ks * 32;
            unsigned bh[4][4];
            #pragma unroll
            for (int ntp = 0; ntp < 4; ntp++)
                ldm_x4(bh[ntp], kb + ntp * 2304 + ks32);
            if (ks < 3) {
                #pragma unroll
                for (int nt = 0; nt < 8; nt++) {
                    unsigned hbx[2] = { bh[nt >> 1][(nt & 1) * 2], bh[nt >> 1][(nt & 1) * 2 + 1] };
                    mma16816h(sw[nt], uH[ks], hbx);
                }
            } else {
                unsigned a8[2] = { uH[3][0], uH[3][1] };   // f 48..55
                #pragma unroll
                for (int nt = 0; nt < 8; nt++)
                    mma16808h(sw[nt], a8, bh[nt >> 1][(nt & 1) * 2]);
            }
        }

        // --- exp (scaled 2^-4) + tail mask; pack fp16 weights; consistent sums
        const bool full = (l0 + 64 <= LL);
        unsigned pk01[8], pk23[8];
        #pragma unroll
        for (int nt = 0; nt < 8; nt++) {
            float e0 = __expf(sw[nt][0]) * 0.0625f;
            float e1 = __expf(sw[nt][1]) * 0.0625f;
            float e2 = __expf(sw[nt][2]) * 0.0625f;
            float e3 = __expf(sw[nt][3]) * 0.0625f;
            if (!full) {
                int lc = l0 + nt * 8 + c2;
                if (lc >= LL)     { e0 = 0.f; e2 = 0.f; }
                if (lc + 1 >= LL) { e1 = 0.f; e3 = 0.f; }
            }
            __half2 q01 = __floats2half2_rn(e0, e1);
            __half2 q23 = __floats2half2_rn(e2, e3);
            float2 f01 = __half22float2(q01);
            float2 f23 = __half22float2(q23);
            rs0 += f01.x + f01.y;
            rs1 += f23.x + f23.y;
            pk01[nt] = *(unsigned*)&q01;
            pk23[nt] = *(unsigned*)&q23;
        }

        // A-frags for m4t from packed weights
        unsigned aW[4][4];
        #pragma unroll
        for (int kt = 0; kt < 4; kt++) {
            aW[kt][0] = pk01[2 * kt];
            aW[kt][1] = pk23[2 * kt];
            aW[kt][2] = pk01[2 * kt + 1];
            aW[kt][3] = pk23[2 * kt + 1];
        }

        // --- m4t accumulate: D2 += w' . hpt  (7 n-tiles: f 0..55 covers 50)
        #pragma unroll
        for (int ks = 0; ks < 4; ks++) {
            const uint32_t ks32 = ks * 32;
            unsigned bhH[4][4];
            #pragma unroll
            for (int ntp = 0; ntp < 4; ntp++)
                ldm_x4(bhH[ntp], tb + ntp * 2304 + ks32);
            #pragma unroll
            for (int nt = 0; nt < 7; nt++) {
                unsigned hx[2] = { bhH[nt >> 1][(nt & 1) * 2], bhH[nt >> 1][(nt & 1) * 2 + 1] };
                mma16816h(D2[nt], aW[ks], hx);
            }
        }

        __syncthreads();
        if (t + 2 < 40) stage(t + 2, s);
        CP_COMMIT();
        CP_WAIT1();
        __syncthreads();
    }

    // --- normalize (rounded-weight sums -> exact weighted average)
    rs0 += __shfl_xor_sync(0xFFFFFFFF, rs0, 1);
    rs0 += __shfl_xor_sync(0xFFFFFFFF, rs0, 2);
    rs1 += __shfl_xor_sync(0xFFFFFFFF, rs1, 1);
    rs1 += __shfl_xor_sync(0xFFFFFFFF, rs1, 2);
    float inv0 = (yr0 < YY) ? 1.f / rs0 : 0.f;
    float inv1 = (yr1 < YY) ? 1.f / rs1 : 0.f;

    #pragma unroll
    for (int nt = 0; nt < 7; nt++) {
        int col = nt * 8 + c2;
        m4s[(wy * 16 + r) * 68 + col]         = D2[nt][0] * inv0;
        m4s[(wy * 16 + r) * 68 + col + 1]     = D2[nt][1] * inv0;
        m4s[(wy * 16 + 8 + r) * 68 + col]     = D2[nt][2] * inv1;
        m4s[(wy * 16 + 8 + r) * 68 + col + 1] = D2[nt][3] * inv1;
    }
    __syncthreads();

    // --- epilogue: 2 threads per y
    {
        const int yl = tid >> 1;
        const int half = tid & 1;
        const int y = y0 + yl;
        float m[50];
        #pragma unroll
        for (int f = 0; f < 50; f++) m[f] = m4s[yl * 68 + f];

        const int g0 = half * 25;
        for (int g = g0; g < g0 + 25; g++) {
            float s = 0.f;
            #pragma unroll
            for (int f = 0; f < 50; f++) s += m[f] * gs[f * 50 + g];
            g_sup[(size_t)(b * FF + g) * YPAD + y] = __float2half_rn(s);
        }

        if (y < YY) {
            if (half == 0) {
                const float* wt = f4t_w + (size_t)y * 50;
                float s1 = 0.f;
                #pragma unroll
                for (int f = 0; f < 50; f++) s1 += m[f] * wt[f];
                out[(size_t)b * YY + y] = s1 + f4t_b[y];
            } else {
                const float* w4 = f4_w + (size_t)y * 100;
                float s2 = 0.f;
                #pragma unroll
                for (int f = 0; f < 50; f++) s2 += m[f] * w4[f];
                out[(size_t)BB * YY + (size_t)b * YY + y] = s2 + f4_b[y];
            }
        }
    }
}

// ---------------------------------------------------------------------------
// Kernel 3: adj GEMM, single-product fp16 (A = fp16(adj*4096), B = fp16(sup)),
// ldmatrix frags, single-sync pipeline: A 2-stage reg-prefetch, B 3-stage.
// ---------------------------------------------------------------------------
#define ADJ_ASTG 18432                 // per A stage (single fp16 plane)
#define ADJ_BBASE 36864
#define ADJ_BSTG 11520                 // per B stage (single fp16 plane)
#define ADJ_GB (36864 + 3 * 11520)     // 71424
#define ADJ_SMEM (ADJ_GB + 256)

__global__ __launch_bounds__(256) void k_adj_mma(
    const float* __restrict__ adj, const float* __restrict__ gcnb,
    const float* __restrict__ f4w, float* __restrict__ out)
{
    extern __shared__ __align__(16) char smd[];
    const uint32_t sb = smem_u32(smd);
    float* gb = (float*)(smd + ADJ_GB);

    const int tid = threadIdx.x;
    const int wid = tid >> 5;
    const int lane = tid & 31;
    const int warp_m = wid & 3;
    const int warp_n = wid >> 2;
    const int r = lane >> 2;
    const int cc = (lane & 3) * 2;

    const int n0 = blockIdx.x * 80;
    const int m0 = blockIdx.y * 128;

    if (tid < 50) gb[tid] = gcnb[tid];

    const uint32_t aoff = (uint32_t)((warp_m * 32 + (lane & 15)) * 144 + (lane >> 4) * 16);
    const int row_b = (lane & 7) | ((lane & 16) >> 1);
    const int colh  = (lane >> 3) & 1;
    const uint32_t bpair = (uint32_t)((warp_n * 40 + row_b) * 144 + colh * 16);
    const uint32_t blast = (uint32_t)((warp_n * 40 + 32 + (lane & 7)) * 144 + ((lane >> 3) & 1) * 16);

    float2 av[16];

    auto ldgA = [&](int t) {
        const int z0 = t * 64;
        #pragma unroll
        for (int k = 0; k < 16; k++) {
            int i = tid + k * 256;
            int row = i >> 5, p = i & 31;
            int gm = m0 + row, z = z0 + 2 * p;
            float2 v = make_float2(0.f, 0.f);
            if (gm < YY) {
                if (z + 1 < YY) v = *(const float2*)(adj + (size_t)gm * YY + z);
                else if (z < YY) v.x = adj[(size_t)gm * YY + z];
            }
            av[k] = v;
        }
    };
    auto stsA = [&](int s) {
        const int base = s * ADJ_ASTG;
        #pragma unroll
        for (int k = 0; k < 16; k++) {
            int i = tid + k * 256;
            int row = i >> 5, p = i & 31;
            __half2 hv = __floats2half2_rn(av[k].x * 4096.f, av[k].y * 4096.f);
            *(unsigned*)(smd + base + row * 144 + p * 4) = *(unsigned*)&hv;
        }
    };
    auto stageB = [&](int t, int s) {
        const int z0 = t * 64;
        const uint32_t base = sb + ADJ_BBASE + s * ADJ_BSTG;
        for (int i = tid; i < 640; i += 256) {
            int n = i >> 3, c = i & 7;
            size_t o = (size_t)(n0 + n) * YPAD + z0 + c * 8;
            cp16(base + n * 144 + c * 16, g_sup + o);
        }
    };

    float d[2][5][4];
    #pragma unroll
    for (int mt = 0; mt < 2; mt++)
        #pragma unroll
        for (int nt = 0; nt < 5; nt++)
            #pragma unroll
            for (int i = 0; i < 4; i++) d[mt][nt][i] = 0.f;

    // preloop
    ldgA(0);
    stageB(0, 0); CP_COMMIT();
    stageB(1, 1); CP_COMMIT();
    stsA(0);
    ldgA(1);

    int bs = 0;                            // t % 3
    for (int t = 0; t < NCHUNK; t++) {
        const int s = t & 1;
        CP_WAIT1();                        // B(t) done
        __syncthreads();                   // A(t) stores + prev compute done

        const uint32_t aA = sb + s * ADJ_ASTG + aoff;
        const uint32_t bBp = sb + ADJ_BBASE + bs * ADJ_BSTG + bpair;
        const uint32_t bBl = sb + ADJ_BBASE + bs * ADJ_BSTG + blast;

        #pragma unroll
        for (int ks = 0; ks < 4; ks++) {
            const uint32_t ks32 = ks * 32;
            unsigned aH[2][4];
            ldm_x4(aH[0], aA + ks32);
            ldm_x4(aH[1], aA + 2304 + ks32);

            unsigned bH[5][2];
            {
                unsigned p0[4], p1[4], q[2];
                ldm_x4(p0, bBp + ks32);
                ldm_x4(p1, bBp + 2304 + ks32);
                ldm_x2(q,  bBl + ks32);
                bH[0][0]=p0[0]; bH[0][1]=p0[1]; bH[1][0]=p0[2]; bH[1][1]=p0[3];
                bH[2][0]=p1[0]; bH[2][1]=p1[1]; bH[3][0]=p1[2]; bH[3][1]=p1[3];
                bH[4][0]=q[0];  bH[4][1]=q[1];
            }
            #pragma unroll
            for (int mt = 0; mt < 2; mt++)
                #pragma unroll
                for (int nt = 0; nt < 5; nt++)
                    mma16816h(d[mt][nt], aH[mt], bH[nt]);
        }

        if (t + 1 < NCHUNK) stsA((t + 1) & 1);
        if (t + 2 < NCHUNK) {
            ldgA(t + 2);
            int bs2 = bs + 2; if (bs2 >= 3) bs2 -= 3;
            stageB(t + 2, bs2);
        }
        CP_COMMIT();
        if (++bs == 3) bs = 0;
    }

    const float inv_scale = 1.f / 4096.f;
    const size_t obase = (size_t)BB * YY;
    #pragma unroll
    for (int mt = 0; mt < 2; mt++) {
        int row0 = m0 + warp_m * 32 + mt * 16 + r;
        #pragma unroll
        for (int nt = 0; nt < 5; nt++) {
            int col0 = n0 + warp_n * 40 + nt * 8 + cc;
            int b = col0 / 50;
            int g = col0 - b * 50;
            float gb0 = gb[g], gb1 = gb[g + 1];
            #pragma unroll
            for (int rr = 0; rr < 2; rr++) {
                int y = row0 + rr * 8;
                if (y < YY) {
                    float v0 = d[mt][nt][rr * 2 + 0] * inv_scale + gb0;
                    float v1 = d[mt][nt][rr * 2 + 1] * inv_scale + gb1;
                    v0 = v0 > 0.f ? v0 : 0.2f * v0;
                    v1 = v1 > 0.f ? v1 : 0.2f * v1;
                    const float* fw = f4w + (size_t)y * 100 + 50;
                    float s = v0 * fw[g] + v1 * fw[g + 1];
                    atomicAdd(&out[obase + (size_t)b * YY + y], s);
                }
            }
        }
    }
}

// ---------------------------------------------------------------------------
extern "C" void kernel_launch(void* const* d_in, const int* in_sizes, int n_in,
                              void* d_out, int out_size)
{
    const int*   x     = (const int*)  d_in[0];
    const float* embw  = (const float*)d_in[2];
    const float* convw = (const float*)d_in[3];
    const float* convb = (const float*)d_in[4];
    const float* U4    = (const float*)d_in[5];
    const float* gcnw  = (const float*)d_in[6];
    const float* gcnb  = (const float*)d_in[7];
    const float* adj   = (const float*)d_in[8];
    const float* f4tw  = (const float*)d_in[9];
    const float* f4tb  = (const float*)d_in[10];
    const float* f4w   = (const float*)d_in[11];
    const float* f4b   = (const float*)d_in[12];
    float* out = (float*)d_out;

    cudaFuncSetAttribute(k_attn_mma, cudaFuncAttributeMaxDynamicSharedMemorySize, ATT_SMEM);
    cudaFuncSetAttribute(k_adj_mma,  cudaFuncAttributeMaxDynamicSharedMemorySize, ADJ_SMEM);

    k_embconv <<<dim3(40, BB), 256>>>(x, embw, convw, convb);
    k_attn_mma<<<dim3(70, BB), 256, ATT_SMEM>>>(U4, gcnw, f4tw, f4tb, f4w, f4b, out);
    k_adj_mma <<<dim3(5, 70), 256, ADJ_SMEM>>>(adj, gcnb, f4w, out);
}

// round 17
// speedup vs baseline: 6.5289x; 1.0386x over previous
#include <cuda_runtime.h>
#include <cuda_fp16.h>
#include <math.h>
#include <cstdint>

#define BB 8
#define LL 2500
#define LPAD 2560       // 40 chunks of 64
#define EE 100
#define FF 50
#define KK 9
#define YY 8922
#define NC (BB*FF)      // 400
#define YPAD 8960       // 70*128 = 140*64
#define NCHUNK 140      // K chunks of 64 for adj GEMM

typedef unsigned long long ull;

// Scratch (no allocations allowed)
__device__ __half g_hpk[BB*LPAD*64];     // [b][l][f]   fp16(hp)
__device__ __half g_hpt[BB*64*LPAD];     // [b][f][l]   fp16(hp)
__device__ __half g_sup[NC*YPAD];        // [n400][z]   fp16(support)

// ---------------------------------------------------------------------------
// helpers
// ---------------------------------------------------------------------------
__device__ __forceinline__ void mma16816h(float d[4], const unsigned a[4], const unsigned b[2]) {
    asm volatile(
        "mma.sync.aligned.m16n8k16.row.col.f32.f16.f16.f32 "
        "{%0,%1,%2,%3}, {%4,%5,%6,%7}, {%8,%9}, {%0,%1,%2,%3};"
        : "+f"(d[0]), "+f"(d[1]), "+f"(d[2]), "+f"(d[3])
        : "r"(a[0]), "r"(a[1]), "r"(a[2]), "r"(a[3]), "r"(b[0]), "r"(b[1]));
}
__device__ __forceinline__ void mma16808h(float d[4], const unsigned a[2], const unsigned b0) {
    asm volatile(
        "mma.sync.aligned.m16n8k8.row.col.f32.f16.f16.f32 "
        "{%0,%1,%2,%3}, {%4,%5}, {%6}, {%0,%1,%2,%3};"
        : "+f"(d[0]), "+f"(d[1]), "+f"(d[2]), "+f"(d[3])
        : "r"(a[0]), "r"(a[1]), "r"(b0));
}
__device__ __forceinline__ ull ffma2(ull a, ull b, ull c) {
    ull d;
    asm("fma.rn.f32x2 %0, %1, %2, %3;" : "=l"(d) : "l"(a), "l"(b), "l"(c));
    return d;
}
__device__ __forceinline__ void unpack2(ull v, float& lo, float& hi) {
    asm("mov.b64 {%0, %1}, %2;" : "=f"(lo), "=f"(hi) : "l"(v));
}
__device__ __forceinline__ float ex2f(float x) {
    float y;
    asm("ex2.approx.f32 %0, %1;" : "=f"(y) : "f"(x));
    return y;
}
__device__ __forceinline__ uint32_t smem_u32(const void* p) {
    uint32_t a;
    asm("{ .reg .u64 t; cvta.to.shared.u64 t, %1; cvt.u32.u64 %0, t; }" : "=r"(a) : "l"(p));
    return a;
}
__device__ __forceinline__ void cp16(uint32_t dst, const void* src) {
    asm volatile("cp.async.cg.shared.global [%0], [%1], 16;" :: "r"(dst), "l"(src) : "memory");
}
#define CP_COMMIT() asm volatile("cp.async.commit_group;" ::: "memory")
#define CP_WAIT1()  asm volatile("cp.async.wait_group 1;" ::: "memory")

__device__ __forceinline__ void ldm_x4(unsigned r[4], uint32_t addr) {
    asm volatile("ldmatrix.sync.aligned.m8n8.x4.shared.b16 {%0,%1,%2,%3}, [%4];"
        : "=r"(r[0]), "=r"(r[1]), "=r"(r[2]), "=r"(r[3]) : "r"(addr));
}
__device__ __forceinline__ void ldm_x2(unsigned r[2], uint32_t addr) {
    asm volatile("ldmatrix.sync.aligned.m8n8.x2.shared.b16 {%0,%1}, [%2];"
        : "=r"(r[0]), "=r"(r[1]) : "r"(addr));
}

// ---------------------------------------------------------------------------
// Kernel 1: embedding + conv1d + tanh -> fp16 planes (hpk + hpt). (unchanged)
// ---------------------------------------------------------------------------
__global__ __launch_bounds__(256) void k_embconv(
    const int* __restrict__ x, const float* __restrict__ embw,
    const float* __restrict__ convw, const float* __restrict__ convb)
{
    __shared__ float es[72][104];
    __shared__ float ws2[64][108];

    const int b  = blockIdx.y;
    const int l0 = blockIdx.x * 64;
    const int tid = threadIdx.x;

    for (int idx = tid; idx < 72 * 100; idx += 256) {
        int r = idx / 100, e = idx - r * 100;
        int l = l0 - 4 + r;
        float v = 0.f;
        if (l >= 0 && l < LL) {
            int tok = x[b * LL + l];
            v = embw[(size_t)tok * EE + e];
        }
        es[r][e] = v;
    }

    const int fx = tid & 15;
    const int ly = tid >> 4;
    ull acc2[4][4][2];
    #pragma unroll
    for (int i = 0; i < 4; i++)
        #pragma unroll
        for (int j = 0; j < 4; j++) { acc2[i][j][0] = 0ull; acc2[i][j][1] = 0ull; }

    for (int k = 0; k < KK; k++) {
        __syncthreads();
        for (int idx = tid; idx < 6400; idx += 256) {
            int f = idx & 63, e = idx >> 6;
            ws2[f][e] = (f < FF) ? convw[f * (EE * KK) + e * KK + k] : 0.f;
        }
        __syncthreads();
        #pragma unroll 5
        for (int e = 0; e < EE; e += 4) {
            ulonglong2 au[4], wu[4];
            #pragma unroll
            for (int i = 0; i < 4; i++) au[i] = *(const ulonglong2*)&es[ly + 16 * i + k][e];
            #pragma unroll
            for (int j = 0; j < 4; j++) wu[j] = *(const ulonglong2*)&ws2[fx + 16 * j][e];
            #pragma unroll
            for (int i = 0; i < 4; i++)
                #pragma unroll
                for (int j = 0; j < 4; j++) {
                    acc2[i][j][0] = ffma2(au[i].x, wu[j].x, acc2[i][j][0]);
                    acc2[i][j][1] = ffma2(au[i].y, wu[j].y, acc2[i][j][1]);
                }
        }
    }

    __syncthreads();
    __half* tp = (__half*)es;              // [64 f][72 l-stride]

    #pragma unroll
    for (int i = 0; i < 4; i++) {
        int lr = ly + 16 * i;
        int l = l0 + lr;
        #pragma unroll
        for (int j = 0; j < 4; j++) {
            int f = fx + 16 * j;
            float a0, a1, b0, b1;
            unpack2(acc2[i][j][0], a0, a1);
            unpack2(acc2[i][j][1], b0, b1);
            float s = (a0 + a1) + (b0 + b1);
            float val = 0.f;
            if (l < LL && f < FF) val = tanhf(s + convb[f]);
            __half h = __float2half_rn(val);
            g_hpk[((size_t)b * LPAD + l) * 64 + f] = h;
            tp[f * 72 + lr] = h;
        }
    }
    __syncthreads();

    {
        int f = tid >> 2;
        int c0 = (tid & 3) * 16;
        uint4 v0 = *(const uint4*)&tp[f * 72 + c0];
        uint4 v1 = *(const uint4*)&tp[f * 72 + c0 + 8];
        size_t o = ((size_t)b * 64 + f) * LPAD + l0 + c0;
        *(uint4*)&g_hpt[o] = v0;
        *(uint4*)&g_hpt[o + 8] = v1;
    }
}

// ---------------------------------------------------------------------------
// Kernel 2 (HMMA fp16): attention. grid (70, B), block 256, 2 CTAs/SM.
// 3-stage cp.async ring, single sync per chunk, ex2-folded exp.
// ---------------------------------------------------------------------------
#define ATT_STG 18432                  // 2 planes x 9216 per stage
#define ATT_GS  55296                  // after 3 stages
#define ATT_SMEM (55296 + 10016)

__global__ __launch_bounds__(256, 2) void k_attn_mma(
    const float* __restrict__ U4, const float* __restrict__ gcnw,
    const float* __restrict__ f4t_w, const float* __restrict__ f4t_b,
    const float* __restrict__ f4_w, const float* __restrict__ f4_b,
    float* __restrict__ out)
{
    extern __shared__ __align__(16) char smd[];
    const uint32_t sb = smem_u32(smd);
    float* gs = (float*)(smd + ATT_GS);
    float* m4s = (float*)smd;              // [128][68] after main loop

    const int b = blockIdx.y;
    const int y0 = blockIdx.x * 128;
    const int tid = threadIdx.x;
    const int wy = tid >> 5;
    const int lane = tid & 31;
    const int r = lane >> 2;
    const int c2 = (lane & 3) * 2;

    const int row_b = (lane & 7) | ((lane & 16) >> 1);
    const int colh  = (lane >> 3) & 1;
    const uint32_t boffT = (uint32_t)(row_b * 144 + colh * 16);

    for (int i = tid; i < 2500; i += 256) gs[i] = gcnw[i];

    auto stage = [&](int t, int s) {
        const int l0c = t * 64;
        const uint32_t base = sb + s * ATT_STG;
        #pragma unroll
        for (int it = 0; it < 2; it++) {
            int idx = tid + it * 256;
            int row = idx >> 3, c = idx & 7;
            uint32_t d0 = base + row * 144 + c * 16;
            size_t srck = ((size_t)b * LPAD + l0c + row) * 64 + c * 8;
            cp16(d0, g_hpk + srck);
            size_t srct = ((size_t)b * 64 + row) * LPAD + l0c + c * 8;
            cp16(d0 + 9216, g_hpt + srct);
        }
    };

    // --- preload U4 single-fp16 A-fragments
    const int yr0 = y0 + wy * 16 + r;
    const int yr1 = yr0 + 8;
    unsigned uH[4][4];
    #pragma unroll
    for (int ks = 0; ks < 4; ks++) {
        #pragma unroll
        for (int q = 0; q < 4; q++) {
            int row = (q & 1) ? yr1 : yr0;
            int col = ks * 16 + c2 + ((q & 2) ? 8 : 0);
            float v0 = 0.f, v1 = 0.f;
            if (row < YY) {
                if (col < FF)     v0 = U4[(size_t)row * FF + col];
                if (col + 1 < FF) v1 = U4[(size_t)row * FF + col + 1];
            }
            __half2 hh = __floats2half2_rn(v0, v1);
            uH[ks][q] = *(unsigned*)&hh;
        }
    }

    float D2[7][4];
    #pragma unroll
    for (int n = 0; n < 7; n++)
        #pragma unroll
        for (int i = 0; i < 4; i++) D2[n][i] = 0.f;
    float rs0 = 0.f, rs1 = 0.f;

    stage(0, 0); CP_COMMIT();
    stage(1, 1); CP_COMMIT();

    const float L2E = 1.4426950408889634f;
    int bs = 0;
    for (int t = 0; t < 40; t++) {
        CP_WAIT1();                         // stage t landed
        __syncthreads();                    // all warps done with stage t-1

        const int l0 = t * 64;
        const uint32_t kb = sb + bs * ATT_STG + boffT;  // hpk plane
        const uint32_t tb = kb + 9216;                  // hpt plane

        // --- scores: S = u . hpk  (3x k16 + 1x k8 over f48-55)
        float sw[8][4];
        #pragma unroll
        for (int nt = 0; nt < 8; nt++)
            #pragma unroll
            for (int i = 0; i < 4; i++) sw[nt][i] = 0.f;

        #pragma unroll
        for (int ks = 0; ks < 4; ks++) {
            const uint32_t ks32 = ks * 32;
            unsigned bh[4][4];
            #pragma unroll
            for (int ntp = 0; ntp < 4; ntp++)
                ldm_x4(bh[ntp], kb + ntp * 2304 + ks32);
            if (ks < 3) {
                #pragma unroll
                for (int nt = 0; nt < 8; nt++) {
                    unsigned hbx[2] = { bh[nt >> 1][(nt & 1) * 2], bh[nt >> 1][(nt & 1) * 2 + 1] };
                    mma16816h(sw[nt], uH[ks], hbx);
                }
            } else {
                unsigned a8[2] = { uH[3][0], uH[3][1] };   // f 48..55
                #pragma unroll
                for (int nt = 0; nt < 8; nt++)
                    mma16808h(sw[nt], a8, bh[nt >> 1][(nt & 1) * 2]);
            }
        }

        // --- exp via ex2 fold (= __expf(S)*2^-4) + tail mask; consistent sums
        const bool full = (l0 + 64 <= LL);
        unsigned pk01[8], pk23[8];
        #pragma unroll
        for (int nt = 0; nt < 8; nt++) {
            float e0 = ex2f(fmaf(sw[nt][0], L2E, -4.f));
            float e1 = ex2f(fmaf(sw[nt][1], L2E, -4.f));
            float e2 = ex2f(fmaf(sw[nt][2], L2E, -4.f));
            float e3 = ex2f(fmaf(sw[nt][3], L2E, -4.f));
            if (!full) {
                int lc = l0 + nt * 8 + c2;
                if (lc >= LL)     { e0 = 0.f; e2 = 0.f; }
                if (lc + 1 >= LL) { e1 = 0.f; e3 = 0.f; }
            }
            __half2 q01 = __floats2half2_rn(e0, e1);
            __half2 q23 = __floats2half2_rn(e2, e3);
            float2 f01 = __half22float2(q01);
            float2 f23 = __half22float2(q23);
            rs0 += f01.x + f01.y;
            rs1 += f23.x + f23.y;
            pk01[nt] = *(unsigned*)&q01;
            pk23[nt] = *(unsigned*)&q23;
        }

        unsigned aW[4][4];
        #pragma unroll
        for (int kt = 0; kt < 4; kt++) {
            aW[kt][0] = pk01[2 * kt];
            aW[kt][1] = pk23[2 * kt];
            aW[kt][2] = pk01[2 * kt + 1];
            aW[kt][3] = pk23[2 * kt + 1];
        }

        // --- m4t accumulate: D2 += w' . hpt  (7 n-tiles)
        #pragma unroll
        for (int ks = 0; ks < 4; ks++) {
            const uint32_t ks32 = ks * 32;
            unsigned bhH[4][4];
            #pragma unroll
            for (int ntp = 0; ntp < 4; ntp++)
                ldm_x4(bhH[ntp], tb + ntp * 2304 + ks32);
            #pragma unroll
            for (int nt = 0; nt < 7; nt++) {
                unsigned hx[2] = { bhH[nt >> 1][(nt & 1) * 2], bhH[nt >> 1][(nt & 1) * 2 + 1] };
                mma16816h(D2[nt], aW[ks], hx);
            }
        }

        if (t + 2 < 40) {
            int s2 = bs + 2; if (s2 >= 3) s2 -= 3;
            stage(t + 2, s2);
        }
        CP_COMMIT();
        if (++bs == 3) bs = 0;
    }

    // --- normalize (rounded-weight sums -> exact weighted average)
    rs0 += __shfl_xor_sync(0xFFFFFFFF, rs0, 1);
    rs0 += __shfl_xor_sync(0xFFFFFFFF, rs0, 2);
    rs1 += __shfl_xor_sync(0xFFFFFFFF, rs1, 1);
    rs1 += __shfl_xor_sync(0xFFFFFFFF, rs1, 2);
    float inv0 = (yr0 < YY) ? 1.f / rs0 : 0.f;
    float inv1 = (yr1 < YY) ? 1.f / rs1 : 0.f;

    __syncthreads();                        // all stage reads done; alias m4s
    #pragma unroll
    for (int nt = 0; nt < 7; nt++) {
        int col = nt * 8 + c2;
        m4s[(wy * 16 + r) * 68 + col]         = D2[nt][0] * inv0;
        m4s[(wy * 16 + r) * 68 + col + 1]     = D2[nt][1] * inv0;
        m4s[(wy * 16 + 8 + r) * 68 + col]     = D2[nt][2] * inv1;
        m4s[(wy * 16 + 8 + r) * 68 + col + 1] = D2[nt][3] * inv1;
    }
    __syncthreads();

    // --- epilogue: 2 threads per y
    {
        const int yl = tid >> 1;
        const int half = tid & 1;
        const int y = y0 + yl;
        float m[50];
        #pragma unroll
        for (int f = 0; f < 50; f++) m[f] = m4s[yl * 68 + f];

        const int g0 = half * 25;
        for (int g = g0; g < g0 + 25; g++) {
            float s = 0.f;
            #pragma unroll
            for (int f = 0; f < 50; f++) s += m[f] * gs[f * 50 + g];
            g_sup[(size_t)(b * FF + g) * YPAD + y] = __float2half_rn(s);
        }

        if (y < YY) {
            if (half == 0) {
                const float* wt = f4t_w + (size_t)y * 50;
                float s1 = 0.f;
                #pragma unroll
                for (int f = 0; f < 50; f++) s1 += m[f] * wt[f];
                out[(size_t)b * YY + y] = s1 + f4t_b[y];
            } else {
                const float* w4 = f4_w + (size_t)y * 100;
                float s2 = 0.f;
                #pragma unroll
                for (int f = 0; f < 50; f++) s2 += m[f] * w4[f];
                out[(size_t)BB * YY + (size_t)b * YY + y] = s2 + f4_b[y];
            }
        }
    }
}

// ---------------------------------------------------------------------------
// Kernel 3: adj GEMM, single-product fp16, ldmatrix frags, single-sync
// pipeline (A 2-stage reg-prefetch, B 3-stage cp.async), 2 CTAs/SM hint.
// ---------------------------------------------------------------------------
#define ADJ_ASTG 18432
#define ADJ_BBASE 36864
#define ADJ_BSTG 11520
#define ADJ_GB (36864 + 3 * 11520)     // 71424
#define ADJ_SMEM (ADJ_GB + 256)

__global__ __launch_bounds__(256, 2) void k_adj_mma(
    const float* __restrict__ adj, const float* __restrict__ gcnb,
    const float* __restrict__ f4w, float* __restrict__ out)
{
    extern __shared__ __align__(16) char smd[];
    const uint32_t sb = smem_u32(smd);
    float* gb = (float*)(smd + ADJ_GB);

    const int tid = threadIdx.x;
    const int wid = tid >> 5;
    const int lane = tid & 31;
    const int warp_m = wid & 3;
    const int warp_n = wid >> 2;
    const int r = lane >> 2;
    const int cc = (lane & 3) * 2;

    const int n0 = blockIdx.x * 80;
    const int m0 = blockIdx.y * 128;

    if (tid < 50) gb[tid] = gcnb[tid];

    const uint32_t aoff = (uint32_t)((warp_m * 32 + (lane & 15)) * 144 + (lane >> 4) * 16);
    const int row_b = (lane & 7) | ((lane & 16) >> 1);
    const int colh  = (lane >> 3) & 1;
    const uint32_t bpair = (uint32_t)((warp_n * 40 + row_b) * 144 + colh * 16);
    const uint32_t blast = (uint32_t)((warp_n * 40 + 32 + (lane & 7)) * 144 + ((lane >> 3) & 1) * 16);

    float2 av[16];

    auto ldgA = [&](int t) {
        const int z0 = t * 64;
        #pragma unroll
        for (int k = 0; k < 16; k++) {
            int i = tid + k * 256;
            int row = i >> 5, p = i & 31;
            int gm = m0 + row, z = z0 + 2 * p;
            float2 v = make_float2(0.f, 0.f);
            if (gm < YY) {
                if (z + 1 < YY) v = *(const float2*)(adj + (size_t)gm * YY + z);
                else if (z < YY) v.x = adj[(size_t)gm * YY + z];
            }
            av[k] = v;
        }
    };
    auto stsA = [&](int s) {
        const int base = s * ADJ_ASTG;
        #pragma unroll
        for (int k = 0; k < 16; k++) {
            int i = tid + k * 256;
            int row = i >> 5, p = i & 31;
            __half2 hv = __floats2half2_rn(av[k].x * 4096.f, av[k].y * 4096.f);
            *(unsigned*)(smd + base + row * 144 + p * 4) = *(unsigned*)&hv;
        }
    };
    auto stageB = [&](int t, int s) {
        const int z0 = t * 64;
        const uint32_t base = sb + ADJ_BBASE + s * ADJ_BSTG;
        for (int i = tid; i < 640; i += 256) {
            int n = i >> 3, c = i & 7;
            size_t o = (size_t)(n0 + n) * YPAD + z0 + c * 8;
            cp16(base + n * 144 + c * 16, g_sup + o);
        }
    };

    float d[2][5][4];
    #pragma unroll
    for (int mt = 0; mt < 2; mt++)
        #pragma unroll
        for (int nt = 0; nt < 5; nt++)
            #pragma unroll
            for (int i = 0; i < 4; i++) d[mt][nt][i] = 0.f;

    // preloop
    ldgA(0);
    stageB(0, 0); CP_COMMIT();
    stageB(1, 1); CP_COMMIT();
    stsA(0);
    ldgA(1);

    int bs = 0;
    for (int t = 0; t < NCHUNK; t++) {
        const int s = t & 1;
        CP_WAIT1();
        __syncthreads();

        const uint32_t aA = sb + s * ADJ_ASTG + aoff;
        const uint32_t bBp = sb + ADJ_BBASE + bs * ADJ_BSTG + bpair;
        const uint32_t bBl = sb + ADJ_BBASE + bs * ADJ_BSTG + blast;

        #pragma unroll
        for (int ks = 0; ks < 4; ks++) {
            const uint32_t ks32 = ks * 32;
            unsigned aH[2][4];
            ldm_x4(aH[0], aA + ks32);
            ldm_x4(aH[1], aA + 2304 + ks32);

            unsigned bH[5][2];
            {
                unsigned p0[4], p1[4], q[2];
                ldm_x4(p0, bBp + ks32);
                ldm_x4(p1, bBp + 2304 + ks32);
                ldm_x2(q,  bBl + ks32);
                bH[0][0]=p0[0]; bH[0][1]=p0[1]; bH[1][0]=p0[2]; bH[1][1]=p0[3];
                bH[2][0]=p1[0]; bH[2][1]=p1[1]; bH[3][0]=p1[2]; bH[3][1]=p1[3];
                bH[4][0]=q[0];  bH[4][1]=q[1];
            }
            #pragma unroll
            for (int mt = 0; mt < 2; mt++)
                #pragma unroll
                for (int nt = 0; nt < 5; nt++)
                    mma16816h(d[mt][nt], aH[mt], bH[nt]);
        }

        if (t + 1 < NCHUNK) stsA((t + 1) & 1);
        if (t + 2 < NCHUNK) {
            ldgA(t + 2);
            int bs2 = bs + 2; if (bs2 >= 3) bs2 -= 3;
            stageB(t + 2, bs2);
        }
        CP_COMMIT();
        if (++bs == 3) bs = 0;
    }

    const float inv_scale = 1.f / 4096.f;
    const size_t obase = (size_t)BB * YY;
    #pragma unroll
    for (int mt = 0; mt < 2; mt++) {
        int row0 = m0 + warp_m * 32 + mt * 16 + r;
        #pragma unroll
        for (int nt = 0; nt < 5; nt++) {
            int col0 = n0 + warp_n * 40 + nt * 8 + cc;
            int b = col0 / 50;
            int g = col0 - b * 50;
            float gb0 = gb[g], gb1 = gb[g + 1];
            #pragma unroll
            for (int rr = 0; rr < 2; rr++) {
                int y = row0 + rr * 8;
                if (y < YY) {
                    float v0 = d[mt][nt][rr * 2 + 0] * inv_scale + gb0;
                    float v1 = d[mt][nt][rr * 2 + 1] * inv_scale + gb1;
                    v0 = v0 > 0.f ? v0 : 0.2f * v0;
                    v1 = v1 > 0.f ? v1 : 0.2f * v1;
                    const float* fw = f4w + (size_t)y * 100 + 50;
                    float s = v0 * fw[g] + v1 * fw[g + 1];
                    atomicAdd(&out[obase + (size_t)b * YY + y], s);
                }
            }
        }
    }
}

// ---------------------------------------------------------------------------
extern "C" void kernel_launch(void* const* d_in, const int* in_sizes, int n_in,
                              void* d_out, int out_size)
{
    const int*   x     = (const int*)  d_in[0];
    const float* embw  = (const float*)d_in[2];
    const float* convw = (const float*)d_in[3];
    const float* convb = (const float*)d_in[4];
    const float* U4    = (const float*)d_in[5];
    const float* gcnw  = (const float*)d_in[6];
    const float* gcnb  = (const float*)d_in[7];
    const float* adj   = (const float*)d_in[8];
    const float* f4tw  = (const float*)d_in[9];
    const float* f4tb  = (const float*)d_in[10];
    const float* f4w   = (const float*)d_in[11];
    const float* f4b   = (const float*)d_in[12];
    float* out = (float*)d_out;

    cudaFuncSetAttribute(k_attn_mma, cudaFuncAttributeMaxDynamicSharedMemorySize, ATT_SMEM);
    cudaFuncSetAttribute(k_adj_mma,  cudaFuncAttributeMaxDynamicSharedMemorySize, ADJ_SMEM);

    k_embconv <<<dim3(40, BB), 256>>>(x, embw, convw, convb);
    k_attn_mma<<<dim3(70, BB), 256, ATT_SMEM>>>(U4, gcnw, f4tw, f4tb, f4w, f4b, out);
    k_adj_mma <<<dim3(5, 70), 256, ADJ_SMEM>>>(adj, gcnb, f4w, out);
}